// round 1
// baseline (speedup 1.0000x reference)
#include <cuda_runtime.h>

#define BSZ  2
#define CDIM 1024
#define TDIM 2048
#define HN   16
#define DH   64

// Scratch (static device globals — no allocation allowed)
__device__ float g_Q [(size_t)BSZ * CDIM * TDIM];
__device__ float g_K [(size_t)BSZ * CDIM * TDIM];
__device__ float g_Vt[(size_t)BSZ * CDIM * TDIM];  // (B, T, C) transposed V
__device__ float g_AO[(size_t)BSZ * CDIM * TDIM];

// ---------------------------------------------------------------------------
// SGEMM: C[b] = A(MxK) * B[b](KxN) + bias, optional mask multiply (per column),
// optional transposed output (writes (N,M) layout, used for V).
// Block tile 128x128, BK=8, 256 threads, 8x8 per thread.
// ---------------------------------------------------------------------------
__global__ __launch_bounds__(256)
void sgemm_kernel(const float* __restrict__ A, const float* __restrict__ Bm,
                  const float* __restrict__ bias, float* __restrict__ Cm,
                  const unsigned* __restrict__ mask,
                  int M, int N, int K, int outTrans)
{
    const int b = blockIdx.z;
    const float* Bp = Bm + (size_t)b * K * N;
    float*       Cp = Cm + (size_t)b * M * N;
    const unsigned* mb = mask ? (mask + (size_t)b * N) : nullptr;

    __shared__ float As[8][132];   // padded: conflict-free transpose store
    __shared__ float Bs[8][128];

    const int tid = threadIdx.x;
    const int tx  = tid & 15;
    const int ty  = tid >> 4;
    const int bm  = blockIdx.y * 128;
    const int bn  = blockIdx.x * 128;

    const int arow = tid >> 1;
    const int acol = (tid & 1) * 4;
    const int brow = tid >> 5;
    const int bcol = (tid & 31) * 4;

    float acc[8][8];
#pragma unroll
    for (int i = 0; i < 8; ++i)
#pragma unroll
        for (int j = 0; j < 8; ++j) acc[i][j] = 0.f;

    const float* Ap  = A  + (size_t)(bm + arow) * K + acol;
    const float* Bpp = Bp + (size_t)brow * N + bn + bcol;

    for (int k0 = 0; k0 < K; k0 += 8) {
        float4 av = *(const float4*)(Ap + k0);
        float4 bv = *(const float4*)(Bpp + (size_t)k0 * N);
        As[acol + 0][arow] = av.x;
        As[acol + 1][arow] = av.y;
        As[acol + 2][arow] = av.z;
        As[acol + 3][arow] = av.w;
        *(float4*)&Bs[brow][bcol] = bv;
        __syncthreads();
#pragma unroll
        for (int k = 0; k < 8; ++k) {
            float4 a0 = *(const float4*)&As[k][ty * 8];
            float4 a1 = *(const float4*)&As[k][ty * 8 + 4];
            float4 b0 = *(const float4*)&Bs[k][tx * 8];
            float4 b1 = *(const float4*)&Bs[k][tx * 8 + 4];
            float ar[8] = {a0.x, a0.y, a0.z, a0.w, a1.x, a1.y, a1.z, a1.w};
            float br[8] = {b0.x, b0.y, b0.z, b0.w, b1.x, b1.y, b1.z, b1.w};
#pragma unroll
            for (int i = 0; i < 8; ++i)
#pragma unroll
                for (int j = 0; j < 8; ++j)
                    acc[i][j] = fmaf(ar[i], br[j], acc[i][j]);
        }
        __syncthreads();
    }

    if (!outTrans) {
#pragma unroll
        for (int i = 0; i < 8; ++i) {
            const int row = bm + ty * 8 + i;
            const float bi = bias[row];
            float* cr = Cp + (size_t)row * N + bn + tx * 8;
#pragma unroll
            for (int j4 = 0; j4 < 8; j4 += 4) {
                float4 o;
                o.x = acc[i][j4 + 0] + bi;
                o.y = acc[i][j4 + 1] + bi;
                o.z = acc[i][j4 + 2] + bi;
                o.w = acc[i][j4 + 3] + bi;
                if (mb) {
                    const int col = bn + tx * 8 + j4;
                    o.x *= (mb[col + 0] ? 1.f : 0.f);
                    o.y *= (mb[col + 1] ? 1.f : 0.f);
                    o.z *= (mb[col + 2] ? 1.f : 0.f);
                    o.w *= (mb[col + 3] ? 1.f : 0.f);
                }
                *(float4*)(cr + j4) = o;
            }
        }
    } else {
        // write (N, M) layout: Cp[col * M + row]
#pragma unroll
        for (int i = 0; i < 8; ++i) {
            const int row = bm + ty * 8 + i;
            const float bi = bias[row];
#pragma unroll
            for (int j = 0; j < 8; ++j) {
                const int col = bn + tx * 8 + j;
                Cp[(size_t)col * M + row] = acc[i][j] + bi;
            }
        }
    }
}

// ---------------------------------------------------------------------------
// Flash-style masked attention.
// Grid: (T/64, H, B). Block: 256 threads (16x16).
// Q,K in (B,C,T) layout; V in (B,T,C); output O in (B,C,T).
// Per block: 64 queries, streamed over 32 tiles of 64 keys, online softmax.
// smem: qsT[d][i] 16KB, ksT[d][j] 16KB (aliased with ps[i][j]), vs[j][d] 16KB.
// ---------------------------------------------------------------------------
__global__ __launch_bounds__(256)
void attn_kernel(const float* __restrict__ Q, const float* __restrict__ K,
                 const float* __restrict__ Vt, const unsigned* __restrict__ mask,
                 float* __restrict__ O)
{
    __shared__ float sm[3 * 64 * 64];   // 48 KB
    float* qsT   = sm;              // [d*64 + i]
    float* ks_ps = sm + 4096;       // first ksT [d*64 + j], later ps [i*64 + j]
    float* vs    = sm + 8192;       // [j*64 + d]

    const int b  = blockIdx.z;
    const int h  = blockIdx.y;
    const int q0 = blockIdx.x * 64;

    const size_t base = ((size_t)b * CDIM + h * DH) * TDIM;
    const float* Qb = Q + base;
    const float* Kb = K + base;
    const float* Vb = Vt + (size_t)b * TDIM * CDIM + h * DH;
    const unsigned* mb = mask + (size_t)b * TDIM;
    float* Ob = O + base;

    const int tid = threadIdx.x;
    const int tx  = tid & 15;
    const int ty  = tid >> 4;
    const int i0  = ty * 4;
    const int j0  = tx * 4;

    // Load Q tile: qsT[d][i]
    {
        const int g4 = tid & 15;    // float4 group along i / j
        const int d0 = tid >> 4;    // 0..15
#pragma unroll
        for (int r = 0; r < 4; ++r) {
            const int d = d0 + r * 16;
            float4 v = *(const float4*)(Qb + (size_t)d * TDIM + q0 + g4 * 4);
            *(float4*)&qsT[d * 64 + g4 * 4] = v;
        }
    }

    float m[4], l[4], acc[4][4];
#pragma unroll
    for (int i = 0; i < 4; ++i) {
        m[i] = -1e30f; l[i] = 0.f;
#pragma unroll
        for (int c = 0; c < 4; ++c) acc[i][c] = 0.f;
    }

    const float scale = 0.125f;   // 1/sqrt(64)

    for (int k0 = 0; k0 < TDIM; k0 += 64) {
        __syncthreads();   // qsT ready (1st iter); ps/vs consumed (later iters)

        // Load K tile ksT[d][j] and V tile vs[j][d]
        {
            const int g4 = tid & 15;
            const int r0 = tid >> 4;
#pragma unroll
            for (int r = 0; r < 4; ++r) {
                const int d = r0 + r * 16;
                float4 v = *(const float4*)(Kb + (size_t)d * TDIM + k0 + g4 * 4);
                *(float4*)&ks_ps[d * 64 + g4 * 4] = v;
            }
#pragma unroll
            for (int r = 0; r < 4; ++r) {
                const int j = r0 + r * 16;
                float4 v = *(const float4*)(Vb + (size_t)(k0 + j) * CDIM + g4 * 4);
                *(float4*)&vs[j * 64 + g4 * 4] = v;
            }
        }
        __syncthreads();

        // S = Q^T K  (each thread: 4 queries x 4 keys)
        float s[4][4];
#pragma unroll
        for (int i = 0; i < 4; ++i)
#pragma unroll
            for (int j = 0; j < 4; ++j) s[i][j] = 0.f;

#pragma unroll 4
        for (int d = 0; d < 64; ++d) {
            float4 qv = *(const float4*)&qsT[d * 64 + i0];
            float4 kv = *(const float4*)&ks_ps[d * 64 + j0];
            float qr[4] = {qv.x, qv.y, qv.z, qv.w};
            float kr[4] = {kv.x, kv.y, kv.z, kv.w};
#pragma unroll
            for (int i = 0; i < 4; ++i)
#pragma unroll
                for (int j = 0; j < 4; ++j)
                    s[i][j] = fmaf(qr[i], kr[j], s[i][j]);
        }

        // mask + scale
        unsigned mk[4];
#pragma unroll
        for (int j = 0; j < 4; ++j) mk[j] = mb[k0 + j0 + j];
#pragma unroll
        for (int i = 0; i < 4; ++i)
#pragma unroll
            for (int j = 0; j < 4; ++j)
                s[i][j] = mk[j] ? s[i][j] * scale : -1e30f;

        // online softmax update
        float fac[4];
#pragma unroll
        for (int i = 0; i < 4; ++i) {
            float mm = fmaxf(fmaxf(s[i][0], s[i][1]), fmaxf(s[i][2], s[i][3]));
#pragma unroll
            for (int off = 8; off; off >>= 1)
                mm = fmaxf(mm, __shfl_xor_sync(0xffffffffu, mm, off, 16));
            const float mnew = fmaxf(m[i], mm);
            float ls = 0.f;
#pragma unroll
            for (int j = 0; j < 4; ++j) {
                const float p = mk[j] ? __expf(s[i][j] - mnew) : 0.f;
                s[i][j] = p;
                ls += p;
            }
#pragma unroll
            for (int off = 8; off; off >>= 1)
                ls += __shfl_xor_sync(0xffffffffu, ls, off, 16);
            fac[i] = __expf(m[i] - mnew);
            l[i] = l[i] * fac[i] + ls;
            m[i] = mnew;
#pragma unroll
            for (int c = 0; c < 4; ++c) acc[i][c] *= fac[i];
        }

        __syncthreads();   // everyone done reading ksT
        // store P into aliased region: ps[i][j]
#pragma unroll
        for (int i = 0; i < 4; ++i) {
            float4 pv = make_float4(s[i][0], s[i][1], s[i][2], s[i][3]);
            *(float4*)&ks_ps[(i0 + i) * 64 + j0] = pv;
        }
        __syncthreads();

        // O += P V  (each thread: 4 queries x 4 d's, d = tx*4..)
#pragma unroll 4
        for (int j = 0; j < 64; ++j) {
            float4 v = *(const float4*)&vs[j * 64 + j0];
            float p0 = ks_ps[(i0 + 0) * 64 + j];
            float p1 = ks_ps[(i0 + 1) * 64 + j];
            float p2 = ks_ps[(i0 + 2) * 64 + j];
            float p3 = ks_ps[(i0 + 3) * 64 + j];
            acc[0][0] = fmaf(p0, v.x, acc[0][0]); acc[0][1] = fmaf(p0, v.y, acc[0][1]);
            acc[0][2] = fmaf(p0, v.z, acc[0][2]); acc[0][3] = fmaf(p0, v.w, acc[0][3]);
            acc[1][0] = fmaf(p1, v.x, acc[1][0]); acc[1][1] = fmaf(p1, v.y, acc[1][1]);
            acc[1][2] = fmaf(p1, v.z, acc[1][2]); acc[1][3] = fmaf(p1, v.w, acc[1][3]);
            acc[2][0] = fmaf(p2, v.x, acc[2][0]); acc[2][1] = fmaf(p2, v.y, acc[2][1]);
            acc[2][2] = fmaf(p2, v.z, acc[2][2]); acc[2][3] = fmaf(p2, v.w, acc[2][3]);
            acc[3][0] = fmaf(p3, v.x, acc[3][0]); acc[3][1] = fmaf(p3, v.y, acc[3][1]);
            acc[3][2] = fmaf(p3, v.z, acc[3][2]); acc[3][3] = fmaf(p3, v.w, acc[3][3]);
        }
    }

    // normalize and write out in (C, T) layout
#pragma unroll
    for (int i = 0; i < 4; ++i) {
        const float inv = (l[i] > 0.f) ? (1.f / l[i]) : 0.f;
        const int qi = q0 + i0 + i;
#pragma unroll
        for (int c = 0; c < 4; ++c) {
            const int d = j0 + c;
            Ob[(size_t)d * TDIM + qi] = acc[i][c] * inv;
        }
    }
}

// ---------------------------------------------------------------------------
__global__ void write_mask_kernel(const unsigned* __restrict__ mask,
                                  float* __restrict__ out, int n)
{
    int i = blockIdx.x * blockDim.x + threadIdx.x;
    if (i < n) out[i] = mask[i] ? 1.0f : 0.0f;
}

// ---------------------------------------------------------------------------
extern "C" void kernel_launch(void* const* d_in, const int* in_sizes, int n_in,
                              void* d_out, int out_size)
{
    const float*    x    = (const float*)d_in[0];
    const unsigned* mask = (const unsigned*)d_in[1];   // nonzero == true (int32/float32 both work)
    const float*    Wq   = (const float*)d_in[2];
    const float*    bq   = (const float*)d_in[3];
    const float*    Wk   = (const float*)d_in[4];
    const float*    bk   = (const float*)d_in[5];
    const float*    Wv   = (const float*)d_in[6];
    const float*    bv   = (const float*)d_in[7];
    const float*    Wp   = (const float*)d_in[8];
    const float*    bp   = (const float*)d_in[9];
    float* out = (float*)d_out;

    float *gq, *gk, *gvt, *gao;
    cudaGetSymbolAddress((void**)&gq,  g_Q);
    cudaGetSymbolAddress((void**)&gk,  g_K);
    cudaGetSymbolAddress((void**)&gvt, g_Vt);
    cudaGetSymbolAddress((void**)&gao, g_AO);

    dim3 gg(TDIM / 128, CDIM / 128, BSZ);
    sgemm_kernel<<<gg, 256>>>(Wq, x, bq, gq,  nullptr, CDIM, TDIM, CDIM, 0);
    sgemm_kernel<<<gg, 256>>>(Wk, x, bk, gk,  nullptr, CDIM, TDIM, CDIM, 0);
    sgemm_kernel<<<gg, 256>>>(Wv, x, bv, gvt, nullptr, CDIM, TDIM, CDIM, 1);

    dim3 ga(TDIM / 64, HN, BSZ);
    attn_kernel<<<ga, 256>>>(gq, gk, gvt, mask, gao);

    sgemm_kernel<<<gg, 256>>>(Wp, gao, bp, out, mask, CDIM, TDIM, CDIM, 0);

    const long long nout = (long long)BSZ * CDIM * TDIM;
    const int tail = out_size - (int)nout;
    if (tail >= BSZ * TDIM) {
        write_mask_kernel<<<(BSZ * TDIM + 255) / 256, 256>>>(
            mask, out + nout, BSZ * TDIM);
    }
}

// round 3
// speedup vs baseline: 1.1769x; 1.1769x over previous
#include <cuda_runtime.h>
#include <cuda_bf16.h>
#include <stdint.h>

#define BSZ  2
#define CDIM 1024
#define TDIM 2048
#define HN   16
#define DH   64

// ---------------- scratch (static device globals) ----------------
__device__ float g_Q [(size_t)BSZ * CDIM * TDIM];
__device__ float g_K [(size_t)BSZ * CDIM * TDIM];
__device__ float g_Vt[(size_t)BSZ * CDIM * TDIM];   // (B, T, C)
__device__ float g_AO[(size_t)BSZ * CDIM * TDIM];
__device__ __nv_bfloat16 g_Wh [(size_t)4 * CDIM * CDIM];
__device__ __nv_bfloat16 g_Wl [(size_t)4 * CDIM * CDIM];
__device__ __nv_bfloat16 g_xTh[(size_t)BSZ * TDIM * CDIM];   // (B, T, C) bf16 hi
__device__ __nv_bfloat16 g_xTl[(size_t)BSZ * TDIM * CDIM];
__device__ __nv_bfloat16 g_aTh[(size_t)BSZ * TDIM * CDIM];
__device__ __nv_bfloat16 g_aTl[(size_t)BSZ * TDIM * CDIM];

// ---------------- helpers ----------------
__device__ __forceinline__ uint32_t smem_u32(const void* p) {
    uint32_t a;
    asm("{ .reg .u64 t; cvta.to.shared.u64 t, %1; cvt.u32.u64 %0, t; }" : "=r"(a) : "l"(p));
    return a;
}
__device__ __forceinline__ uint32_t sw128(uint32_t off) { return off ^ ((off >> 3) & 0x70); }

__device__ __forceinline__ void ldsm4(uint32_t* r, uint32_t addr) {
    asm volatile("ldmatrix.sync.aligned.m8n8.x4.shared.b16 {%0,%1,%2,%3}, [%4];"
        : "=r"(r[0]), "=r"(r[1]), "=r"(r[2]), "=r"(r[3]) : "r"(addr));
}
__device__ __forceinline__ void mma16816(float* c, const uint32_t* a, const uint32_t* b) {
    asm volatile("mma.sync.aligned.m16n8k16.row.col.f32.bf16.bf16.f32 "
        "{%0,%1,%2,%3}, {%4,%5,%6,%7}, {%8,%9}, {%0,%1,%2,%3};"
        : "+f"(c[0]), "+f"(c[1]), "+f"(c[2]), "+f"(c[3])
        : "r"(a[0]), "r"(a[1]), "r"(a[2]), "r"(a[3]), "r"(b[0]), "r"(b[1]));
}

// ---------------------------------------------------------------------------
// bf16 split GEMM via mma.sync: C = (Ah+Al)(Bh+Bl)^T + bias  (drop Al*Bl)
// A: [1024,1024] K-major.  B: [2048,1024] K-major per batch.
// Block tile 128x128, k-block 32 (row = 128B: hi[0:64B] | lo[64:128B]).
// 8 warps (2x4), warp tile 64x32.
// ---------------------------------------------------------------------------
__global__ __launch_bounds__(256)
void mma_gemm(const __nv_bfloat16* __restrict__ Ah, const __nv_bfloat16* __restrict__ Al,
              const __nv_bfloat16* __restrict__ Bh, const __nv_bfloat16* __restrict__ Bl,
              const float* __restrict__ bias, float* __restrict__ Cout,
              const unsigned* __restrict__ mask, int transOut)
{
    __shared__ __align__(1024) unsigned char smA[16384];
    __shared__ __align__(1024) unsigned char smB[16384];

    const int b    = blockIdx.z;
    const int n0   = blockIdx.x * 128;
    const int m0   = blockIdx.y * 128;
    const int tid  = threadIdx.x;
    const int wid  = tid >> 5;
    const int lane = tid & 31;
    const int wy   = wid & 1;    // m half (64)
    const int wx   = wid >> 1;   // n quarter (32)

    const uint32_t smA_u = smem_u32(smA);
    const uint32_t smB_u = smem_u32(smB);

    const __nv_bfloat16* Bhb = Bh + (size_t)b * TDIM * CDIM;
    const __nv_bfloat16* Blb = Bl + (size_t)b * TDIM * CDIM;

    const int r     = tid >> 1;
    const int which = tid & 1;                       // 0 = hi, 1 = lo
    const __nv_bfloat16* Asrc = which ? Al  : Ah;
    const __nv_bfloat16* Bsrc = which ? Blb : Bhb;
    const size_t aOff = (size_t)(m0 + r) * CDIM;
    const size_t bOff = (size_t)(n0 + r) * CDIM;
    const uint32_t rowb = (uint32_t)r * 128 + (uint32_t)which * 64;

    float acc[4][4][4];
#pragma unroll
    for (int i = 0; i < 4; ++i)
#pragma unroll
        for (int j = 0; j < 4; ++j)
#pragma unroll
            for (int c = 0; c < 4; ++c) acc[i][j][c] = 0.f;

    // precomputed ldmatrix lane addresses (byte offsets within tile, pre-swizzle)
    const uint32_t aRow = (uint32_t)(wy * 64 + (lane & 15));
    const uint32_t aCol = (uint32_t)((lane >> 4) << 4);
    const uint32_t bRow = (uint32_t)(wx * 32 + (lane & 7) + ((lane >> 4) << 3));
    const uint32_t bCol = (uint32_t)(((lane >> 3) & 1) << 4);

    for (int kb = 0; kb < 32; ++kb) {
        const int k0 = kb * 32;
        const uint4* pa = (const uint4*)(Asrc + aOff + k0);
        const uint4* pb = (const uint4*)(Bsrc + bOff + k0);
        uint4 av0 = pa[0], av1 = pa[1], av2 = pa[2], av3 = pa[3];
        uint4 bv0 = pb[0], bv1 = pb[1], bv2 = pb[2], bv3 = pb[3];

        __syncthreads();   // previous iteration's MMA reads complete
        *(uint4*)(smA + sw128(rowb +  0)) = av0;
        *(uint4*)(smA + sw128(rowb + 16)) = av1;
        *(uint4*)(smA + sw128(rowb + 32)) = av2;
        *(uint4*)(smA + sw128(rowb + 48)) = av3;
        *(uint4*)(smB + sw128(rowb +  0)) = bv0;
        *(uint4*)(smB + sw128(rowb + 16)) = bv1;
        *(uint4*)(smB + sw128(rowb + 32)) = bv2;
        *(uint4*)(smB + sw128(rowb + 48)) = bv3;
        __syncthreads();

#pragma unroll
        for (int s = 0; s < 2; ++s) {
            const uint32_t ksA = s * 32;      // hi at +0, lo at +64
            uint32_t afr[4][4], bh[4][2], bl[4][2];

            // A-hi fragments (4 m-tiles)
#pragma unroll
            for (int mt = 0; mt < 4; ++mt)
                ldsm4(afr[mt], smA_u + sw128((aRow + mt * 16) * 128 + ksA + aCol));
            // B-hi fragments (4 n-tiles via 2 x4 loads)
#pragma unroll
            for (int np = 0; np < 2; ++np) {
                uint32_t rr[4];
                ldsm4(rr, smB_u + sw128((bRow + np * 16) * 128 + ksA + bCol));
                bh[np * 2 + 0][0] = rr[0]; bh[np * 2 + 0][1] = rr[1];
                bh[np * 2 + 1][0] = rr[2]; bh[np * 2 + 1][1] = rr[3];
            }
            // hh
#pragma unroll
            for (int mt = 0; mt < 4; ++mt)
#pragma unroll
                for (int nt = 0; nt < 4; ++nt)
                    mma16816(acc[mt][nt], afr[mt], bh[nt]);

            // B-lo fragments
#pragma unroll
            for (int np = 0; np < 2; ++np) {
                uint32_t rr[4];
                ldsm4(rr, smB_u + sw128((bRow + np * 16) * 128 + 64 + ksA + bCol));
                bl[np * 2 + 0][0] = rr[0]; bl[np * 2 + 0][1] = rr[1];
                bl[np * 2 + 1][0] = rr[2]; bl[np * 2 + 1][1] = rr[3];
            }
            // h*lo
#pragma unroll
            for (int mt = 0; mt < 4; ++mt)
#pragma unroll
                for (int nt = 0; nt < 4; ++nt)
                    mma16816(acc[mt][nt], afr[mt], bl[nt]);

            // A-lo fragments (reuse afr)
#pragma unroll
            for (int mt = 0; mt < 4; ++mt)
                ldsm4(afr[mt], smA_u + sw128((aRow + mt * 16) * 128 + 64 + ksA + aCol));
            // lo*h
#pragma unroll
            for (int mt = 0; mt < 4; ++mt)
#pragma unroll
                for (int nt = 0; nt < 4; ++nt)
                    mma16816(acc[mt][nt], afr[mt], bh[nt]);
        }
    }

    // epilogue
    const unsigned* mb = mask ? (mask + (size_t)b * TDIM) : nullptr;
    const int qrow = lane >> 2;
    const int qcol = (lane & 3) * 2;
#pragma unroll
    for (int mt = 0; mt < 4; ++mt) {
#pragma unroll
        for (int rh = 0; rh < 2; ++rh) {
            const int row = m0 + wy * 64 + mt * 16 + qrow + rh * 8;
            const float bi = bias[row];
#pragma unroll
            for (int nt = 0; nt < 4; ++nt) {
                const int col = n0 + wx * 32 + nt * 8 + qcol;
                float v0 = acc[mt][nt][rh * 2 + 0] + bi;
                float v1 = acc[mt][nt][rh * 2 + 1] + bi;
                if (mb) {
                    v0 *= (mb[col + 0] ? 1.f : 0.f);
                    v1 *= (mb[col + 1] ? 1.f : 0.f);
                }
                if (!transOut) {
                    float2* dst = (float2*)(Cout + (size_t)b * CDIM * TDIM +
                                            (size_t)row * TDIM + col);
                    *dst = make_float2(v0, v1);
                } else {
                    float* dst = Cout + (size_t)b * TDIM * CDIM;
                    dst[(size_t)(col + 0) * CDIM + row] = v0;
                    dst[(size_t)(col + 1) * CDIM + row] = v1;
                }
            }
        }
    }
}

// ---------------------------------------------------------------------------
__global__ void split_w_kernel(const float* __restrict__ w,
                               __nv_bfloat16* __restrict__ hi,
                               __nv_bfloat16* __restrict__ lo, int n)
{
    int i = blockIdx.x * blockDim.x + threadIdx.x;
    if (i < n) {
        float v = w[i];
        __nv_bfloat16 h = __float2bfloat16(v);
        hi[i] = h;
        lo[i] = __float2bfloat16(v - __bfloat162float(h));
    }
}

// ---------------------------------------------------------------------------
__global__ __launch_bounds__(256)
void transpose_split_kernel(const float* __restrict__ src,
                            __nv_bfloat16* __restrict__ dh,
                            __nv_bfloat16* __restrict__ dl)
{
    __shared__ float tile[32][33];
    const int b = blockIdx.z;
    const float* s = src + (size_t)b * CDIM * TDIM;
    __nv_bfloat16* ph = dh + (size_t)b * TDIM * CDIM;
    __nv_bfloat16* pl = dl + (size_t)b * TDIM * CDIM;
    const int tx = threadIdx.x, ty = threadIdx.y;
    const int t0 = blockIdx.x * 32, c0 = blockIdx.y * 32;
#pragma unroll
    for (int i = 0; i < 4; ++i)
        tile[ty + i * 8][tx] = s[(size_t)(c0 + ty + i * 8) * TDIM + t0 + tx];
    __syncthreads();
#pragma unroll
    for (int i = 0; i < 4; ++i) {
        float v = tile[tx][ty + i * 8];
        __nv_bfloat16 h = __float2bfloat16(v);
        size_t idx = (size_t)(t0 + ty + i * 8) * CDIM + c0 + tx;
        ph[idx] = h;
        pl[idx] = __float2bfloat16(v - __bfloat162float(h));
    }
}

// ---------------------------------------------------------------------------
// Flash-style masked attention (fp32 SIMT, proven R1).
// ---------------------------------------------------------------------------
__global__ __launch_bounds__(256)
void attn_kernel(const float* __restrict__ Q, const float* __restrict__ K,
                 const float* __restrict__ Vt, const unsigned* __restrict__ mask,
                 float* __restrict__ O)
{
    __shared__ float sm[3 * 64 * 64];
    float* qsT   = sm;
    float* ks_ps = sm + 4096;
    float* vs    = sm + 8192;

    const int b  = blockIdx.z;
    const int h  = blockIdx.y;
    const int q0 = blockIdx.x * 64;

    const size_t base = ((size_t)b * CDIM + h * DH) * TDIM;
    const float* Qb = Q + base;
    const float* Kb = K + base;
    const float* Vb = Vt + (size_t)b * TDIM * CDIM + h * DH;
    const unsigned* mb = mask + (size_t)b * TDIM;
    float* Ob = O + base;

    const int tid = threadIdx.x;
    const int tx  = tid & 15;
    const int ty  = tid >> 4;
    const int i0  = ty * 4;
    const int j0  = tx * 4;

    {
        const int g4 = tid & 15;
        const int d0 = tid >> 4;
#pragma unroll
        for (int rr = 0; rr < 4; ++rr) {
            const int d = d0 + rr * 16;
            float4 v = *(const float4*)(Qb + (size_t)d * TDIM + q0 + g4 * 4);
            *(float4*)&qsT[d * 64 + g4 * 4] = v;
        }
    }

    float m[4], l[4], acc[4][4];
#pragma unroll
    for (int i = 0; i < 4; ++i) {
        m[i] = -1e30f; l[i] = 0.f;
#pragma unroll
        for (int c = 0; c < 4; ++c) acc[i][c] = 0.f;
    }

    const float scale = 0.125f;

    for (int k0 = 0; k0 < TDIM; k0 += 64) {
        __syncthreads();
        {
            const int g4 = tid & 15;
            const int r0 = tid >> 4;
#pragma unroll
            for (int rr = 0; rr < 4; ++rr) {
                const int d = r0 + rr * 16;
                float4 v = *(const float4*)(Kb + (size_t)d * TDIM + k0 + g4 * 4);
                *(float4*)&ks_ps[d * 64 + g4 * 4] = v;
            }
#pragma unroll
            for (int rr = 0; rr < 4; ++rr) {
                const int j = r0 + rr * 16;
                float4 v = *(const float4*)(Vb + (size_t)(k0 + j) * CDIM + g4 * 4);
                *(float4*)&vs[j * 64 + g4 * 4] = v;
            }
        }
        __syncthreads();

        float s[4][4];
#pragma unroll
        for (int i = 0; i < 4; ++i)
#pragma unroll
            for (int j = 0; j < 4; ++j) s[i][j] = 0.f;

#pragma unroll 4
        for (int d = 0; d < 64; ++d) {
            float4 qv = *(const float4*)&qsT[d * 64 + i0];
            float4 kv = *(const float4*)&ks_ps[d * 64 + j0];
            float qr[4] = {qv.x, qv.y, qv.z, qv.w};
            float kr[4] = {kv.x, kv.y, kv.z, kv.w};
#pragma unroll
            for (int i = 0; i < 4; ++i)
#pragma unroll
                for (int j = 0; j < 4; ++j)
                    s[i][j] = fmaf(qr[i], kr[j], s[i][j]);
        }

        unsigned mk[4];
#pragma unroll
        for (int j = 0; j < 4; ++j) mk[j] = mb[k0 + j0 + j];
#pragma unroll
        for (int i = 0; i < 4; ++i)
#pragma unroll
            for (int j = 0; j < 4; ++j)
                s[i][j] = mk[j] ? s[i][j] * scale : -1e30f;

        float fac[4];
#pragma unroll
        for (int i = 0; i < 4; ++i) {
            float mm = fmaxf(fmaxf(s[i][0], s[i][1]), fmaxf(s[i][2], s[i][3]));
#pragma unroll
            for (int off = 8; off; off >>= 1)
                mm = fmaxf(mm, __shfl_xor_sync(0xffffffffu, mm, off, 16));
            const float mnew = fmaxf(m[i], mm);
            float ls = 0.f;
#pragma unroll
            for (int j = 0; j < 4; ++j) {
                const float p = mk[j] ? __expf(s[i][j] - mnew) : 0.f;
                s[i][j] = p;
                ls += p;
            }
#pragma unroll
            for (int off = 8; off; off >>= 1)
                ls += __shfl_xor_sync(0xffffffffu, ls, off, 16);
            fac[i] = __expf(m[i] - mnew);
            l[i] = l[i] * fac[i] + ls;
            m[i] = mnew;
#pragma unroll
            for (int c = 0; c < 4; ++c) acc[i][c] *= fac[i];
        }

        __syncthreads();
#pragma unroll
        for (int i = 0; i < 4; ++i) {
            float4 pv = make_float4(s[i][0], s[i][1], s[i][2], s[i][3]);
            *(float4*)&ks_ps[(i0 + i) * 64 + j0] = pv;
        }
        __syncthreads();

#pragma unroll 4
        for (int j = 0; j < 64; ++j) {
            float4 v = *(const float4*)&vs[j * 64 + j0];
            float p0 = ks_ps[(i0 + 0) * 64 + j];
            float p1 = ks_ps[(i0 + 1) * 64 + j];
            float p2 = ks_ps[(i0 + 2) * 64 + j];
            float p3 = ks_ps[(i0 + 3) * 64 + j];
            acc[0][0] = fmaf(p0, v.x, acc[0][0]); acc[0][1] = fmaf(p0, v.y, acc[0][1]);
            acc[0][2] = fmaf(p0, v.z, acc[0][2]); acc[0][3] = fmaf(p0, v.w, acc[0][3]);
            acc[1][0] = fmaf(p1, v.x, acc[1][0]); acc[1][1] = fmaf(p1, v.y, acc[1][1]);
            acc[1][2] = fmaf(p1, v.z, acc[1][2]); acc[1][3] = fmaf(p1, v.w, acc[1][3]);
            acc[2][0] = fmaf(p2, v.x, acc[2][0]); acc[2][1] = fmaf(p2, v.y, acc[2][1]);
            acc[2][2] = fmaf(p2, v.z, acc[2][2]); acc[2][3] = fmaf(p2, v.w, acc[2][3]);
            acc[3][0] = fmaf(p3, v.x, acc[3][0]); acc[3][1] = fmaf(p3, v.y, acc[3][1]);
            acc[3][2] = fmaf(p3, v.z, acc[3][2]); acc[3][3] = fmaf(p3, v.w, acc[3][3]);
        }
    }

#pragma unroll
    for (int i = 0; i < 4; ++i) {
        const float inv = (l[i] > 0.f) ? (1.f / l[i]) : 0.f;
        const int qi = q0 + i0 + i;
#pragma unroll
        for (int c = 0; c < 4; ++c) {
            const int d = j0 + c;
            Ob[(size_t)d * TDIM + qi] = acc[i][c] * inv;
        }
    }
}

// ---------------------------------------------------------------------------
__global__ void write_mask_kernel(const unsigned* __restrict__ mask,
                                  float* __restrict__ out, int n)
{
    int i = blockIdx.x * blockDim.x + threadIdx.x;
    if (i < n) out[i] = mask[i] ? 1.0f : 0.0f;
}

// ---------------------------------------------------------------------------
extern "C" void kernel_launch(void* const* d_in, const int* in_sizes, int n_in,
                              void* d_out, int out_size)
{
    const float*    x    = (const float*)d_in[0];
    const unsigned* mask = (const unsigned*)d_in[1];
    const float*    Wq   = (const float*)d_in[2];
    const float*    bq   = (const float*)d_in[3];
    const float*    Wk   = (const float*)d_in[4];
    const float*    bk   = (const float*)d_in[5];
    const float*    Wv   = (const float*)d_in[6];
    const float*    bv   = (const float*)d_in[7];
    const float*    Wp   = (const float*)d_in[8];
    const float*    bp   = (const float*)d_in[9];
    float* out = (float*)d_out;

    float *gq, *gk, *gvt, *gao;
    __nv_bfloat16 *wh, *wl, *xh, *xl, *ah, *al;
    cudaGetSymbolAddress((void**)&gq,  g_Q);
    cudaGetSymbolAddress((void**)&gk,  g_K);
    cudaGetSymbolAddress((void**)&gvt, g_Vt);
    cudaGetSymbolAddress((void**)&gao, g_AO);
    cudaGetSymbolAddress((void**)&wh,  g_Wh);
    cudaGetSymbolAddress((void**)&wl,  g_Wl);
    cudaGetSymbolAddress((void**)&xh,  g_xTh);
    cudaGetSymbolAddress((void**)&xl,  g_xTl);
    cudaGetSymbolAddress((void**)&ah,  g_aTh);
    cudaGetSymbolAddress((void**)&al,  g_aTl);

    const int WN = CDIM * CDIM;
    const int wblk = (WN + 255) / 256;
    split_w_kernel<<<wblk, 256>>>(Wq, wh + 0 * (size_t)WN, wl + 0 * (size_t)WN, WN);
    split_w_kernel<<<wblk, 256>>>(Wk, wh + 1 * (size_t)WN, wl + 1 * (size_t)WN, WN);
    split_w_kernel<<<wblk, 256>>>(Wv, wh + 2 * (size_t)WN, wl + 2 * (size_t)WN, WN);
    split_w_kernel<<<wblk, 256>>>(Wp, wh + 3 * (size_t)WN, wl + 3 * (size_t)WN, WN);

    dim3 gt(TDIM / 32, CDIM / 32, BSZ);
    transpose_split_kernel<<<gt, dim3(32, 8)>>>(x, xh, xl);

    dim3 gg(TDIM / 128, CDIM / 128, BSZ);
    mma_gemm<<<gg, 256>>>(wh + 0 * (size_t)WN, wl + 0 * (size_t)WN, xh, xl, bq, gq,  nullptr, 0);
    mma_gemm<<<gg, 256>>>(wh + 1 * (size_t)WN, wl + 1 * (size_t)WN, xh, xl, bk, gk,  nullptr, 0);
    mma_gemm<<<gg, 256>>>(wh + 2 * (size_t)WN, wl + 2 * (size_t)WN, xh, xl, bv, gvt, nullptr, 1);

    dim3 ga(TDIM / 64, HN, BSZ);
    attn_kernel<<<ga, 256>>>(gq, gk, gvt, mask, gao);

    transpose_split_kernel<<<gt, dim3(32, 8)>>>(gao, ah, al);
    mma_gemm<<<gg, 256>>>(wh + 3 * (size_t)WN, wl + 3 * (size_t)WN, ah, al, bp, out, mask, 0);

    const long long nout = (long long)BSZ * CDIM * TDIM;
    const int tail = out_size - (int)nout;
    if (tail >= BSZ * TDIM) {
        write_mask_kernel<<<(BSZ * TDIM + 255) / 256, 256>>>(
            mask, out + nout, BSZ * TDIM);
    }
}

// round 4
// speedup vs baseline: 2.9321x; 2.4915x over previous
#include <cuda_runtime.h>
#include <cuda_bf16.h>
#include <stdint.h>

#define BSZ  2
#define CDIM 1024
#define TDIM 2048
#define HN   16
#define DH   64

// ---------------- scratch (static device globals; zero-init persists for
// rows >= cnt, which are never written — padded tiles multiply exact zeros) ----
__device__ float g_Q [(size_t)BSZ * CDIM * TDIM];
__device__ float g_K [(size_t)BSZ * CDIM * TDIM];
__device__ float g_Vt[(size_t)BSZ * CDIM * TDIM];   // (B, Tc, C) compact
__device__ __nv_bfloat16 g_Wh [(size_t)4 * CDIM * CDIM];
__device__ __nv_bfloat16 g_Wl [(size_t)4 * CDIM * CDIM];
__device__ __nv_bfloat16 g_xTh[(size_t)BSZ * TDIM * CDIM];   // (B, Tc, C) bf16 hi
__device__ __nv_bfloat16 g_xTl[(size_t)BSZ * TDIM * CDIM];
__device__ __nv_bfloat16 g_aTh[(size_t)BSZ * TDIM * CDIM];   // attn out hi (B, Tc, C)
__device__ __nv_bfloat16 g_aTl[(size_t)BSZ * TDIM * CDIM];
__device__ int g_idx[BSZ * TDIM];
__device__ int g_cnt[BSZ];

// ---------------- helpers ----------------
__device__ __forceinline__ uint32_t smem_u32(const void* p) {
    uint32_t a;
    asm("{ .reg .u64 t; cvta.to.shared.u64 t, %1; cvt.u32.u64 %0, t; }" : "=r"(a) : "l"(p));
    return a;
}
__device__ __forceinline__ uint32_t sw128(uint32_t off) { return off ^ ((off >> 3) & 0x70); }

__device__ __forceinline__ void ldsm4(uint32_t* r, uint32_t addr) {
    asm volatile("ldmatrix.sync.aligned.m8n8.x4.shared.b16 {%0,%1,%2,%3}, [%4];"
        : "=r"(r[0]), "=r"(r[1]), "=r"(r[2]), "=r"(r[3]) : "r"(addr));
}
__device__ __forceinline__ void mma16816(float* c, const uint32_t* a, const uint32_t* b) {
    asm volatile("mma.sync.aligned.m16n8k16.row.col.f32.bf16.bf16.f32 "
        "{%0,%1,%2,%3}, {%4,%5,%6,%7}, {%8,%9}, {%0,%1,%2,%3};"
        : "+f"(c[0]), "+f"(c[1]), "+f"(c[2]), "+f"(c[3])
        : "r"(a[0]), "r"(a[1]), "r"(a[2]), "r"(a[3]), "r"(b[0]), "r"(b[1]));
}

// ---------------------------------------------------------------------------
// Deterministic compaction: per batch, idx[i] = i-th valid t (ascending),
// cnt = number of valid positions. Block-wide prefix scan, 256 threads.
// ---------------------------------------------------------------------------
__global__ __launch_bounds__(256)
void compact_kernel(const unsigned* __restrict__ mask, int* __restrict__ idx,
                    int* __restrict__ cnt)
{
    __shared__ int wsum[8];
    __shared__ int wexcl[8];
    const int b = blockIdx.x;
    const unsigned* mb = mask + (size_t)b * TDIM;
    int* ib = idx + (size_t)b * TDIM;
    const int tid  = threadIdx.x;
    const int lane = tid & 31, w = tid >> 5;
    unsigned v[8]; int c = 0;
#pragma unroll
    for (int i = 0; i < 8; ++i) { v[i] = mb[tid * 8 + i]; c += v[i] ? 1 : 0; }
    int inc = c;
#pragma unroll
    for (int off = 1; off < 32; off <<= 1) {
        int n = __shfl_up_sync(0xffffffffu, inc, off);
        if (lane >= off) inc += n;
    }
    if (lane == 31) wsum[w] = inc;
    __syncthreads();
    if (tid == 0) {
        int s = 0;
#pragma unroll
        for (int i = 0; i < 8; ++i) { wexcl[i] = s; s += wsum[i]; }
        cnt[b] = s;
    }
    __syncthreads();
    int p = wexcl[w] + inc - c;
#pragma unroll
    for (int i = 0; i < 8; ++i) if (v[i]) ib[p++] = tid * 8 + i;
}

// ---------------------------------------------------------------------------
// Gather + transpose + hi/lo split: x (B,C,T) -> (B, Tc, C) bf16 hi/lo.
// ---------------------------------------------------------------------------
__global__ __launch_bounds__(256)
void gather_transpose_split(const float* __restrict__ src,
                            const int* __restrict__ idx, const int* __restrict__ cnt,
                            __nv_bfloat16* __restrict__ dh, __nv_bfloat16* __restrict__ dl)
{
    __shared__ float tile[32][33];
    __shared__ int tloc[32];
    const int b = blockIdx.z;
    const int n = cnt[b];
    const int i0 = blockIdx.x * 32;
    if (i0 >= n) return;
    const int c0 = blockIdx.y * 32;
    const float* s = src + (size_t)b * CDIM * TDIM;
    __nv_bfloat16* ph = dh + (size_t)b * TDIM * CDIM;
    __nv_bfloat16* pl = dl + (size_t)b * TDIM * CDIM;
    const int tx = threadIdx.x, ty = threadIdx.y;
    if (ty == 0) tloc[tx] = (i0 + tx < n) ? idx[b * TDIM + i0 + tx] : -1;
    __syncthreads();
    const int t = tloc[tx];
#pragma unroll
    for (int i = 0; i < 4; ++i)
        tile[ty + i * 8][tx] = (t >= 0) ? s[(size_t)(c0 + ty + i * 8) * TDIM + t] : 0.f;
    __syncthreads();
#pragma unroll
    for (int i = 0; i < 4; ++i) {
        const int irow = i0 + ty + i * 8;
        if (irow < n) {
            float v = tile[tx][ty + i * 8];
            __nv_bfloat16 h = __float2bfloat16(v);
            size_t o = (size_t)irow * CDIM + c0 + tx;
            ph[o] = h;
            pl[o] = __float2bfloat16(v - __bfloat162float(h));
        }
    }
}

// ---------------------------------------------------------------------------
// bf16 split GEMM via mma.sync. A [1024,1024] K-major, B [Tc,1024] K-major.
// mode 0: dense (C,T) out (cols = compact pos). mode 1: (Tc,C) transposed out.
// mode 2: scatter cols through idx into (C,T) with bias (out pre-zeroed).
// ---------------------------------------------------------------------------
__global__ __launch_bounds__(256)
void mma_gemm(const __nv_bfloat16* __restrict__ Ah, const __nv_bfloat16* __restrict__ Al,
              const __nv_bfloat16* __restrict__ Bh, const __nv_bfloat16* __restrict__ Bl,
              const float* __restrict__ bias, float* __restrict__ Cout,
              const int* __restrict__ cnt, const int* __restrict__ idx, int mode)
{
    __shared__ __align__(1024) unsigned char smA[16384];
    __shared__ __align__(1024) unsigned char smB[16384];
    __shared__ int sidx[128];

    const int b    = blockIdx.z;
    const int nlim = cnt[b];
    const int n0   = blockIdx.x * 128;
    if (n0 >= nlim) return;
    const int m0   = blockIdx.y * 128;
    const int tid  = threadIdx.x;
    const int wid  = tid >> 5;
    const int lane = tid & 31;
    const int wy   = wid & 1;
    const int wx   = wid >> 1;

    const uint32_t smA_u = smem_u32(smA);
    const uint32_t smB_u = smem_u32(smB);

    const __nv_bfloat16* Bhb = Bh + (size_t)b * TDIM * CDIM;
    const __nv_bfloat16* Blb = Bl + (size_t)b * TDIM * CDIM;

    const int r     = tid >> 1;
    const int which = tid & 1;
    const __nv_bfloat16* Asrc = which ? Al  : Ah;
    const __nv_bfloat16* Bsrc = which ? Blb : Bhb;
    const size_t aOff = (size_t)(m0 + r) * CDIM;
    const size_t bOff = (size_t)(n0 + r) * CDIM;
    const uint32_t rowb = (uint32_t)r * 128 + (uint32_t)which * 64;

    float acc[4][4][4];
#pragma unroll
    for (int i = 0; i < 4; ++i)
#pragma unroll
        for (int j = 0; j < 4; ++j)
#pragma unroll
            for (int c = 0; c < 4; ++c) acc[i][j][c] = 0.f;

    const uint32_t aRow = (uint32_t)(wy * 64 + (lane & 15));
    const uint32_t aCol = (uint32_t)((lane >> 4) << 4);
    const uint32_t bRow = (uint32_t)(wx * 32 + (lane & 7) + ((lane >> 4) << 3));
    const uint32_t bCol = (uint32_t)(((lane >> 3) & 1) << 4);

    for (int kb = 0; kb < 32; ++kb) {
        const int k0 = kb * 32;
        const uint4* pa = (const uint4*)(Asrc + aOff + k0);
        const uint4* pb = (const uint4*)(Bsrc + bOff + k0);
        uint4 av0 = pa[0], av1 = pa[1], av2 = pa[2], av3 = pa[3];
        uint4 bv0 = pb[0], bv1 = pb[1], bv2 = pb[2], bv3 = pb[3];

        __syncthreads();
        *(uint4*)(smA + sw128(rowb +  0)) = av0;
        *(uint4*)(smA + sw128(rowb + 16)) = av1;
        *(uint4*)(smA + sw128(rowb + 32)) = av2;
        *(uint4*)(smA + sw128(rowb + 48)) = av3;
        *(uint4*)(smB + sw128(rowb +  0)) = bv0;
        *(uint4*)(smB + sw128(rowb + 16)) = bv1;
        *(uint4*)(smB + sw128(rowb + 32)) = bv2;
        *(uint4*)(smB + sw128(rowb + 48)) = bv3;
        __syncthreads();

#pragma unroll
        for (int s = 0; s < 2; ++s) {
            const uint32_t ksA = s * 32;
            uint32_t afr[4][4], bh[4][2], bl[4][2];
#pragma unroll
            for (int mt = 0; mt < 4; ++mt)
                ldsm4(afr[mt], smA_u + sw128((aRow + mt * 16) * 128 + ksA + aCol));
#pragma unroll
            for (int np = 0; np < 2; ++np) {
                uint32_t rr[4];
                ldsm4(rr, smB_u + sw128((bRow + np * 16) * 128 + ksA + bCol));
                bh[np * 2 + 0][0] = rr[0]; bh[np * 2 + 0][1] = rr[1];
                bh[np * 2 + 1][0] = rr[2]; bh[np * 2 + 1][1] = rr[3];
            }
#pragma unroll
            for (int mt = 0; mt < 4; ++mt)
#pragma unroll
                for (int nt = 0; nt < 4; ++nt)
                    mma16816(acc[mt][nt], afr[mt], bh[nt]);
#pragma unroll
            for (int np = 0; np < 2; ++np) {
                uint32_t rr[4];
                ldsm4(rr, smB_u + sw128((bRow + np * 16) * 128 + 64 + ksA + bCol));
                bl[np * 2 + 0][0] = rr[0]; bl[np * 2 + 0][1] = rr[1];
                bl[np * 2 + 1][0] = rr[2]; bl[np * 2 + 1][1] = rr[3];
            }
#pragma unroll
            for (int mt = 0; mt < 4; ++mt)
#pragma unroll
                for (int nt = 0; nt < 4; ++nt)
                    mma16816(acc[mt][nt], afr[mt], bl[nt]);
#pragma unroll
            for (int mt = 0; mt < 4; ++mt)
                ldsm4(afr[mt], smA_u + sw128((aRow + mt * 16) * 128 + 64 + ksA + aCol));
#pragma unroll
            for (int mt = 0; mt < 4; ++mt)
#pragma unroll
                for (int nt = 0; nt < 4; ++nt)
                    mma16816(acc[mt][nt], afr[mt], bh[nt]);
        }
    }

    if (mode == 2) {
        if (tid < 128) sidx[tid] = (n0 + tid < nlim) ? idx[b * TDIM + n0 + tid] : -1;
        __syncthreads();
    }

    const int qrow = lane >> 2;
    const int qcol = (lane & 3) * 2;
#pragma unroll
    for (int mt = 0; mt < 4; ++mt) {
#pragma unroll
        for (int rh = 0; rh < 2; ++rh) {
            const int row = m0 + wy * 64 + mt * 16 + qrow + rh * 8;
            const float bi = bias[row];
#pragma unroll
            for (int nt = 0; nt < 4; ++nt) {
                const int col = n0 + wx * 32 + nt * 8 + qcol;
                float v0 = acc[mt][nt][rh * 2 + 0] + bi;
                float v1 = acc[mt][nt][rh * 2 + 1] + bi;
                if (mode == 0) {
                    float2* dst = (float2*)(Cout + (size_t)b * CDIM * TDIM +
                                            (size_t)row * TDIM + col);
                    *dst = make_float2(v0, v1);
                } else if (mode == 1) {
                    float* dst = Cout + (size_t)b * TDIM * CDIM;
                    dst[(size_t)(col + 0) * CDIM + row] = v0;
                    dst[(size_t)(col + 1) * CDIM + row] = v1;
                } else {
                    float* dst = Cout + (size_t)b * CDIM * TDIM + (size_t)row * TDIM;
                    const int t0 = sidx[col - n0 + 0];
                    const int t1 = sidx[col - n0 + 1];
                    if (t0 >= 0) dst[t0] = v0;
                    if (t1 >= 0) dst[t1] = v1;
                }
            }
        }
    }
}

// ---------------------------------------------------------------------------
__global__ void split_w_kernel(const float* __restrict__ w,
                               __nv_bfloat16* __restrict__ hi,
                               __nv_bfloat16* __restrict__ lo, int n)
{
    int i = blockIdx.x * blockDim.x + threadIdx.x;
    if (i < n) {
        float v = w[i];
        __nv_bfloat16 h = __float2bfloat16(v);
        hi[i] = h;
        lo[i] = __float2bfloat16(v - __bfloat162float(h));
    }
}

// ---------------------------------------------------------------------------
// Flash-style attention over compacted positions (all keys valid; boundary
// handled by position < cnt). Writes hi/lo bf16 (B, Tc, C) directly.
// ---------------------------------------------------------------------------
__global__ __launch_bounds__(256)
void attn_kernel(const float* __restrict__ Q, const float* __restrict__ K,
                 const float* __restrict__ Vt, const int* __restrict__ cnt,
                 __nv_bfloat16* __restrict__ Oh, __nv_bfloat16* __restrict__ Ol)
{
    __shared__ float sm[3 * 64 * 64];
    float* qsT   = sm;
    float* ks_ps = sm + 4096;
    float* vs    = sm + 8192;

    const int b    = blockIdx.z;
    const int kend = cnt[b];
    const int q0   = blockIdx.x * 64;
    if (q0 >= kend) return;
    const int h = blockIdx.y;

    const size_t base = ((size_t)b * CDIM + h * DH) * TDIM;
    const float* Qb = Q + base;
    const float* Kb = K + base;
    const float* Vb = Vt + (size_t)b * TDIM * CDIM + h * DH;

    const int tid = threadIdx.x;
    const int tx  = tid & 15;
    const int ty  = tid >> 4;
    const int i0  = ty * 4;
    const int j0  = tx * 4;

    {
        const int g4 = tid & 15;
        const int d0 = tid >> 4;
#pragma unroll
        for (int rr = 0; rr < 4; ++rr) {
            const int d = d0 + rr * 16;
            float4 v = *(const float4*)(Qb + (size_t)d * TDIM + q0 + g4 * 4);
            *(float4*)&qsT[d * 64 + g4 * 4] = v;
        }
    }

    float m[4], l[4], acc[4][4];
#pragma unroll
    for (int i = 0; i < 4; ++i) {
        m[i] = -1e30f; l[i] = 0.f;
#pragma unroll
        for (int c = 0; c < 4; ++c) acc[i][c] = 0.f;
    }

    const float scale = 0.125f;

    for (int k0 = 0; k0 < kend; k0 += 64) {
        __syncthreads();
        {
            const int g4 = tid & 15;
            const int r0 = tid >> 4;
#pragma unroll
            for (int rr = 0; rr < 4; ++rr) {
                const int d = r0 + rr * 16;
                float4 v = *(const float4*)(Kb + (size_t)d * TDIM + k0 + g4 * 4);
                *(float4*)&ks_ps[d * 64 + g4 * 4] = v;
            }
#pragma unroll
            for (int rr = 0; rr < 4; ++rr) {
                const int j = r0 + rr * 16;
                float4 v = *(const float4*)(Vb + (size_t)(k0 + j) * CDIM + g4 * 4);
                *(float4*)&vs[j * 64 + g4 * 4] = v;
            }
        }
        __syncthreads();

        float s[4][4];
#pragma unroll
        for (int i = 0; i < 4; ++i)
#pragma unroll
            for (int j = 0; j < 4; ++j) s[i][j] = 0.f;

#pragma unroll 4
        for (int d = 0; d < 64; ++d) {
            float4 qv = *(const float4*)&qsT[d * 64 + i0];
            float4 kv = *(const float4*)&ks_ps[d * 64 + j0];
            float qr[4] = {qv.x, qv.y, qv.z, qv.w};
            float kr[4] = {kv.x, kv.y, kv.z, kv.w};
#pragma unroll
            for (int i = 0; i < 4; ++i)
#pragma unroll
                for (int j = 0; j < 4; ++j)
                    s[i][j] = fmaf(qr[i], kr[j], s[i][j]);
        }

        bool ok[4];
#pragma unroll
        for (int j = 0; j < 4; ++j) ok[j] = (k0 + j0 + j) < kend;
#pragma unroll
        for (int i = 0; i < 4; ++i)
#pragma unroll
            for (int j = 0; j < 4; ++j)
                s[i][j] = ok[j] ? s[i][j] * scale : -1e30f;

        float fac[4];
#pragma unroll
        for (int i = 0; i < 4; ++i) {
            float mm = fmaxf(fmaxf(s[i][0], s[i][1]), fmaxf(s[i][2], s[i][3]));
#pragma unroll
            for (int off = 8; off; off >>= 1)
                mm = fmaxf(mm, __shfl_xor_sync(0xffffffffu, mm, off, 16));
            const float mnew = fmaxf(m[i], mm);
            float ls = 0.f;
#pragma unroll
            for (int j = 0; j < 4; ++j) {
                const float p = ok[j] ? __expf(s[i][j] - mnew) : 0.f;
                s[i][j] = p;
                ls += p;
            }
#pragma unroll
            for (int off = 8; off; off >>= 1)
                ls += __shfl_xor_sync(0xffffffffu, ls, off, 16);
            fac[i] = __expf(m[i] - mnew);
            l[i] = l[i] * fac[i] + ls;
            m[i] = mnew;
#pragma unroll
            for (int c = 0; c < 4; ++c) acc[i][c] *= fac[i];
        }

        __syncthreads();
#pragma unroll
        for (int i = 0; i < 4; ++i) {
            float4 pv = make_float4(s[i][0], s[i][1], s[i][2], s[i][3]);
            *(float4*)&ks_ps[(i0 + i) * 64 + j0] = pv;
        }
        __syncthreads();

#pragma unroll 4
        for (int j = 0; j < 64; ++j) {
            float4 v = *(const float4*)&vs[j * 64 + j0];
            float p0 = ks_ps[(i0 + 0) * 64 + j];
            float p1 = ks_ps[(i0 + 1) * 64 + j];
            float p2 = ks_ps[(i0 + 2) * 64 + j];
            float p3 = ks_ps[(i0 + 3) * 64 + j];
            acc[0][0] = fmaf(p0, v.x, acc[0][0]); acc[0][1] = fmaf(p0, v.y, acc[0][1]);
            acc[0][2] = fmaf(p0, v.z, acc[0][2]); acc[0][3] = fmaf(p0, v.w, acc[0][3]);
            acc[1][0] = fmaf(p1, v.x, acc[1][0]); acc[1][1] = fmaf(p1, v.y, acc[1][1]);
            acc[1][2] = fmaf(p1, v.z, acc[1][2]); acc[1][3] = fmaf(p1, v.w, acc[1][3]);
            acc[2][0] = fmaf(p2, v.x, acc[2][0]); acc[2][1] = fmaf(p2, v.y, acc[2][1]);
            acc[2][2] = fmaf(p2, v.z, acc[2][2]); acc[2][3] = fmaf(p2, v.w, acc[2][3]);
            acc[3][0] = fmaf(p3, v.x, acc[3][0]); acc[3][1] = fmaf(p3, v.y, acc[3][1]);
            acc[3][2] = fmaf(p3, v.z, acc[3][2]); acc[3][3] = fmaf(p3, v.w, acc[3][3]);
        }
    }

    // write compact (Tc, C) bf16 hi/lo
#pragma unroll
    for (int i = 0; i < 4; ++i) {
        const int qi = q0 + i0 + i;
        if (qi < kend) {
            const float inv = (l[i] > 0.f) ? (1.f / l[i]) : 0.f;
            unsigned hp[2], lp[2];
#pragma unroll
            for (int c2 = 0; c2 < 2; ++c2) {
                float v0 = acc[i][c2 * 2 + 0] * inv;
                float v1 = acc[i][c2 * 2 + 1] * inv;
                __nv_bfloat16 h0 = __float2bfloat16(v0);
                __nv_bfloat16 h1 = __float2bfloat16(v1);
                __nv_bfloat16 l0 = __float2bfloat16(v0 - __bfloat162float(h0));
                __nv_bfloat16 l1 = __float2bfloat16(v1 - __bfloat162float(h1));
                hp[c2] = (unsigned)__bfloat16_as_ushort(h0) |
                         ((unsigned)__bfloat16_as_ushort(h1) << 16);
                lp[c2] = (unsigned)__bfloat16_as_ushort(l0) |
                         ((unsigned)__bfloat16_as_ushort(l1) << 16);
            }
            const size_t o = ((size_t)b * TDIM + qi) * CDIM + h * DH + j0;
            *(uint2*)&Oh[o] = make_uint2(hp[0], hp[1]);
            *(uint2*)&Ol[o] = make_uint2(lp[0], lp[1]);
        }
    }
}

// ---------------------------------------------------------------------------
__global__ void zero_kernel(float4* __restrict__ p, int n4)
{
    int i = blockIdx.x * blockDim.x + threadIdx.x;
    if (i < n4) p[i] = make_float4(0.f, 0.f, 0.f, 0.f);
}

__global__ void write_mask_kernel(const unsigned* __restrict__ mask,
                                  float* __restrict__ out, int n)
{
    int i = blockIdx.x * blockDim.x + threadIdx.x;
    if (i < n) out[i] = mask[i] ? 1.0f : 0.0f;
}

// ---------------------------------------------------------------------------
extern "C" void kernel_launch(void* const* d_in, const int* in_sizes, int n_in,
                              void* d_out, int out_size)
{
    const float*    x    = (const float*)d_in[0];
    const unsigned* mask = (const unsigned*)d_in[1];
    const float*    Wq   = (const float*)d_in[2];
    const float*    bq   = (const float*)d_in[3];
    const float*    Wk   = (const float*)d_in[4];
    const float*    bk   = (const float*)d_in[5];
    const float*    Wv   = (const float*)d_in[6];
    const float*    bv   = (const float*)d_in[7];
    const float*    Wp   = (const float*)d_in[8];
    const float*    bp   = (const float*)d_in[9];
    float* out = (float*)d_out;

    float *gq, *gk, *gvt;
    __nv_bfloat16 *wh, *wl, *xh, *xl, *ah, *al;
    int *gidx, *gcnt;
    cudaGetSymbolAddress((void**)&gq,   g_Q);
    cudaGetSymbolAddress((void**)&gk,   g_K);
    cudaGetSymbolAddress((void**)&gvt,  g_Vt);
    cudaGetSymbolAddress((void**)&wh,   g_Wh);
    cudaGetSymbolAddress((void**)&wl,   g_Wl);
    cudaGetSymbolAddress((void**)&xh,   g_xTh);
    cudaGetSymbolAddress((void**)&xl,   g_xTl);
    cudaGetSymbolAddress((void**)&ah,   g_aTh);
    cudaGetSymbolAddress((void**)&al,   g_aTl);
    cudaGetSymbolAddress((void**)&gidx, g_idx);
    cudaGetSymbolAddress((void**)&gcnt, g_cnt);

    compact_kernel<<<BSZ, 256>>>(mask, gidx, gcnt);

    const int n4 = BSZ * CDIM * TDIM / 4;
    zero_kernel<<<(n4 + 255) / 256, 256>>>((float4*)out, n4);

    const int WN = CDIM * CDIM;
    const int wblk = (WN + 255) / 256;
    split_w_kernel<<<wblk, 256>>>(Wq, wh + 0 * (size_t)WN, wl + 0 * (size_t)WN, WN);
    split_w_kernel<<<wblk, 256>>>(Wk, wh + 1 * (size_t)WN, wl + 1 * (size_t)WN, WN);
    split_w_kernel<<<wblk, 256>>>(Wv, wh + 2 * (size_t)WN, wl + 2 * (size_t)WN, WN);
    split_w_kernel<<<wblk, 256>>>(Wp, wh + 3 * (size_t)WN, wl + 3 * (size_t)WN, WN);

    dim3 gt(TDIM / 32, CDIM / 32, BSZ);
    gather_transpose_split<<<gt, dim3(32, 8)>>>(x, gidx, gcnt, xh, xl);

    dim3 gg(TDIM / 128, CDIM / 128, BSZ);
    mma_gemm<<<gg, 256>>>(wh + 0 * (size_t)WN, wl + 0 * (size_t)WN, xh, xl, bq, gq,  gcnt, gidx, 0);
    mma_gemm<<<gg, 256>>>(wh + 1 * (size_t)WN, wl + 1 * (size_t)WN, xh, xl, bk, gk,  gcnt, gidx, 0);
    mma_gemm<<<gg, 256>>>(wh + 2 * (size_t)WN, wl + 2 * (size_t)WN, xh, xl, bv, gvt, gcnt, gidx, 1);

    dim3 ga(TDIM / 64, HN, BSZ);
    attn_kernel<<<ga, 256>>>(gq, gk, gvt, gcnt, ah, al);

    mma_gemm<<<gg, 256>>>(wh + 3 * (size_t)WN, wl + 3 * (size_t)WN, ah, al, bp, out, gcnt, gidx, 2);

    const long long nout = (long long)BSZ * CDIM * TDIM;
    const int tail = out_size - (int)nout;
    if (tail >= BSZ * TDIM) {
        write_mask_kernel<<<(BSZ * TDIM + 255) / 256, 256>>>(
            mask, out + nout, BSZ * TDIM);
    }
}

// round 5
// speedup vs baseline: 4.0257x; 1.3730x over previous
#include <cuda_runtime.h>
#include <cuda_bf16.h>
#include <stdint.h>

#define BSZ  2
#define CDIM 1024
#define TDIM 2048
#define HN   16
#define DH   64

// ---------------- scratch (static device globals) ----------------
__device__ __nv_bfloat16 g_Wh [(size_t)4 * CDIM * CDIM];
__device__ __nv_bfloat16 g_Wl [(size_t)4 * CDIM * CDIM];
__device__ __nv_bfloat16 g_xTh[(size_t)BSZ * TDIM * CDIM];   // (B, Tc, C)
__device__ __nv_bfloat16 g_xTl[(size_t)BSZ * TDIM * CDIM];
__device__ __nv_bfloat16 g_qh [(size_t)BSZ * HN * TDIM * DH]; // (B,H,Tc,D)
__device__ __nv_bfloat16 g_ql [(size_t)BSZ * HN * TDIM * DH];
__device__ __nv_bfloat16 g_kh [(size_t)BSZ * HN * TDIM * DH];
__device__ __nv_bfloat16 g_kl [(size_t)BSZ * HN * TDIM * DH];
__device__ __nv_bfloat16 g_vh [(size_t)BSZ * CDIM * TDIM];    // (B, C, Tc)
__device__ __nv_bfloat16 g_vl [(size_t)BSZ * CDIM * TDIM];
__device__ __nv_bfloat16 g_aTh[(size_t)BSZ * TDIM * CDIM];    // attn out (B, Tc, C)
__device__ __nv_bfloat16 g_aTl[(size_t)BSZ * TDIM * CDIM];
__device__ int g_idx[BSZ * TDIM];
__device__ int g_cnt[BSZ];

// ---------------- helpers ----------------
__device__ __forceinline__ uint32_t smem_u32(const void* p) {
    uint32_t a;
    asm("{ .reg .u64 t; cvta.to.shared.u64 t, %1; cvt.u32.u64 %0, t; }" : "=r"(a) : "l"(p));
    return a;
}
__device__ __forceinline__ uint32_t sw128(uint32_t off) { return off ^ ((off >> 3) & 0x70); }

__device__ __forceinline__ void ldsm4(uint32_t* r, uint32_t addr) {
    asm volatile("ldmatrix.sync.aligned.m8n8.x4.shared.b16 {%0,%1,%2,%3}, [%4];"
        : "=r"(r[0]), "=r"(r[1]), "=r"(r[2]), "=r"(r[3]) : "r"(addr));
}
__device__ __forceinline__ void mma16816(float* c, const uint32_t* a, const uint32_t* b) {
    asm volatile("mma.sync.aligned.m16n8k16.row.col.f32.bf16.bf16.f32 "
        "{%0,%1,%2,%3}, {%4,%5,%6,%7}, {%8,%9}, {%0,%1,%2,%3};"
        : "+f"(c[0]), "+f"(c[1]), "+f"(c[2]), "+f"(c[3])
        : "r"(a[0]), "r"(a[1]), "r"(a[2]), "r"(a[3]), "r"(b[0]), "r"(b[1]));
}
__device__ __forceinline__ void split1(float v, __nv_bfloat16& h, __nv_bfloat16& l) {
    h = __float2bfloat16(v);
    l = __float2bfloat16(v - __bfloat162float(h));
}
__device__ __forceinline__ void split2(float v0, float v1, uint32_t& hi, uint32_t& lo) {
    __nv_bfloat16 h0, l0, h1, l1;
    split1(v0, h0, l0); split1(v1, h1, l1);
    hi = (uint32_t)__bfloat16_as_ushort(h0) | ((uint32_t)__bfloat16_as_ushort(h1) << 16);
    lo = (uint32_t)__bfloat16_as_ushort(l0) | ((uint32_t)__bfloat16_as_ushort(l1) << 16);
}

// ---------------------------------------------------------------------------
// Deterministic mask compaction.
// ---------------------------------------------------------------------------
__global__ __launch_bounds__(256)
void compact_kernel(const unsigned* __restrict__ mask, int* __restrict__ idx,
                    int* __restrict__ cnt)
{
    __shared__ int wsum[8];
    __shared__ int wexcl[8];
    const int b = blockIdx.x;
    const unsigned* mb = mask + (size_t)b * TDIM;
    int* ib = idx + (size_t)b * TDIM;
    const int tid  = threadIdx.x;
    const int lane = tid & 31, w = tid >> 5;
    unsigned v[8]; int c = 0;
#pragma unroll
    for (int i = 0; i < 8; ++i) { v[i] = mb[tid * 8 + i]; c += v[i] ? 1 : 0; }
    int inc = c;
#pragma unroll
    for (int off = 1; off < 32; off <<= 1) {
        int n = __shfl_up_sync(0xffffffffu, inc, off);
        if (lane >= off) inc += n;
    }
    if (lane == 31) wsum[w] = inc;
    __syncthreads();
    if (tid == 0) {
        int s = 0;
#pragma unroll
        for (int i = 0; i < 8; ++i) { wexcl[i] = s; s += wsum[i]; }
        cnt[b] = s;
    }
    __syncthreads();
    int p = wexcl[w] + inc - c;
#pragma unroll
    for (int i = 0; i < 8; ++i) if (v[i]) ib[p++] = tid * 8 + i;
}

// ---------------------------------------------------------------------------
// Gather + transpose + hi/lo split: x (B,C,T) -> (B, Tc, C) bf16 hi/lo.
// ---------------------------------------------------------------------------
__global__ __launch_bounds__(256)
void gather_transpose_split(const float* __restrict__ src,
                            const int* __restrict__ idx, const int* __restrict__ cnt,
                            __nv_bfloat16* __restrict__ dh, __nv_bfloat16* __restrict__ dl)
{
    __shared__ float tile[32][33];
    __shared__ int tloc[32];
    const int b = blockIdx.z;
    const int n = cnt[b];
    const int i0 = blockIdx.x * 32;
    if (i0 >= n) return;
    const int c0 = blockIdx.y * 32;
    const float* s = src + (size_t)b * CDIM * TDIM;
    __nv_bfloat16* ph = dh + (size_t)b * TDIM * CDIM;
    __nv_bfloat16* pl = dl + (size_t)b * TDIM * CDIM;
    const int tx = threadIdx.x, ty = threadIdx.y;
    if (ty == 0) tloc[tx] = (i0 + tx < n) ? idx[b * TDIM + i0 + tx] : -1;
    __syncthreads();
    const int t = tloc[tx];
#pragma unroll
    for (int i = 0; i < 4; ++i)
        tile[ty + i * 8][tx] = (t >= 0) ? s[(size_t)(c0 + ty + i * 8) * TDIM + t] : 0.f;
    __syncthreads();
#pragma unroll
    for (int i = 0; i < 4; ++i) {
        const int irow = i0 + ty + i * 8;
        if (irow < n) {
            float v = tile[tx][ty + i * 8];
            __nv_bfloat16 h, l; split1(v, h, l);
            size_t o = (size_t)irow * CDIM + c0 + tx;
            ph[o] = h; pl[o] = l;
        }
    }
}

// ---------------------------------------------------------------------------
// bf16 split GEMM via mma.sync. A [1024,1024] K-major, B [Tc,1024] K-major.
// mode 2: scatter fp32 cols through idx into (C,T) with bias (out pre-zeroed).
// mode 3: bf16 hi/lo out to (B,H,Tc,D)  [Q, K]
// mode 4: bf16 hi/lo out to (B,C,Tc)    [V]
// ---------------------------------------------------------------------------
__global__ __launch_bounds__(256)
void mma_gemm(const __nv_bfloat16* __restrict__ Ah, const __nv_bfloat16* __restrict__ Al,
              const __nv_bfloat16* __restrict__ Bh, const __nv_bfloat16* __restrict__ Bl,
              const float* __restrict__ bias, float* __restrict__ Cout,
              __nv_bfloat16* __restrict__ Ohp, __nv_bfloat16* __restrict__ Olp,
              const int* __restrict__ cnt, const int* __restrict__ idx, int mode)
{
    __shared__ __align__(1024) unsigned char smA[16384];
    __shared__ __align__(1024) unsigned char smB[16384];
    __shared__ int sidx[128];

    const int b    = blockIdx.z;
    const int nlim = cnt[b];
    const int n0   = blockIdx.x * 128;
    if (n0 >= nlim) return;
    const int m0   = blockIdx.y * 128;
    const int tid  = threadIdx.x;
    const int wid  = tid >> 5;
    const int lane = tid & 31;
    const int wy   = wid & 1;
    const int wx   = wid >> 1;

    const uint32_t smA_u = smem_u32(smA);
    const uint32_t smB_u = smem_u32(smB);

    const __nv_bfloat16* Bhb = Bh + (size_t)b * TDIM * CDIM;
    const __nv_bfloat16* Blb = Bl + (size_t)b * TDIM * CDIM;

    const int r     = tid >> 1;
    const int which = tid & 1;
    const __nv_bfloat16* Asrc = which ? Al  : Ah;
    const __nv_bfloat16* Bsrc = which ? Blb : Bhb;
    const size_t aOff = (size_t)(m0 + r) * CDIM;
    const size_t bOff = (size_t)(n0 + r) * CDIM;
    const uint32_t rowb = (uint32_t)r * 128 + (uint32_t)which * 64;

    float acc[4][4][4];
#pragma unroll
    for (int i = 0; i < 4; ++i)
#pragma unroll
        for (int j = 0; j < 4; ++j)
#pragma unroll
            for (int c = 0; c < 4; ++c) acc[i][j][c] = 0.f;

    const uint32_t aRow = (uint32_t)(wy * 64 + (lane & 15));
    const uint32_t aCol = (uint32_t)((lane >> 4) << 4);
    const uint32_t bRow = (uint32_t)(wx * 32 + (lane & 7) + ((lane >> 4) << 3));
    const uint32_t bCol = (uint32_t)(((lane >> 3) & 1) << 4);

    for (int kb = 0; kb < 32; ++kb) {
        const int k0 = kb * 32;
        const uint4* pa = (const uint4*)(Asrc + aOff + k0);
        const uint4* pb = (const uint4*)(Bsrc + bOff + k0);
        uint4 av0 = pa[0], av1 = pa[1], av2 = pa[2], av3 = pa[3];
        uint4 bv0 = pb[0], bv1 = pb[1], bv2 = pb[2], bv3 = pb[3];

        __syncthreads();
        *(uint4*)(smA + sw128(rowb +  0)) = av0;
        *(uint4*)(smA + sw128(rowb + 16)) = av1;
        *(uint4*)(smA + sw128(rowb + 32)) = av2;
        *(uint4*)(smA + sw128(rowb + 48)) = av3;
        *(uint4*)(smB + sw128(rowb +  0)) = bv0;
        *(uint4*)(smB + sw128(rowb + 16)) = bv1;
        *(uint4*)(smB + sw128(rowb + 32)) = bv2;
        *(uint4*)(smB + sw128(rowb + 48)) = bv3;
        __syncthreads();

#pragma unroll
        for (int s = 0; s < 2; ++s) {
            const uint32_t ksA = s * 32;
            uint32_t afr[4][4], bh[4][2], bl[4][2];
#pragma unroll
            for (int mt = 0; mt < 4; ++mt)
                ldsm4(afr[mt], smA_u + sw128((aRow + mt * 16) * 128 + ksA + aCol));
#pragma unroll
            for (int np = 0; np < 2; ++np) {
                uint32_t rr[4];
                ldsm4(rr, smB_u + sw128((bRow + np * 16) * 128 + ksA + bCol));
                bh[np * 2 + 0][0] = rr[0]; bh[np * 2 + 0][1] = rr[1];
                bh[np * 2 + 1][0] = rr[2]; bh[np * 2 + 1][1] = rr[3];
            }
#pragma unroll
            for (int mt = 0; mt < 4; ++mt)
#pragma unroll
                for (int nt = 0; nt < 4; ++nt)
                    mma16816(acc[mt][nt], afr[mt], bh[nt]);
#pragma unroll
            for (int np = 0; np < 2; ++np) {
                uint32_t rr[4];
                ldsm4(rr, smB_u + sw128((bRow + np * 16) * 128 + 64 + ksA + bCol));
                bl[np * 2 + 0][0] = rr[0]; bl[np * 2 + 0][1] = rr[1];
                bl[np * 2 + 1][0] = rr[2]; bl[np * 2 + 1][1] = rr[3];
            }
#pragma unroll
            for (int mt = 0; mt < 4; ++mt)
#pragma unroll
                for (int nt = 0; nt < 4; ++nt)
                    mma16816(acc[mt][nt], afr[mt], bl[nt]);
#pragma unroll
            for (int mt = 0; mt < 4; ++mt)
                ldsm4(afr[mt], smA_u + sw128((aRow + mt * 16) * 128 + 64 + ksA + aCol));
#pragma unroll
            for (int mt = 0; mt < 4; ++mt)
#pragma unroll
                for (int nt = 0; nt < 4; ++nt)
                    mma16816(acc[mt][nt], afr[mt], bh[nt]);
        }
    }

    if (mode == 2) {
        if (tid < 128) sidx[tid] = (n0 + tid < nlim) ? idx[b * TDIM + n0 + tid] : -1;
        __syncthreads();
    }

    const int qrow = lane >> 2;
    const int qcol = (lane & 3) * 2;
#pragma unroll
    for (int mt = 0; mt < 4; ++mt) {
#pragma unroll
        for (int rh = 0; rh < 2; ++rh) {
            const int row = m0 + wy * 64 + mt * 16 + qrow + rh * 8;
            const float bi = bias[row];
#pragma unroll
            for (int nt = 0; nt < 4; ++nt) {
                const int col = n0 + wx * 32 + nt * 8 + qcol;
                float v0 = acc[mt][nt][rh * 2 + 0] + bi;
                float v1 = acc[mt][nt][rh * 2 + 1] + bi;
                if (mode == 2) {
                    float* dst = Cout + (size_t)b * CDIM * TDIM + (size_t)row * TDIM;
                    const int t0 = sidx[col - n0 + 0];
                    const int t1 = sidx[col - n0 + 1];
                    if (t0 >= 0) dst[t0] = v0;
                    if (t1 >= 0) dst[t1] = v1;
                } else if (mode == 3) {
                    const int hh = row >> 6, dd = row & 63;
                    const size_t a0 = ((size_t)(b * HN + hh) * TDIM + col) * DH + dd;
                    __nv_bfloat16 h0, l0, h1, l1;
                    split1(v0, h0, l0); split1(v1, h1, l1);
                    Ohp[a0] = h0;       Olp[a0] = l0;
                    Ohp[a0 + DH] = h1;  Olp[a0 + DH] = l1;
                } else { // mode 4
                    const size_t a0 = ((size_t)b * CDIM + row) * TDIM + col;
                    uint32_t hi, lo; split2(v0, v1, hi, lo);
                    *(uint32_t*)&Ohp[a0] = hi;
                    *(uint32_t*)&Olp[a0] = lo;
                }
            }
        }
    }
}

// ---------------------------------------------------------------------------
__global__ void split_w_kernel(const float* __restrict__ w,
                               __nv_bfloat16* __restrict__ hi,
                               __nv_bfloat16* __restrict__ lo, int n)
{
    int i = blockIdx.x * blockDim.x + threadIdx.x;
    if (i < n) { __nv_bfloat16 h, l; split1(w[i], h, l); hi[i] = h; lo[i] = l; }
}

// ---------------------------------------------------------------------------
// Tensor-core flash attention over compact positions. 128 q per block, 8 warps
// (16 q rows each), 64-key tiles. Q,K: (B,H,Tc,D) hi/lo. V: (B,C,Tc) hi/lo.
// Out: (B,Tc,C) bf16 hi/lo.
// ---------------------------------------------------------------------------
__global__ __launch_bounds__(256)
void attn_mma(const __nv_bfloat16* __restrict__ Qh, const __nv_bfloat16* __restrict__ Ql,
              const __nv_bfloat16* __restrict__ Kh, const __nv_bfloat16* __restrict__ Kl,
              const __nv_bfloat16* __restrict__ Vh, const __nv_bfloat16* __restrict__ Vl,
              const int* __restrict__ cnt,
              __nv_bfloat16* __restrict__ Oh, __nv_bfloat16* __restrict__ Ol)
{
    __shared__ __align__(1024) unsigned char sm[32768];
    const int b = blockIdx.z, h = blockIdx.y;
    const int kend = cnt[b];
    const int q0 = blockIdx.x * 128;
    if (q0 >= kend) return;
    const int tid = threadIdx.x, wid = tid >> 5, lane = tid & 31;
    const uint32_t smu = smem_u32(sm);

    // ---- stage Q tile (hi @0, lo @16384), extract A-fragments ----
    const __nv_bfloat16* Qhb = Qh + ((size_t)(b * HN + h) * TDIM + q0) * DH;
    const __nv_bfloat16* Qlb = Ql + ((size_t)(b * HN + h) * TDIM + q0) * DH;
#pragma unroll
    for (int it = 0; it < 4; ++it) {
        const int lin = it * 256 + tid;         // 0..1023
        const int row = lin >> 3, qd = lin & 7;
        uint4 a = *(const uint4*)(Qhb + (size_t)row * DH + qd * 8);
        uint4 c = *(const uint4*)(Qlb + (size_t)row * DH + qd * 8);
        const uint32_t so = sw128((uint32_t)row * 128 + qd * 16);
        *(uint4*)(sm + so) = a;
        *(uint4*)(sm + 16384 + so) = c;
    }
    __syncthreads();
    uint32_t qfh[4][4], qfl[4][4];
    {
        const uint32_t aRow = wid * 16 + (lane & 15);
        const uint32_t aColB = (lane >> 4) << 4;
#pragma unroll
        for (int kk = 0; kk < 4; ++kk) {
            ldsm4(qfh[kk], smu + sw128(aRow * 128 + kk * 32 + aColB));
            ldsm4(qfl[kk], smu + 16384 + sw128(aRow * 128 + kk * 32 + aColB));
        }
    }
    __syncthreads();

    float oacc[8][4];
#pragma unroll
    for (int i = 0; i < 8; ++i)
#pragma unroll
        for (int c = 0; c < 4; ++c) oacc[i][c] = 0.f;
    float mrow[2] = {-1e30f, -1e30f}, lrow[2] = {0.f, 0.f};
    const float scale = 0.125f;
    const uint32_t bRow  = (lane & 7) + ((lane >> 4) << 3);
    const uint32_t bColB = ((lane >> 3) & 1) << 4;
    const int jc = (lane & 3) * 2;

    const __nv_bfloat16* Khb = Kh + ((size_t)(b * HN + h) * TDIM) * DH;
    const __nv_bfloat16* Klb = Kl + ((size_t)(b * HN + h) * TDIM) * DH;
    const __nv_bfloat16* Vhb = Vh + ((size_t)b * CDIM + h * DH) * TDIM;
    const __nv_bfloat16* Vlb = Vl + ((size_t)b * CDIM + h * DH) * TDIM;

    for (int k0 = 0; k0 < kend; k0 += 64) {
        // load K hi/lo (rows=key, cols=d) and V hi/lo (rows=d, cols=key)
#pragma unroll
        for (int it = 0; it < 2; ++it) {
            const int lin = it * 256 + tid;     // 0..511
            const int row = lin >> 3, qd = lin & 7;
            uint4 a = *(const uint4*)(Khb + (size_t)(k0 + row) * DH + qd * 8);
            uint4 c = *(const uint4*)(Klb + (size_t)(k0 + row) * DH + qd * 8);
            uint4 e = *(const uint4*)(Vhb + (size_t)row * TDIM + k0 + qd * 8);
            uint4 f = *(const uint4*)(Vlb + (size_t)row * TDIM + k0 + qd * 8);
            const uint32_t so = sw128((uint32_t)row * 128 + qd * 16);
            *(uint4*)(sm + so) = a;
            *(uint4*)(sm +  8192 + so) = c;
            *(uint4*)(sm + 16384 + so) = e;
            *(uint4*)(sm + 24576 + so) = f;
        }
        __syncthreads();

        // ---- S = Q K^T, hi/lo 3-pass ----
        float s[8][4];
#pragma unroll
        for (int i = 0; i < 8; ++i)
#pragma unroll
            for (int c = 0; c < 4; ++c) s[i][c] = 0.f;
#pragma unroll
        for (int kk = 0; kk < 4; ++kk) {
            uint32_t bh[8][2], bl2[8][2];
#pragma unroll
            for (int np = 0; np < 4; ++np) {
                uint32_t rr[4];
                ldsm4(rr, smu + sw128((np * 16 + bRow) * 128 + kk * 32 + bColB));
                bh[np * 2 + 0][0] = rr[0]; bh[np * 2 + 0][1] = rr[1];
                bh[np * 2 + 1][0] = rr[2]; bh[np * 2 + 1][1] = rr[3];
            }
#pragma unroll
            for (int nt = 0; nt < 8; ++nt) mma16816(s[nt], qfh[kk], bh[nt]);
#pragma unroll
            for (int np = 0; np < 4; ++np) {
                uint32_t rr[4];
                ldsm4(rr, smu + 8192 + sw128((np * 16 + bRow) * 128 + kk * 32 + bColB));
                bl2[np * 2 + 0][0] = rr[0]; bl2[np * 2 + 0][1] = rr[1];
                bl2[np * 2 + 1][0] = rr[2]; bl2[np * 2 + 1][1] = rr[3];
            }
#pragma unroll
            for (int nt = 0; nt < 8; ++nt) mma16816(s[nt], qfh[kk], bl2[nt]);
#pragma unroll
            for (int nt = 0; nt < 8; ++nt) mma16816(s[nt], qfl[kk], bh[nt]);
        }

        // ---- online softmax (rows r0=lane>>2, r0+8) ----
#pragma unroll
        for (int rh = 0; rh < 2; ++rh) {
            float mx = -1e30f;
#pragma unroll
            for (int nt = 0; nt < 8; ++nt) {
                const int jg = k0 + nt * 8 + jc;
                float v0 = (jg     < kend) ? s[nt][rh * 2 + 0] * scale : -1e30f;
                float v1 = (jg + 1 < kend) ? s[nt][rh * 2 + 1] * scale : -1e30f;
                s[nt][rh * 2 + 0] = v0; s[nt][rh * 2 + 1] = v1;
                mx = fmaxf(mx, fmaxf(v0, v1));
            }
            mx = fmaxf(mx, __shfl_xor_sync(0xffffffffu, mx, 1));
            mx = fmaxf(mx, __shfl_xor_sync(0xffffffffu, mx, 2));
            const float mnew = fmaxf(mrow[rh], mx);
            const float fac = __expf(mrow[rh] - mnew);
            mrow[rh] = mnew;
            float sum = 0.f;
#pragma unroll
            for (int nt = 0; nt < 8; ++nt) {
                float p0 = __expf(s[nt][rh * 2 + 0] - mnew);
                float p1 = __expf(s[nt][rh * 2 + 1] - mnew);
                s[nt][rh * 2 + 0] = p0; s[nt][rh * 2 + 1] = p1;
                sum += p0 + p1;
            }
            sum += __shfl_xor_sync(0xffffffffu, sum, 1);
            sum += __shfl_xor_sync(0xffffffffu, sum, 2);
            lrow[rh] = lrow[rh] * fac + sum;
#pragma unroll
            for (int nt = 0; nt < 8; ++nt) {
                oacc[nt][rh * 2 + 0] *= fac;
                oacc[nt][rh * 2 + 1] *= fac;
            }
        }

        // ---- P fp32 frag -> bf16 hi/lo A-fragments (accum layout == A layout) ----
        uint32_t ph[4][4], pl2[4][4];
#pragma unroll
        for (int kk2 = 0; kk2 < 4; ++kk2) {
            const int t0 = 2 * kk2, t1 = 2 * kk2 + 1;
            split2(s[t0][0], s[t0][1], ph[kk2][0], pl2[kk2][0]);
            split2(s[t0][2], s[t0][3], ph[kk2][1], pl2[kk2][1]);
            split2(s[t1][0], s[t1][1], ph[kk2][2], pl2[kk2][2]);
            split2(s[t1][2], s[t1][3], ph[kk2][3], pl2[kk2][3]);
        }

        // ---- O += P V, hi/lo 3-pass ----
#pragma unroll
        for (int kk2 = 0; kk2 < 4; ++kk2) {
            uint32_t vbh[8][2], vbl[8][2];
#pragma unroll
            for (int np = 0; np < 4; ++np) {
                uint32_t rr[4];
                ldsm4(rr, smu + 16384 + sw128((np * 16 + bRow) * 128 + kk2 * 32 + bColB));
                vbh[np * 2 + 0][0] = rr[0]; vbh[np * 2 + 0][1] = rr[1];
                vbh[np * 2 + 1][0] = rr[2]; vbh[np * 2 + 1][1] = rr[3];
            }
#pragma unroll
            for (int nt = 0; nt < 8; ++nt) mma16816(oacc[nt], ph[kk2], vbh[nt]);
#pragma unroll
            for (int np = 0; np < 4; ++np) {
                uint32_t rr[4];
                ldsm4(rr, smu + 24576 + sw128((np * 16 + bRow) * 128 + kk2 * 32 + bColB));
                vbl[np * 2 + 0][0] = rr[0]; vbl[np * 2 + 0][1] = rr[1];
                vbl[np * 2 + 1][0] = rr[2]; vbl[np * 2 + 1][1] = rr[3];
            }
#pragma unroll
            for (int nt = 0; nt < 8; ++nt) mma16816(oacc[nt], ph[kk2], vbl[nt]);
#pragma unroll
            for (int nt = 0; nt < 8; ++nt) mma16816(oacc[nt], pl2[kk2], vbh[nt]);
        }
        __syncthreads();
    }

    // ---- epilogue: normalize, split hi/lo, write (B,Tc,C) ----
#pragma unroll
    for (int rh = 0; rh < 2; ++rh) {
        const int q = q0 + wid * 16 + (lane >> 2) + rh * 8;
        const float inv = (lrow[rh] > 0.f) ? (1.f / lrow[rh]) : 0.f;
        const size_t base = ((size_t)b * TDIM + q) * CDIM + h * DH;
#pragma unroll
        for (int nt = 0; nt < 8; ++nt) {
            const int d = nt * 8 + jc;
            uint32_t hi, lo;
            split2(oacc[nt][rh * 2 + 0] * inv, oacc[nt][rh * 2 + 1] * inv, hi, lo);
            *(uint32_t*)&Oh[base + d] = hi;
            *(uint32_t*)&Ol[base + d] = lo;
        }
    }
}

// ---------------------------------------------------------------------------
__global__ void zero_kernel(float4* __restrict__ p, int n4)
{
    int i = blockIdx.x * blockDim.x + threadIdx.x;
    if (i < n4) p[i] = make_float4(0.f, 0.f, 0.f, 0.f);
}

__global__ void write_mask_kernel(const unsigned* __restrict__ mask,
                                  float* __restrict__ out, int n)
{
    int i = blockIdx.x * blockDim.x + threadIdx.x;
    if (i < n) out[i] = mask[i] ? 1.0f : 0.0f;
}

// ---------------------------------------------------------------------------
extern "C" void kernel_launch(void* const* d_in, const int* in_sizes, int n_in,
                              void* d_out, int out_size)
{
    const float*    x    = (const float*)d_in[0];
    const unsigned* mask = (const unsigned*)d_in[1];
    const float*    Wq   = (const float*)d_in[2];
    const float*    bq   = (const float*)d_in[3];
    const float*    Wk   = (const float*)d_in[4];
    const float*    bk   = (const float*)d_in[5];
    const float*    Wv   = (const float*)d_in[6];
    const float*    bv   = (const float*)d_in[7];
    const float*    Wp   = (const float*)d_in[8];
    const float*    bp   = (const float*)d_in[9];
    float* out = (float*)d_out;

    __nv_bfloat16 *wh, *wl, *xh, *xl, *ah, *al, *qh, *ql, *kh, *kl, *vh, *vl;
    int *gidx, *gcnt;
    cudaGetSymbolAddress((void**)&wh,   g_Wh);
    cudaGetSymbolAddress((void**)&wl,   g_Wl);
    cudaGetSymbolAddress((void**)&xh,   g_xTh);
    cudaGetSymbolAddress((void**)&xl,   g_xTl);
    cudaGetSymbolAddress((void**)&ah,   g_aTh);
    cudaGetSymbolAddress((void**)&al,   g_aTl);
    cudaGetSymbolAddress((void**)&qh,   g_qh);
    cudaGetSymbolAddress((void**)&ql,   g_ql);
    cudaGetSymbolAddress((void**)&kh,   g_kh);
    cudaGetSymbolAddress((void**)&kl,   g_kl);
    cudaGetSymbolAddress((void**)&vh,   g_vh);
    cudaGetSymbolAddress((void**)&vl,   g_vl);
    cudaGetSymbolAddress((void**)&gidx, g_idx);
    cudaGetSymbolAddress((void**)&gcnt, g_cnt);

    compact_kernel<<<BSZ, 256>>>(mask, gidx, gcnt);

    const int n4 = BSZ * CDIM * TDIM / 4;
    zero_kernel<<<(n4 + 255) / 256, 256>>>((float4*)out, n4);

    const int WN = CDIM * CDIM;
    const int wblk = (WN + 255) / 256;
    split_w_kernel<<<wblk, 256>>>(Wq, wh + 0 * (size_t)WN, wl + 0 * (size_t)WN, WN);
    split_w_kernel<<<wblk, 256>>>(Wk, wh + 1 * (size_t)WN, wl + 1 * (size_t)WN, WN);
    split_w_kernel<<<wblk, 256>>>(Wv, wh + 2 * (size_t)WN, wl + 2 * (size_t)WN, WN);
    split_w_kernel<<<wblk, 256>>>(Wp, wh + 3 * (size_t)WN, wl + 3 * (size_t)WN, WN);

    dim3 gt(TDIM / 32, CDIM / 32, BSZ);
    gather_transpose_split<<<gt, dim3(32, 8)>>>(x, gidx, gcnt, xh, xl);

    dim3 gg(TDIM / 128, CDIM / 128, BSZ);
    mma_gemm<<<gg, 256>>>(wh + 0 * (size_t)WN, wl + 0 * (size_t)WN, xh, xl, bq,
                          nullptr, qh, ql, gcnt, gidx, 3);
    mma_gemm<<<gg, 256>>>(wh + 1 * (size_t)WN, wl + 1 * (size_t)WN, xh, xl, bk,
                          nullptr, kh, kl, gcnt, gidx, 3);
    mma_gemm<<<gg, 256>>>(wh + 2 * (size_t)WN, wl + 2 * (size_t)WN, xh, xl, bv,
                          nullptr, vh, vl, gcnt, gidx, 4);

    dim3 ga(TDIM / 128, HN, BSZ);
    attn_mma<<<ga, 256>>>(qh, ql, kh, kl, vh, vl, gcnt, ah, al);

    mma_gemm<<<gg, 256>>>(wh + 3 * (size_t)WN, wl + 3 * (size_t)WN, ah, al, bp,
                          out, nullptr, nullptr, gcnt, gidx, 2);

    const long long nout = (long long)BSZ * CDIM * TDIM;
    const int tail = out_size - (int)nout;
    if (tail >= BSZ * TDIM) {
        write_mask_kernel<<<(BSZ * TDIM + 255) / 256, 256>>>(
            mask, out + nout, BSZ * TDIM);
    }
}

// round 6
// speedup vs baseline: 4.1104x; 1.0210x over previous
#include <cuda_runtime.h>
#include <cuda_bf16.h>
#include <stdint.h>

#define BSZ  2
#define CDIM 1024
#define TDIM 2048
#define HN   16
#define DH   64

// ---------------- scratch (static device globals) ----------------
__device__ __nv_bfloat16 g_Wh [(size_t)4 * CDIM * CDIM];   // [Wq;Wk;Wv;Wp]
__device__ __nv_bfloat16 g_Wl [(size_t)4 * CDIM * CDIM];
__device__ __nv_bfloat16 g_xTh[(size_t)BSZ * TDIM * CDIM];   // (B, Tc, C)
__device__ __nv_bfloat16 g_xTl[(size_t)BSZ * TDIM * CDIM];
__device__ __nv_bfloat16 g_qh [(size_t)BSZ * HN * TDIM * DH]; // (B,H,Tc,D)
__device__ __nv_bfloat16 g_ql [(size_t)BSZ * HN * TDIM * DH];
__device__ __nv_bfloat16 g_kh [(size_t)BSZ * HN * TDIM * DH];
__device__ __nv_bfloat16 g_kl [(size_t)BSZ * HN * TDIM * DH];
__device__ __nv_bfloat16 g_vh [(size_t)BSZ * CDIM * TDIM];    // (B, C, Tc)
__device__ __nv_bfloat16 g_vl [(size_t)BSZ * CDIM * TDIM];
__device__ __nv_bfloat16 g_aTh[(size_t)BSZ * TDIM * CDIM];    // attn out (B, Tc, C)
__device__ __nv_bfloat16 g_aTl[(size_t)BSZ * TDIM * CDIM];
__device__ int g_idx[BSZ * TDIM];
__device__ int g_cnt[BSZ];

// ---------------- helpers ----------------
__device__ __forceinline__ uint32_t smem_u32(const void* p) {
    uint32_t a;
    asm("{ .reg .u64 t; cvta.to.shared.u64 t, %1; cvt.u32.u64 %0, t; }" : "=r"(a) : "l"(p));
    return a;
}
__device__ __forceinline__ uint32_t sw128(uint32_t off) { return off ^ ((off >> 3) & 0x70); }

__device__ __forceinline__ void ldsm4(uint32_t* r, uint32_t addr) {
    asm volatile("ldmatrix.sync.aligned.m8n8.x4.shared.b16 {%0,%1,%2,%3}, [%4];"
        : "=r"(r[0]), "=r"(r[1]), "=r"(r[2]), "=r"(r[3]) : "r"(addr));
}
__device__ __forceinline__ void mma16816(float* c, const uint32_t* a, const uint32_t* b) {
    asm volatile("mma.sync.aligned.m16n8k16.row.col.f32.bf16.bf16.f32 "
        "{%0,%1,%2,%3}, {%4,%5,%6,%7}, {%8,%9}, {%0,%1,%2,%3};"
        : "+f"(c[0]), "+f"(c[1]), "+f"(c[2]), "+f"(c[3])
        : "r"(a[0]), "r"(a[1]), "r"(a[2]), "r"(a[3]), "r"(b[0]), "r"(b[1]));
}
__device__ __forceinline__ void split1(float v, __nv_bfloat16& h, __nv_bfloat16& l) {
    h = __float2bfloat16(v);
    l = __float2bfloat16(v - __bfloat162float(h));
}
__device__ __forceinline__ void split2(float v0, float v1, uint32_t& hi, uint32_t& lo) {
    __nv_bfloat16 h0, l0, h1, l1;
    split1(v0, h0, l0); split1(v1, h1, l1);
    hi = (uint32_t)__bfloat16_as_ushort(h0) | ((uint32_t)__bfloat16_as_ushort(h1) << 16);
    lo = (uint32_t)__bfloat16_as_ushort(l0) | ((uint32_t)__bfloat16_as_ushort(l1) << 16);
}
__device__ __forceinline__ void cpasync16(uint32_t dst, const void* src) {
    asm volatile("cp.async.cg.shared.global [%0], [%1], 16;" :: "r"(dst), "l"(src));
}
#define CP_COMMIT() asm volatile("cp.async.commit_group;" ::: "memory")
#define CP_WAIT0()  asm volatile("cp.async.wait_group 0;" ::: "memory")
#define CP_WAIT1()  asm volatile("cp.async.wait_group 1;" ::: "memory")

// ---------------------------------------------------------------------------
// Deterministic mask compaction.
// ---------------------------------------------------------------------------
__global__ __launch_bounds__(256)
void compact_kernel(const unsigned* __restrict__ mask, int* __restrict__ idx,
                    int* __restrict__ cnt)
{
    __shared__ int wsum[8];
    __shared__ int wexcl[8];
    const int b = blockIdx.x;
    const unsigned* mb = mask + (size_t)b * TDIM;
    int* ib = idx + (size_t)b * TDIM;
    const int tid  = threadIdx.x;
    const int lane = tid & 31, w = tid >> 5;
    unsigned v[8]; int c = 0;
#pragma unroll
    for (int i = 0; i < 8; ++i) { v[i] = mb[tid * 8 + i]; c += v[i] ? 1 : 0; }
    int inc = c;
#pragma unroll
    for (int off = 1; off < 32; off <<= 1) {
        int n = __shfl_up_sync(0xffffffffu, inc, off);
        if (lane >= off) inc += n;
    }
    if (lane == 31) wsum[w] = inc;
    __syncthreads();
    if (tid == 0) {
        int s = 0;
#pragma unroll
        for (int i = 0; i < 8; ++i) { wexcl[i] = s; s += wsum[i]; }
        cnt[b] = s;
    }
    __syncthreads();
    int p = wexcl[w] + inc - c;
#pragma unroll
    for (int i = 0; i < 8; ++i) if (v[i]) ib[p++] = tid * 8 + i;
}

// ---------------------------------------------------------------------------
// Gather + transpose + hi/lo split: x (B,C,T) -> (B, Tc, C) bf16 hi/lo.
// ---------------------------------------------------------------------------
__global__ __launch_bounds__(256)
void gather_transpose_split(const float* __restrict__ src,
                            const int* __restrict__ idx, const int* __restrict__ cnt,
                            __nv_bfloat16* __restrict__ dh, __nv_bfloat16* __restrict__ dl)
{
    __shared__ float tile[32][33];
    __shared__ int tloc[32];
    const int b = blockIdx.z;
    const int n = cnt[b];
    const int i0 = blockIdx.x * 32;
    if (i0 >= n) return;
    const int c0 = blockIdx.y * 32;
    const float* s = src + (size_t)b * CDIM * TDIM;
    __nv_bfloat16* ph = dh + (size_t)b * TDIM * CDIM;
    __nv_bfloat16* pl = dl + (size_t)b * TDIM * CDIM;
    const int tx = threadIdx.x, ty = threadIdx.y;
    if (ty == 0) tloc[tx] = (i0 + tx < n) ? idx[b * TDIM + i0 + tx] : -1;
    __syncthreads();
    const int t = tloc[tx];
#pragma unroll
    for (int i = 0; i < 4; ++i)
        tile[ty + i * 8][tx] = (t >= 0) ? s[(size_t)(c0 + ty + i * 8) * TDIM + t] : 0.f;
    __syncthreads();
#pragma unroll
    for (int i = 0; i < 4; ++i) {
        const int irow = i0 + ty + i * 8;
        if (irow < n) {
            float v = tile[tx][ty + i * 8];
            __nv_bfloat16 h, l; split1(v, h, l);
            size_t o = (size_t)irow * CDIM + c0 + tx;
            ph[o] = h; pl[o] = l;
        }
    }
}

// ---------------------------------------------------------------------------
// Double-buffered cp.async bf16 split GEMM (hh + hl + lh).
// fusedQKV=1: A rows 0..3071 = [Wq;Wk;Wv]; outputs Q/K hi-lo (B,H,Tc,D), V (B,C,Tc).
// fusedQKV=0: P-proj, scatter fp32 through idx into (C,T) (out pre-zeroed).
// Dynamic smem: 2 stages x (A 16KB + B 16KB) = 64KB.
// ---------------------------------------------------------------------------
extern __shared__ unsigned char dynsm[];

__global__ __launch_bounds__(256)
void mma_gemm(const __nv_bfloat16* __restrict__ Ah, const __nv_bfloat16* __restrict__ Al,
              const __nv_bfloat16* __restrict__ Bh, const __nv_bfloat16* __restrict__ Bl,
              const float* __restrict__ b0, const float* __restrict__ b1,
              const float* __restrict__ b2, float* __restrict__ Cout,
              __nv_bfloat16* __restrict__ Qh, __nv_bfloat16* __restrict__ Ql,
              __nv_bfloat16* __restrict__ Kh, __nv_bfloat16* __restrict__ Kl,
              __nv_bfloat16* __restrict__ Vh, __nv_bfloat16* __restrict__ Vl,
              const int* __restrict__ cnt, const int* __restrict__ idx, int fusedQKV)
{
    __shared__ int sidx[128];

    const int b    = blockIdx.z;
    const int nlim = cnt[b];
    const int n0   = blockIdx.x * 128;
    if (n0 >= nlim) return;
    const int m0   = blockIdx.y * 128;
    const int tid  = threadIdx.x;
    const int wid  = tid >> 5;
    const int lane = tid & 31;
    const int wy   = wid & 1;
    const int wx   = wid >> 1;

    const uint32_t smu = smem_u32(dynsm);

    const __nv_bfloat16* Bhb = Bh + (size_t)b * TDIM * CDIM;
    const __nv_bfloat16* Blb = Bl + (size_t)b * TDIM * CDIM;

    const int r     = tid >> 1;
    const int which = tid & 1;
    const __nv_bfloat16* aP = (which ? Al : Ah) + (size_t)(m0 + r) * CDIM;
    const __nv_bfloat16* bP = (which ? Blb : Bhb) + (size_t)(n0 + r) * CDIM;
    const uint32_t rowb = (uint32_t)r * 128 + (uint32_t)which * 64;

    float acc[4][4][4];
#pragma unroll
    for (int i = 0; i < 4; ++i)
#pragma unroll
        for (int j = 0; j < 4; ++j)
#pragma unroll
            for (int c = 0; c < 4; ++c) acc[i][j][c] = 0.f;

    const uint32_t aRow = (uint32_t)(wy * 64 + (lane & 15));
    const uint32_t aCol = (uint32_t)((lane >> 4) << 4);
    const uint32_t bRow = (uint32_t)(wx * 32 + (lane & 7) + ((lane >> 4) << 3));
    const uint32_t bCol = (uint32_t)(((lane >> 3) & 1) << 4);

    // prologue: stage 0
    {
#pragma unroll
        for (int i = 0; i < 4; ++i) {
            cpasync16(smu + sw128(rowb + i * 16), aP + i * 8);
            cpasync16(smu + 16384 + sw128(rowb + i * 16), bP + i * 8);
        }
        CP_COMMIT();
    }

    for (int kb = 0; kb < 32; ++kb) {
        const uint32_t stg = (uint32_t)(kb & 1) * 32768u;
        if (kb < 31) {
            const uint32_t nst = (uint32_t)((kb + 1) & 1) * 32768u;
            const int k1 = (kb + 1) * 32;
#pragma unroll
            for (int i = 0; i < 4; ++i) {
                cpasync16(smu + nst + sw128(rowb + i * 16), aP + k1 + i * 8);
                cpasync16(smu + nst + 16384 + sw128(rowb + i * 16), bP + k1 + i * 8);
            }
            CP_COMMIT();
            CP_WAIT1();
        } else {
            CP_WAIT0();
        }
        __syncthreads();

        const uint32_t smA_u = smu + stg;
        const uint32_t smB_u = smu + stg + 16384;
#pragma unroll
        for (int s = 0; s < 2; ++s) {
            const uint32_t ksA = s * 32;
            uint32_t afr[4][4], bh[4][2], bl[4][2];
#pragma unroll
            for (int mt = 0; mt < 4; ++mt)
                ldsm4(afr[mt], smA_u + sw128((aRow + mt * 16) * 128 + ksA + aCol));
#pragma unroll
            for (int np = 0; np < 2; ++np) {
                uint32_t rr[4];
                ldsm4(rr, smB_u + sw128((bRow + np * 16) * 128 + ksA + bCol));
                bh[np * 2 + 0][0] = rr[0]; bh[np * 2 + 0][1] = rr[1];
                bh[np * 2 + 1][0] = rr[2]; bh[np * 2 + 1][1] = rr[3];
            }
#pragma unroll
            for (int mt = 0; mt < 4; ++mt)
#pragma unroll
                for (int nt = 0; nt < 4; ++nt)
                    mma16816(acc[mt][nt], afr[mt], bh[nt]);
#pragma unroll
            for (int np = 0; np < 2; ++np) {
                uint32_t rr[4];
                ldsm4(rr, smB_u + sw128((bRow + np * 16) * 128 + 64 + ksA + bCol));
                bl[np * 2 + 0][0] = rr[0]; bl[np * 2 + 0][1] = rr[1];
                bl[np * 2 + 1][0] = rr[2]; bl[np * 2 + 1][1] = rr[3];
            }
#pragma unroll
            for (int mt = 0; mt < 4; ++mt)
#pragma unroll
                for (int nt = 0; nt < 4; ++nt)
                    mma16816(acc[mt][nt], afr[mt], bl[nt]);
#pragma unroll
            for (int mt = 0; mt < 4; ++mt)
                ldsm4(afr[mt], smA_u + sw128((aRow + mt * 16) * 128 + 64 + ksA + aCol));
#pragma unroll
            for (int mt = 0; mt < 4; ++mt)
#pragma unroll
                for (int nt = 0; nt < 4; ++nt)
                    mma16816(acc[mt][nt], afr[mt], bh[nt]);
        }
        __syncthreads();
    }

    // ---- epilogue ----
    const int sector = m0 >> 10;          // 0=Q 1=K 2=V (fused) ; 0 for P-proj
    const int mbase  = m0 & 1023;
    const float* bptr = fusedQKV ? (sector == 0 ? b0 : (sector == 1 ? b1 : b2)) : b0;

    if (!fusedQKV) {
        if (tid < 128) sidx[tid] = (n0 + tid < nlim) ? idx[b * TDIM + n0 + tid] : -1;
        __syncthreads();
    }

    const int qrow = lane >> 2;
    const int qcol = (lane & 3) * 2;
#pragma unroll
    for (int mt = 0; mt < 4; ++mt) {
#pragma unroll
        for (int rh = 0; rh < 2; ++rh) {
            const int rloc = mbase + wy * 64 + mt * 16 + qrow + rh * 8;
            const float bi = bptr[rloc];
#pragma unroll
            for (int nt = 0; nt < 4; ++nt) {
                const int col = n0 + wx * 32 + nt * 8 + qcol;
                float v0 = acc[mt][nt][rh * 2 + 0] + bi;
                float v1 = acc[mt][nt][rh * 2 + 1] + bi;
                if (!fusedQKV) {
                    float* dst = Cout + (size_t)b * CDIM * TDIM + (size_t)rloc * TDIM;
                    const int t0 = sidx[col - n0 + 0];
                    const int t1 = sidx[col - n0 + 1];
                    if (t0 >= 0) dst[t0] = v0;
                    if (t1 >= 0) dst[t1] = v1;
                } else if (sector < 2) {
                    __nv_bfloat16* oh = sector ? Kh : Qh;
                    __nv_bfloat16* ol = sector ? Kl : Ql;
                    const int hh = rloc >> 6, dd = rloc & 63;
                    const size_t a0 = ((size_t)(b * HN + hh) * TDIM + col) * DH + dd;
                    __nv_bfloat16 h0, l0, h1, l1;
                    split1(v0, h0, l0); split1(v1, h1, l1);
                    oh[a0] = h0;       ol[a0] = l0;
                    oh[a0 + DH] = h1;  ol[a0 + DH] = l1;
                } else {
                    const size_t a0 = ((size_t)b * CDIM + rloc) * TDIM + col;
                    uint32_t hi, lo; split2(v0, v1, hi, lo);
                    *(uint32_t*)&Vh[a0] = hi;
                    *(uint32_t*)&Vl[a0] = lo;
                }
            }
        }
    }
}

// ---------------------------------------------------------------------------
// Fused weight split for all 4 weights (WN = 2^20 elements each).
// ---------------------------------------------------------------------------
__global__ __launch_bounds__(256)
void split_w4_kernel(const float* __restrict__ w0, const float* __restrict__ w1,
                     const float* __restrict__ w2, const float* __restrict__ w3,
                     __nv_bfloat16* __restrict__ hi, __nv_bfloat16* __restrict__ lo)
{
    const unsigned i = blockIdx.x * 256u + threadIdx.x;   // < 4M
    const int sel = i >> 20;
    const float* w = (sel == 0) ? w0 : (sel == 1) ? w1 : (sel == 2) ? w2 : w3;
    float v = w[i & 0xFFFFFu];
    __nv_bfloat16 h, l; split1(v, h, l);
    hi[i] = h; lo[i] = l;
}

// ---------------------------------------------------------------------------
// Tensor-core flash attention (unchanged from R5).
// ---------------------------------------------------------------------------
__global__ __launch_bounds__(256)
void attn_mma(const __nv_bfloat16* __restrict__ Qh, const __nv_bfloat16* __restrict__ Ql,
              const __nv_bfloat16* __restrict__ Kh, const __nv_bfloat16* __restrict__ Kl,
              const __nv_bfloat16* __restrict__ Vh, const __nv_bfloat16* __restrict__ Vl,
              const int* __restrict__ cnt,
              __nv_bfloat16* __restrict__ Oh, __nv_bfloat16* __restrict__ Ol)
{
    __shared__ __align__(1024) unsigned char sm[32768];
    const int b = blockIdx.z, h = blockIdx.y;
    const int kend = cnt[b];
    const int q0 = blockIdx.x * 128;
    if (q0 >= kend) return;
    const int tid = threadIdx.x, wid = tid >> 5, lane = tid & 31;
    const uint32_t smu = smem_u32(sm);

    const __nv_bfloat16* Qhb = Qh + ((size_t)(b * HN + h) * TDIM + q0) * DH;
    const __nv_bfloat16* Qlb = Ql + ((size_t)(b * HN + h) * TDIM + q0) * DH;
#pragma unroll
    for (int it = 0; it < 4; ++it) {
        const int lin = it * 256 + tid;
        const int row = lin >> 3, qd = lin & 7;
        uint4 a = *(const uint4*)(Qhb + (size_t)row * DH + qd * 8);
        uint4 c = *(const uint4*)(Qlb + (size_t)row * DH + qd * 8);
        const uint32_t so = sw128((uint32_t)row * 128 + qd * 16);
        *(uint4*)(sm + so) = a;
        *(uint4*)(sm + 16384 + so) = c;
    }
    __syncthreads();
    uint32_t qfh[4][4], qfl[4][4];
    {
        const uint32_t aRow = wid * 16 + (lane & 15);
        const uint32_t aColB = (lane >> 4) << 4;
#pragma unroll
        for (int kk = 0; kk < 4; ++kk) {
            ldsm4(qfh[kk], smu + sw128(aRow * 128 + kk * 32 + aColB));
            ldsm4(qfl[kk], smu + 16384 + sw128(aRow * 128 + kk * 32 + aColB));
        }
    }
    __syncthreads();

    float oacc[8][4];
#pragma unroll
    for (int i = 0; i < 8; ++i)
#pragma unroll
        for (int c = 0; c < 4; ++c) oacc[i][c] = 0.f;
    float mrow[2] = {-1e30f, -1e30f}, lrow[2] = {0.f, 0.f};
    const float scale = 0.125f;
    const uint32_t bRow  = (lane & 7) + ((lane >> 4) << 3);
    const uint32_t bColB = ((lane >> 3) & 1) << 4;
    const int jc = (lane & 3) * 2;

    const __nv_bfloat16* Khb = Kh + ((size_t)(b * HN + h) * TDIM) * DH;
    const __nv_bfloat16* Klb = Kl + ((size_t)(b * HN + h) * TDIM) * DH;
    const __nv_bfloat16* Vhb = Vh + ((size_t)b * CDIM + h * DH) * TDIM;
    const __nv_bfloat16* Vlb = Vl + ((size_t)b * CDIM + h * DH) * TDIM;

    for (int k0 = 0; k0 < kend; k0 += 64) {
#pragma unroll
        for (int it = 0; it < 2; ++it) {
            const int lin = it * 256 + tid;
            const int row = lin >> 3, qd = lin & 7;
            uint4 a = *(const uint4*)(Khb + (size_t)(k0 + row) * DH + qd * 8);
            uint4 c = *(const uint4*)(Klb + (size_t)(k0 + row) * DH + qd * 8);
            uint4 e = *(const uint4*)(Vhb + (size_t)row * TDIM + k0 + qd * 8);
            uint4 f = *(const uint4*)(Vlb + (size_t)row * TDIM + k0 + qd * 8);
            const uint32_t so = sw128((uint32_t)row * 128 + qd * 16);
            *(uint4*)(sm + so) = a;
            *(uint4*)(sm +  8192 + so) = c;
            *(uint4*)(sm + 16384 + so) = e;
            *(uint4*)(sm + 24576 + so) = f;
        }
        __syncthreads();

        float s[8][4];
#pragma unroll
        for (int i = 0; i < 8; ++i)
#pragma unroll
            for (int c = 0; c < 4; ++c) s[i][c] = 0.f;
#pragma unroll
        for (int kk = 0; kk < 4; ++kk) {
            uint32_t bh[8][2], bl2[8][2];
#pragma unroll
            for (int np = 0; np < 4; ++np) {
                uint32_t rr[4];
                ldsm4(rr, smu + sw128((np * 16 + bRow) * 128 + kk * 32 + bColB));
                bh[np * 2 + 0][0] = rr[0]; bh[np * 2 + 0][1] = rr[1];
                bh[np * 2 + 1][0] = rr[2]; bh[np * 2 + 1][1] = rr[3];
            }
#pragma unroll
            for (int nt = 0; nt < 8; ++nt) mma16816(s[nt], qfh[kk], bh[nt]);
#pragma unroll
            for (int np = 0; np < 4; ++np) {
                uint32_t rr[4];
                ldsm4(rr, smu + 8192 + sw128((np * 16 + bRow) * 128 + kk * 32 + bColB));
                bl2[np * 2 + 0][0] = rr[0]; bl2[np * 2 + 0][1] = rr[1];
                bl2[np * 2 + 1][0] = rr[2]; bl2[np * 2 + 1][1] = rr[3];
            }
#pragma unroll
            for (int nt = 0; nt < 8; ++nt) mma16816(s[nt], qfh[kk], bl2[nt]);
#pragma unroll
            for (int nt = 0; nt < 8; ++nt) mma16816(s[nt], qfl[kk], bh[nt]);
        }

#pragma unroll
        for (int rh = 0; rh < 2; ++rh) {
            float mx = -1e30f;
#pragma unroll
            for (int nt = 0; nt < 8; ++nt) {
                const int jg = k0 + nt * 8 + jc;
                float v0 = (jg     < kend) ? s[nt][rh * 2 + 0] * scale : -1e30f;
                float v1 = (jg + 1 < kend) ? s[nt][rh * 2 + 1] * scale : -1e30f;
                s[nt][rh * 2 + 0] = v0; s[nt][rh * 2 + 1] = v1;
                mx = fmaxf(mx, fmaxf(v0, v1));
            }
            mx = fmaxf(mx, __shfl_xor_sync(0xffffffffu, mx, 1));
            mx = fmaxf(mx, __shfl_xor_sync(0xffffffffu, mx, 2));
            const float mnew = fmaxf(mrow[rh], mx);
            const float fac = __expf(mrow[rh] - mnew);
            mrow[rh] = mnew;
            float sum = 0.f;
#pragma unroll
            for (int nt = 0; nt < 8; ++nt) {
                float p0 = __expf(s[nt][rh * 2 + 0] - mnew);
                float p1 = __expf(s[nt][rh * 2 + 1] - mnew);
                s[nt][rh * 2 + 0] = p0; s[nt][rh * 2 + 1] = p1;
                sum += p0 + p1;
            }
            sum += __shfl_xor_sync(0xffffffffu, sum, 1);
            sum += __shfl_xor_sync(0xffffffffu, sum, 2);
            lrow[rh] = lrow[rh] * fac + sum;
#pragma unroll
            for (int nt = 0; nt < 8; ++nt) {
                oacc[nt][rh * 2 + 0] *= fac;
                oacc[nt][rh * 2 + 1] *= fac;
            }
        }

        uint32_t ph[4][4], pl2[4][4];
#pragma unroll
        for (int kk2 = 0; kk2 < 4; ++kk2) {
            const int t0 = 2 * kk2, t1 = 2 * kk2 + 1;
            split2(s[t0][0], s[t0][1], ph[kk2][0], pl2[kk2][0]);
            split2(s[t0][2], s[t0][3], ph[kk2][1], pl2[kk2][1]);
            split2(s[t1][0], s[t1][1], ph[kk2][2], pl2[kk2][2]);
            split2(s[t1][2], s[t1][3], ph[kk2][3], pl2[kk2][3]);
        }

#pragma unroll
        for (int kk2 = 0; kk2 < 4; ++kk2) {
            uint32_t vbh[8][2], vbl[8][2];
#pragma unroll
            for (int np = 0; np < 4; ++np) {
                uint32_t rr[4];
                ldsm4(rr, smu + 16384 + sw128((np * 16 + bRow) * 128 + kk2 * 32 + bColB));
                vbh[np * 2 + 0][0] = rr[0]; vbh[np * 2 + 0][1] = rr[1];
                vbh[np * 2 + 1][0] = rr[2]; vbh[np * 2 + 1][1] = rr[3];
            }
#pragma unroll
            for (int nt = 0; nt < 8; ++nt) mma16816(oacc[nt], ph[kk2], vbh[nt]);
#pragma unroll
            for (int np = 0; np < 4; ++np) {
                uint32_t rr[4];
                ldsm4(rr, smu + 24576 + sw128((np * 16 + bRow) * 128 + kk2 * 32 + bColB));
                vbl[np * 2 + 0][0] = rr[0]; vbl[np * 2 + 0][1] = rr[1];
                vbl[np * 2 + 1][0] = rr[2]; vbl[np * 2 + 1][1] = rr[3];
            }
#pragma unroll
            for (int nt = 0; nt < 8; ++nt) mma16816(oacc[nt], ph[kk2], vbl[nt]);
#pragma unroll
            for (int nt = 0; nt < 8; ++nt) mma16816(oacc[nt], pl2[kk2], vbh[nt]);
        }
        __syncthreads();
    }

#pragma unroll
    for (int rh = 0; rh < 2; ++rh) {
        const int q = q0 + wid * 16 + (lane >> 2) + rh * 8;
        const float inv = (lrow[rh] > 0.f) ? (1.f / lrow[rh]) : 0.f;
        const size_t base = ((size_t)b * TDIM + q) * CDIM + h * DH;
#pragma unroll
        for (int nt = 0; nt < 8; ++nt) {
            const int d = nt * 8 + jc;
            uint32_t hi, lo;
            split2(oacc[nt][rh * 2 + 0] * inv, oacc[nt][rh * 2 + 1] * inv, hi, lo);
            *(uint32_t*)&Oh[base + d] = hi;
            *(uint32_t*)&Ol[base + d] = lo;
        }
    }
}

// ---------------------------------------------------------------------------
__global__ void zero_kernel(float4* __restrict__ p, int n4)
{
    int i = blockIdx.x * blockDim.x + threadIdx.x;
    if (i < n4) p[i] = make_float4(0.f, 0.f, 0.f, 0.f);
}

__global__ void write_mask_kernel(const unsigned* __restrict__ mask,
                                  float* __restrict__ out, int n)
{
    int i = blockIdx.x * blockDim.x + threadIdx.x;
    if (i < n) out[i] = mask[i] ? 1.0f : 0.0f;
}

// ---------------------------------------------------------------------------
extern "C" void kernel_launch(void* const* d_in, const int* in_sizes, int n_in,
                              void* d_out, int out_size)
{
    const float*    x    = (const float*)d_in[0];
    const unsigned* mask = (const unsigned*)d_in[1];
    const float*    Wq   = (const float*)d_in[2];
    const float*    bq   = (const float*)d_in[3];
    const float*    Wk   = (const float*)d_in[4];
    const float*    bk   = (const float*)d_in[5];
    const float*    Wv   = (const float*)d_in[6];
    const float*    bv   = (const float*)d_in[7];
    const float*    Wp   = (const float*)d_in[8];
    const float*    bp   = (const float*)d_in[9];
    float* out = (float*)d_out;

    __nv_bfloat16 *wh, *wl, *xh, *xl, *ah, *al, *qh, *ql, *kh, *kl, *vh, *vl;
    int *gidx, *gcnt;
    cudaGetSymbolAddress((void**)&wh,   g_Wh);
    cudaGetSymbolAddress((void**)&wl,   g_Wl);
    cudaGetSymbolAddress((void**)&xh,   g_xTh);
    cudaGetSymbolAddress((void**)&xl,   g_xTl);
    cudaGetSymbolAddress((void**)&ah,   g_aTh);
    cudaGetSymbolAddress((void**)&al,   g_aTl);
    cudaGetSymbolAddress((void**)&qh,   g_qh);
    cudaGetSymbolAddress((void**)&ql,   g_ql);
    cudaGetSymbolAddress((void**)&kh,   g_kh);
    cudaGetSymbolAddress((void**)&kl,   g_kl);
    cudaGetSymbolAddress((void**)&vh,   g_vh);
    cudaGetSymbolAddress((void**)&vl,   g_vl);
    cudaGetSymbolAddress((void**)&gidx, g_idx);
    cudaGetSymbolAddress((void**)&gcnt, g_cnt);

    static int smem_set = 0;
    if (!smem_set) {
        cudaFuncSetAttribute(mma_gemm, cudaFuncAttributeMaxDynamicSharedMemorySize, 65536);
        smem_set = 1;
    }

    compact_kernel<<<BSZ, 256>>>(mask, gidx, gcnt);

    const int n4 = BSZ * CDIM * TDIM / 4;
    zero_kernel<<<(n4 + 255) / 256, 256>>>((float4*)out, n4);

    split_w4_kernel<<<4 * CDIM * CDIM / 256, 256>>>(Wq, Wk, Wv, Wp, wh, wl);

    dim3 gt(TDIM / 32, CDIM / 32, BSZ);
    gather_transpose_split<<<gt, dim3(32, 8)>>>(x, gidx, gcnt, xh, xl);

    const size_t WN = (size_t)CDIM * CDIM;
    // fused QKV: A rows 0..3071
    dim3 gqkv(TDIM / 128, 24, BSZ);
    mma_gemm<<<gqkv, 256, 65536>>>(wh, wl, xh, xl, bq, bk, bv,
                                   nullptr, qh, ql, kh, kl, vh, vl, gcnt, gidx, 1);

    dim3 ga(TDIM / 128, HN, BSZ);
    attn_mma<<<ga, 256>>>(qh, ql, kh, kl, vh, vl, gcnt, ah, al);

    dim3 gp(TDIM / 128, CDIM / 128, BSZ);
    mma_gemm<<<gp, 256, 65536>>>(wh + 3 * WN, wl + 3 * WN, ah, al, bp, nullptr, nullptr,
                                 out, nullptr, nullptr, nullptr, nullptr, nullptr, nullptr,
                                 gcnt, gidx, 0);

    const long long nout = (long long)BSZ * CDIM * TDIM;
    const int tail = out_size - (int)nout;
    if (tail >= BSZ * TDIM) {
        write_mask_kernel<<<(BSZ * TDIM + 255) / 256, 256>>>(
            mask, out + nout, BSZ * TDIM);
    }
}

// round 7
// speedup vs baseline: 4.1278x; 1.0042x over previous
#include <cuda_runtime.h>
#include <cuda_bf16.h>
#include <stdint.h>

#define BSZ  2
#define CDIM 1024
#define TDIM 2048
#define HN   16
#define DH   64

// ---------------- scratch (static device globals) ----------------
__device__ __nv_bfloat16 g_Wh [(size_t)4 * CDIM * CDIM];   // [Wq;Wk;Wv;Wp]
__device__ __nv_bfloat16 g_Wl [(size_t)4 * CDIM * CDIM];
__device__ __nv_bfloat16 g_xTh[(size_t)BSZ * TDIM * CDIM];   // (B, Tc, C)
__device__ __nv_bfloat16 g_xTl[(size_t)BSZ * TDIM * CDIM];
__device__ __nv_bfloat16 g_qh [(size_t)BSZ * HN * TDIM * DH]; // (B,H,Tc,D)
__device__ __nv_bfloat16 g_ql [(size_t)BSZ * HN * TDIM * DH];
__device__ __nv_bfloat16 g_kh [(size_t)BSZ * HN * TDIM * DH];
__device__ __nv_bfloat16 g_kl [(size_t)BSZ * HN * TDIM * DH];
__device__ __nv_bfloat16 g_vh [(size_t)BSZ * CDIM * TDIM];    // (B, C, Tc)
__device__ __nv_bfloat16 g_vl [(size_t)BSZ * CDIM * TDIM];
__device__ __nv_bfloat16 g_aTh[(size_t)BSZ * TDIM * CDIM];    // attn out (B, Tc, C)
__device__ __nv_bfloat16 g_aTl[(size_t)BSZ * TDIM * CDIM];
__device__ int g_idx[BSZ * TDIM];
__device__ int g_cnt[BSZ];

// ---------------- helpers ----------------
__device__ __forceinline__ uint32_t smem_u32(const void* p) {
    uint32_t a;
    asm("{ .reg .u64 t; cvta.to.shared.u64 t, %1; cvt.u32.u64 %0, t; }" : "=r"(a) : "l"(p));
    return a;
}
__device__ __forceinline__ uint32_t sw128(uint32_t off) { return off ^ ((off >> 3) & 0x70); }

__device__ __forceinline__ void ldsm4(uint32_t* r, uint32_t addr) {
    asm volatile("ldmatrix.sync.aligned.m8n8.x4.shared.b16 {%0,%1,%2,%3}, [%4];"
        : "=r"(r[0]), "=r"(r[1]), "=r"(r[2]), "=r"(r[3]) : "r"(addr));
}
__device__ __forceinline__ void mma16816(float* c, const uint32_t* a, const uint32_t* b) {
    asm volatile("mma.sync.aligned.m16n8k16.row.col.f32.bf16.bf16.f32 "
        "{%0,%1,%2,%3}, {%4,%5,%6,%7}, {%8,%9}, {%0,%1,%2,%3};"
        : "+f"(c[0]), "+f"(c[1]), "+f"(c[2]), "+f"(c[3])
        : "r"(a[0]), "r"(a[1]), "r"(a[2]), "r"(a[3]), "r"(b[0]), "r"(b[1]));
}
__device__ __forceinline__ void split1(float v, __nv_bfloat16& h, __nv_bfloat16& l) {
    h = __float2bfloat16(v);
    l = __float2bfloat16(v - __bfloat162float(h));
}
__device__ __forceinline__ void split2(float v0, float v1, uint32_t& hi, uint32_t& lo) {
    __nv_bfloat16 h0, l0, h1, l1;
    split1(v0, h0, l0); split1(v1, h1, l1);
    hi = (uint32_t)__bfloat16_as_ushort(h0) | ((uint32_t)__bfloat16_as_ushort(h1) << 16);
    lo = (uint32_t)__bfloat16_as_ushort(l0) | ((uint32_t)__bfloat16_as_ushort(l1) << 16);
}
__device__ __forceinline__ void cpasync16(uint32_t dst, const void* src) {
    asm volatile("cp.async.cg.shared.global [%0], [%1], 16;" :: "r"(dst), "l"(src));
}
#define CP_COMMIT() asm volatile("cp.async.commit_group;" ::: "memory")
#define CP_WAIT0()  asm volatile("cp.async.wait_group 0;" ::: "memory")
#define CP_WAIT1()  asm volatile("cp.async.wait_group 1;" ::: "memory")

// ---------------------------------------------------------------------------
__global__ __launch_bounds__(256)
void compact_kernel(const unsigned* __restrict__ mask, int* __restrict__ idx,
                    int* __restrict__ cnt)
{
    __shared__ int wsum[8];
    __shared__ int wexcl[8];
    const int b = blockIdx.x;
    const unsigned* mb = mask + (size_t)b * TDIM;
    int* ib = idx + (size_t)b * TDIM;
    const int tid  = threadIdx.x;
    const int lane = tid & 31, w = tid >> 5;
    unsigned v[8]; int c = 0;
#pragma unroll
    for (int i = 0; i < 8; ++i) { v[i] = mb[tid * 8 + i]; c += v[i] ? 1 : 0; }
    int inc = c;
#pragma unroll
    for (int off = 1; off < 32; off <<= 1) {
        int n = __shfl_up_sync(0xffffffffu, inc, off);
        if (lane >= off) inc += n;
    }
    if (lane == 31) wsum[w] = inc;
    __syncthreads();
    if (tid == 0) {
        int s = 0;
#pragma unroll
        for (int i = 0; i < 8; ++i) { wexcl[i] = s; s += wsum[i]; }
        cnt[b] = s;
    }
    __syncthreads();
    int p = wexcl[w] + inc - c;
#pragma unroll
    for (int i = 0; i < 8; ++i) if (v[i]) ib[p++] = tid * 8 + i;
}

// ---------------------------------------------------------------------------
__global__ __launch_bounds__(256)
void gather_transpose_split(const float* __restrict__ src,
                            const int* __restrict__ idx, const int* __restrict__ cnt,
                            __nv_bfloat16* __restrict__ dh, __nv_bfloat16* __restrict__ dl)
{
    __shared__ float tile[32][33];
    __shared__ int tloc[32];
    const int b = blockIdx.z;
    const int n = cnt[b];
    const int i0 = blockIdx.x * 32;
    if (i0 >= n) return;
    const int c0 = blockIdx.y * 32;
    const float* s = src + (size_t)b * CDIM * TDIM;
    __nv_bfloat16* ph = dh + (size_t)b * TDIM * CDIM;
    __nv_bfloat16* pl = dl + (size_t)b * TDIM * CDIM;
    const int tx = threadIdx.x, ty = threadIdx.y;
    if (ty == 0) tloc[tx] = (i0 + tx < n) ? idx[b * TDIM + i0 + tx] : -1;
    __syncthreads();
    const int t = tloc[tx];
#pragma unroll
    for (int i = 0; i < 4; ++i)
        tile[ty + i * 8][tx] = (t >= 0) ? s[(size_t)(c0 + ty + i * 8) * TDIM + t] : 0.f;
    __syncthreads();
#pragma unroll
    for (int i = 0; i < 4; ++i) {
        const int irow = i0 + ty + i * 8;
        if (irow < n) {
            float v = tile[tx][ty + i * 8];
            __nv_bfloat16 h, l; split1(v, h, l);
            size_t o = (size_t)irow * CDIM + c0 + tx;
            ph[o] = h; pl[o] = l;
        }
    }
}

// ---------------------------------------------------------------------------
// Double-buffered cp.async bf16 split GEMM, pass order hh -> lh -> hl
// (keeps only {A-hi, A-lo OR B-lo} live; fits 128 regs for occupancy 2).
// ---------------------------------------------------------------------------
extern __shared__ unsigned char dynsm[];

__global__ __launch_bounds__(256, 2)
void mma_gemm(const __nv_bfloat16* __restrict__ Ah, const __nv_bfloat16* __restrict__ Al,
              const __nv_bfloat16* __restrict__ Bh, const __nv_bfloat16* __restrict__ Bl,
              const float* __restrict__ b0, const float* __restrict__ b1,
              const float* __restrict__ b2, float* __restrict__ Cout,
              __nv_bfloat16* __restrict__ Qh, __nv_bfloat16* __restrict__ Ql,
              __nv_bfloat16* __restrict__ Kh, __nv_bfloat16* __restrict__ Kl,
              __nv_bfloat16* __restrict__ Vh, __nv_bfloat16* __restrict__ Vl,
              const int* __restrict__ cnt, const int* __restrict__ idx, int fusedQKV)
{
    __shared__ int sidx[128];

    const int b    = blockIdx.z;
    const int nlim = cnt[b];
    const int n0   = blockIdx.x * 128;
    if (n0 >= nlim) return;
    const int m0   = blockIdx.y * 128;
    const int tid  = threadIdx.x;
    const int wid  = tid >> 5;
    const int lane = tid & 31;
    const int wy   = wid & 1;
    const int wx   = wid >> 1;

    const uint32_t smu = smem_u32(dynsm);

    const __nv_bfloat16* Bhb = Bh + (size_t)b * TDIM * CDIM;
    const __nv_bfloat16* Blb = Bl + (size_t)b * TDIM * CDIM;

    const int r     = tid >> 1;
    const int which = tid & 1;
    const __nv_bfloat16* aP = (which ? Al : Ah) + (size_t)(m0 + r) * CDIM;
    const __nv_bfloat16* bP = (which ? Blb : Bhb) + (size_t)(n0 + r) * CDIM;
    const uint32_t rowb = (uint32_t)r * 128 + (uint32_t)which * 64;

    float acc[4][4][4];
#pragma unroll
    for (int i = 0; i < 4; ++i)
#pragma unroll
        for (int j = 0; j < 4; ++j)
#pragma unroll
            for (int c = 0; c < 4; ++c) acc[i][j][c] = 0.f;

    const uint32_t aRow = (uint32_t)(wy * 64 + (lane & 15));
    const uint32_t aCol = (uint32_t)((lane >> 4) << 4);
    const uint32_t bRow = (uint32_t)(wx * 32 + (lane & 7) + ((lane >> 4) << 3));
    const uint32_t bCol = (uint32_t)(((lane >> 3) & 1) << 4);

    {
#pragma unroll
        for (int i = 0; i < 4; ++i) {
            cpasync16(smu + sw128(rowb + i * 16), aP + i * 8);
            cpasync16(smu + 16384 + sw128(rowb + i * 16), bP + i * 8);
        }
        CP_COMMIT();
    }

    for (int kb = 0; kb < 32; ++kb) {
        const uint32_t stg = (uint32_t)(kb & 1) * 32768u;
        if (kb < 31) {
            const uint32_t nst = (uint32_t)((kb + 1) & 1) * 32768u;
            const int k1 = (kb + 1) * 32;
#pragma unroll
            for (int i = 0; i < 4; ++i) {
                cpasync16(smu + nst + sw128(rowb + i * 16), aP + k1 + i * 8);
                cpasync16(smu + nst + 16384 + sw128(rowb + i * 16), bP + k1 + i * 8);
            }
            CP_COMMIT();
            CP_WAIT1();
        } else {
            CP_WAIT0();
        }
        __syncthreads();

        const uint32_t smA_u = smu + stg;
        const uint32_t smB_u = smu + stg + 16384;
#pragma unroll
        for (int s = 0; s < 2; ++s) {
            const uint32_t ksA = s * 32;
            uint32_t afrH[4][4], afrL[4][4], bfr[4][2];

            // A-hi + B-hi -> hh
#pragma unroll
            for (int mt = 0; mt < 4; ++mt)
                ldsm4(afrH[mt], smA_u + sw128((aRow + mt * 16) * 128 + ksA + aCol));
#pragma unroll
            for (int np = 0; np < 2; ++np) {
                uint32_t rr[4];
                ldsm4(rr, smB_u + sw128((bRow + np * 16) * 128 + ksA + bCol));
                bfr[np * 2 + 0][0] = rr[0]; bfr[np * 2 + 0][1] = rr[1];
                bfr[np * 2 + 1][0] = rr[2]; bfr[np * 2 + 1][1] = rr[3];
            }
#pragma unroll
            for (int mt = 0; mt < 4; ++mt)
#pragma unroll
                for (int nt = 0; nt < 4; ++nt)
                    mma16816(acc[mt][nt], afrH[mt], bfr[nt]);

            // A-lo + B-hi -> lh
#pragma unroll
            for (int mt = 0; mt < 4; ++mt)
                ldsm4(afrL[mt], smA_u + sw128((aRow + mt * 16) * 128 + 64 + ksA + aCol));
#pragma unroll
            for (int mt = 0; mt < 4; ++mt)
#pragma unroll
                for (int nt = 0; nt < 4; ++nt)
                    mma16816(acc[mt][nt], afrL[mt], bfr[nt]);

            // B-lo (overwrite) + A-hi -> hl
#pragma unroll
            for (int np = 0; np < 2; ++np) {
                uint32_t rr[4];
                ldsm4(rr, smB_u + sw128((bRow + np * 16) * 128 + 64 + ksA + bCol));
                bfr[np * 2 + 0][0] = rr[0]; bfr[np * 2 + 0][1] = rr[1];
                bfr[np * 2 + 1][0] = rr[2]; bfr[np * 2 + 1][1] = rr[3];
            }
#pragma unroll
            for (int mt = 0; mt < 4; ++mt)
#pragma unroll
                for (int nt = 0; nt < 4; ++nt)
                    mma16816(acc[mt][nt], afrH[mt], bfr[nt]);
        }
        __syncthreads();
    }

    // ---- epilogue ----
    const int sector = m0 >> 10;
    const int mbase  = m0 & 1023;
    const float* bptr = fusedQKV ? (sector == 0 ? b0 : (sector == 1 ? b1 : b2)) : b0;

    if (!fusedQKV) {
        if (tid < 128) sidx[tid] = (n0 + tid < nlim) ? idx[b * TDIM + n0 + tid] : -1;
        __syncthreads();
    }

    const int qrow = lane >> 2;
    const int qcol = (lane & 3) * 2;
#pragma unroll
    for (int mt = 0; mt < 4; ++mt) {
#pragma unroll
        for (int rh = 0; rh < 2; ++rh) {
            const int rloc = mbase + wy * 64 + mt * 16 + qrow + rh * 8;
            const float bi = bptr[rloc];
#pragma unroll
            for (int nt = 0; nt < 4; ++nt) {
                const int col = n0 + wx * 32 + nt * 8 + qcol;
                float v0 = acc[mt][nt][rh * 2 + 0] + bi;
                float v1 = acc[mt][nt][rh * 2 + 1] + bi;
                if (!fusedQKV) {
                    float* dst = Cout + (size_t)b * CDIM * TDIM + (size_t)rloc * TDIM;
                    const int t0 = sidx[col - n0 + 0];
                    const int t1 = sidx[col - n0 + 1];
                    if (t0 >= 0) dst[t0] = v0;
                    if (t1 >= 0) dst[t1] = v1;
                } else if (sector < 2) {
                    __nv_bfloat16* oh = sector ? Kh : Qh;
                    __nv_bfloat16* ol = sector ? Kl : Ql;
                    const int hh = rloc >> 6, dd = rloc & 63;
                    const size_t a0 = ((size_t)(b * HN + hh) * TDIM + col) * DH + dd;
                    __nv_bfloat16 h0, l0, h1, l1;
                    split1(v0, h0, l0); split1(v1, h1, l1);
                    oh[a0] = h0;       ol[a0] = l0;
                    oh[a0 + DH] = h1;  ol[a0 + DH] = l1;
                } else {
                    const size_t a0 = ((size_t)b * CDIM + rloc) * TDIM + col;
                    uint32_t hi, lo; split2(v0, v1, hi, lo);
                    *(uint32_t*)&Vh[a0] = hi;
                    *(uint32_t*)&Vl[a0] = lo;
                }
            }
        }
    }
}

// ---------------------------------------------------------------------------
__global__ __launch_bounds__(256)
void split_w4_kernel(const float* __restrict__ w0, const float* __restrict__ w1,
                     const float* __restrict__ w2, const float* __restrict__ w3,
                     __nv_bfloat16* __restrict__ hi, __nv_bfloat16* __restrict__ lo)
{
    const unsigned i = blockIdx.x * 256u + threadIdx.x;
    const int sel = i >> 20;
    const float* w = (sel == 0) ? w0 : (sel == 1) ? w1 : (sel == 2) ? w2 : w3;
    float v = w[i & 0xFFFFFu];
    __nv_bfloat16 h, l; split1(v, h, l);
    hi[i] = h; lo[i] = l;
}

// ---------------------------------------------------------------------------
// Tensor-core flash attention, pass order reworked (hh, lh, then hl with
// B-register reuse) to fit 128 regs for occupancy 2.
// ---------------------------------------------------------------------------
__global__ __launch_bounds__(256, 2)
void attn_mma(const __nv_bfloat16* __restrict__ Qh, const __nv_bfloat16* __restrict__ Ql,
              const __nv_bfloat16* __restrict__ Kh, const __nv_bfloat16* __restrict__ Kl,
              const __nv_bfloat16* __restrict__ Vh, const __nv_bfloat16* __restrict__ Vl,
              const int* __restrict__ cnt,
              __nv_bfloat16* __restrict__ Oh, __nv_bfloat16* __restrict__ Ol)
{
    __shared__ __align__(1024) unsigned char sm[32768];
    const int b = blockIdx.z, h = blockIdx.y;
    const int kend = cnt[b];
    const int q0 = blockIdx.x * 128;
    if (q0 >= kend) return;
    const int tid = threadIdx.x, wid = tid >> 5, lane = tid & 31;
    const uint32_t smu = smem_u32(sm);

    const __nv_bfloat16* Qhb = Qh + ((size_t)(b * HN + h) * TDIM + q0) * DH;
    const __nv_bfloat16* Qlb = Ql + ((size_t)(b * HN + h) * TDIM + q0) * DH;
#pragma unroll
    for (int it = 0; it < 4; ++it) {
        const int lin = it * 256 + tid;
        const int row = lin >> 3, qd = lin & 7;
        uint4 a = *(const uint4*)(Qhb + (size_t)row * DH + qd * 8);
        uint4 c = *(const uint4*)(Qlb + (size_t)row * DH + qd * 8);
        const uint32_t so = sw128((uint32_t)row * 128 + qd * 16);
        *(uint4*)(sm + so) = a;
        *(uint4*)(sm + 16384 + so) = c;
    }
    __syncthreads();
    uint32_t qfh[4][4], qfl[4][4];
    {
        const uint32_t aRow = wid * 16 + (lane & 15);
        const uint32_t aColB = (lane >> 4) << 4;
#pragma unroll
        for (int kk = 0; kk < 4; ++kk) {
            ldsm4(qfh[kk], smu + sw128(aRow * 128 + kk * 32 + aColB));
            ldsm4(qfl[kk], smu + 16384 + sw128(aRow * 128 + kk * 32 + aColB));
        }
    }
    __syncthreads();

    float oacc[8][4];
#pragma unroll
    for (int i = 0; i < 8; ++i)
#pragma unroll
        for (int c = 0; c < 4; ++c) oacc[i][c] = 0.f;
    float mrow[2] = {-1e30f, -1e30f}, lrow[2] = {0.f, 0.f};
    const float scale = 0.125f;
    const uint32_t bRow  = (lane & 7) + ((lane >> 4) << 3);
    const uint32_t bColB = ((lane >> 3) & 1) << 4;
    const int jc = (lane & 3) * 2;

    const __nv_bfloat16* Khb = Kh + ((size_t)(b * HN + h) * TDIM) * DH;
    const __nv_bfloat16* Klb = Kl + ((size_t)(b * HN + h) * TDIM) * DH;
    const __nv_bfloat16* Vhb = Vh + ((size_t)b * CDIM + h * DH) * TDIM;
    const __nv_bfloat16* Vlb = Vl + ((size_t)b * CDIM + h * DH) * TDIM;

    for (int k0 = 0; k0 < kend; k0 += 64) {
#pragma unroll
        for (int it = 0; it < 2; ++it) {
            const int lin = it * 256 + tid;
            const int row = lin >> 3, qd = lin & 7;
            uint4 a = *(const uint4*)(Khb + (size_t)(k0 + row) * DH + qd * 8);
            uint4 c = *(const uint4*)(Klb + (size_t)(k0 + row) * DH + qd * 8);
            uint4 e = *(const uint4*)(Vhb + (size_t)row * TDIM + k0 + qd * 8);
            uint4 f = *(const uint4*)(Vlb + (size_t)row * TDIM + k0 + qd * 8);
            const uint32_t so = sw128((uint32_t)row * 128 + qd * 16);
            *(uint4*)(sm + so) = a;
            *(uint4*)(sm +  8192 + so) = c;
            *(uint4*)(sm + 16384 + so) = e;
            *(uint4*)(sm + 24576 + so) = f;
        }
        __syncthreads();

        float s[8][4];
#pragma unroll
        for (int i = 0; i < 8; ++i)
#pragma unroll
            for (int c = 0; c < 4; ++c) s[i][c] = 0.f;
        // S = QK^T : qh*kh, ql*kh, then kl overwrite -> qh*kl
#pragma unroll
        for (int kk = 0; kk < 4; ++kk) {
            uint32_t bfr[8][2];
#pragma unroll
            for (int np = 0; np < 4; ++np) {
                uint32_t rr[4];
                ldsm4(rr, smu + sw128((np * 16 + bRow) * 128 + kk * 32 + bColB));
                bfr[np * 2 + 0][0] = rr[0]; bfr[np * 2 + 0][1] = rr[1];
                bfr[np * 2 + 1][0] = rr[2]; bfr[np * 2 + 1][1] = rr[3];
            }
#pragma unroll
            for (int nt = 0; nt < 8; ++nt) mma16816(s[nt], qfh[kk], bfr[nt]);
#pragma unroll
            for (int nt = 0; nt < 8; ++nt) mma16816(s[nt], qfl[kk], bfr[nt]);
#pragma unroll
            for (int np = 0; np < 4; ++np) {
                uint32_t rr[4];
                ldsm4(rr, smu + 8192 + sw128((np * 16 + bRow) * 128 + kk * 32 + bColB));
                bfr[np * 2 + 0][0] = rr[0]; bfr[np * 2 + 0][1] = rr[1];
                bfr[np * 2 + 1][0] = rr[2]; bfr[np * 2 + 1][1] = rr[3];
            }
#pragma unroll
            for (int nt = 0; nt < 8; ++nt) mma16816(s[nt], qfh[kk], bfr[nt]);
        }

#pragma unroll
        for (int rh = 0; rh < 2; ++rh) {
            float mx = -1e30f;
#pragma unroll
            for (int nt = 0; nt < 8; ++nt) {
                const int jg = k0 + nt * 8 + jc;
                float v0 = (jg     < kend) ? s[nt][rh * 2 + 0] * scale : -1e30f;
                float v1 = (jg + 1 < kend) ? s[nt][rh * 2 + 1] * scale : -1e30f;
                s[nt][rh * 2 + 0] = v0; s[nt][rh * 2 + 1] = v1;
                mx = fmaxf(mx, fmaxf(v0, v1));
            }
            mx = fmaxf(mx, __shfl_xor_sync(0xffffffffu, mx, 1));
            mx = fmaxf(mx, __shfl_xor_sync(0xffffffffu, mx, 2));
            const float mnew = fmaxf(mrow[rh], mx);
            const float fac = __expf(mrow[rh] - mnew);
            mrow[rh] = mnew;
            float sum = 0.f;
#pragma unroll
            for (int nt = 0; nt < 8; ++nt) {
                float p0 = __expf(s[nt][rh * 2 + 0] - mnew);
                float p1 = __expf(s[nt][rh * 2 + 1] - mnew);
                s[nt][rh * 2 + 0] = p0; s[nt][rh * 2 + 1] = p1;
                sum += p0 + p1;
            }
            sum += __shfl_xor_sync(0xffffffffu, sum, 1);
            sum += __shfl_xor_sync(0xffffffffu, sum, 2);
            lrow[rh] = lrow[rh] * fac + sum;
#pragma unroll
            for (int nt = 0; nt < 8; ++nt) {
                oacc[nt][rh * 2 + 0] *= fac;
                oacc[nt][rh * 2 + 1] *= fac;
            }
        }

        uint32_t ph[4][4], pl2[4][4];
#pragma unroll
        for (int kk2 = 0; kk2 < 4; ++kk2) {
            const int t0 = 2 * kk2, t1 = 2 * kk2 + 1;
            split2(s[t0][0], s[t0][1], ph[kk2][0], pl2[kk2][0]);
            split2(s[t0][2], s[t0][3], ph[kk2][1], pl2[kk2][1]);
            split2(s[t1][0], s[t1][1], ph[kk2][2], pl2[kk2][2]);
            split2(s[t1][2], s[t1][3], ph[kk2][3], pl2[kk2][3]);
        }

        // O += P V : ph*vh, pl*vh, then vl overwrite -> ph*vl
#pragma unroll
        for (int kk2 = 0; kk2 < 4; ++kk2) {
            uint32_t vfr[8][2];
#pragma unroll
            for (int np = 0; np < 4; ++np) {
                uint32_t rr[4];
                ldsm4(rr, smu + 16384 + sw128((np * 16 + bRow) * 128 + kk2 * 32 + bColB));
                vfr[np * 2 + 0][0] = rr[0]; vfr[np * 2 + 0][1] = rr[1];
                vfr[np * 2 + 1][0] = rr[2]; vfr[np * 2 + 1][1] = rr[3];
            }
#pragma unroll
            for (int nt = 0; nt < 8; ++nt) mma16816(oacc[nt], ph[kk2], vfr[nt]);
#pragma unroll
            for (int nt = 0; nt < 8; ++nt) mma16816(oacc[nt], pl2[kk2], vfr[nt]);
#pragma unroll
            for (int np = 0; np < 4; ++np) {
                uint32_t rr[4];
                ldsm4(rr, smu + 24576 + sw128((np * 16 + bRow) * 128 + kk2 * 32 + bColB));
                vfr[np * 2 + 0][0] = rr[0]; vfr[np * 2 + 0][1] = rr[1];
                vfr[np * 2 + 1][0] = rr[2]; vfr[np * 2 + 1][1] = rr[3];
            }
#pragma unroll
            for (int nt = 0; nt < 8; ++nt) mma16816(oacc[nt], ph[kk2], vfr[nt]);
        }
        __syncthreads();
    }

#pragma unroll
    for (int rh = 0; rh < 2; ++rh) {
        const int q = q0 + wid * 16 + (lane >> 2) + rh * 8;
        const float inv = (lrow[rh] > 0.f) ? (1.f / lrow[rh]) : 0.f;
        const size_t base = ((size_t)b * TDIM + q) * CDIM + h * DH;
#pragma unroll
        for (int nt = 0; nt < 8; ++nt) {
            const int d = nt * 8 + jc;
            uint32_t hi, lo;
            split2(oacc[nt][rh * 2 + 0] * inv, oacc[nt][rh * 2 + 1] * inv, hi, lo);
            *(uint32_t*)&Oh[base + d] = hi;
            *(uint32_t*)&Ol[base + d] = lo;
        }
    }
}

// ---------------------------------------------------------------------------
__global__ void zero_kernel(float4* __restrict__ p, int n4)
{
    int i = blockIdx.x * blockDim.x + threadIdx.x;
    if (i < n4) p[i] = make_float4(0.f, 0.f, 0.f, 0.f);
}

__global__ void write_mask_kernel(const unsigned* __restrict__ mask,
                                  float* __restrict__ out, int n)
{
    int i = blockIdx.x * blockDim.x + threadIdx.x;
    if (i < n) out[i] = mask[i] ? 1.0f : 0.0f;
}

// ---------------------------------------------------------------------------
extern "C" void kernel_launch(void* const* d_in, const int* in_sizes, int n_in,
                              void* d_out, int out_size)
{
    const float*    x    = (const float*)d_in[0];
    const unsigned* mask = (const unsigned*)d_in[1];
    const float*    Wq   = (const float*)d_in[2];
    const float*    bq   = (const float*)d_in[3];
    const float*    Wk   = (const float*)d_in[4];
    const float*    bk   = (const float*)d_in[5];
    const float*    Wv   = (const float*)d_in[6];
    const float*    bv   = (const float*)d_in[7];
    const float*    Wp   = (const float*)d_in[8];
    const float*    bp   = (const float*)d_in[9];
    float* out = (float*)d_out;

    __nv_bfloat16 *wh, *wl, *xh, *xl, *ah, *al, *qh, *ql, *kh, *kl, *vh, *vl;
    int *gidx, *gcnt;
    cudaGetSymbolAddress((void**)&wh,   g_Wh);
    cudaGetSymbolAddress((void**)&wl,   g_Wl);
    cudaGetSymbolAddress((void**)&xh,   g_xTh);
    cudaGetSymbolAddress((void**)&xl,   g_xTl);
    cudaGetSymbolAddress((void**)&ah,   g_aTh);
    cudaGetSymbolAddress((void**)&al,   g_aTl);
    cudaGetSymbolAddress((void**)&qh,   g_qh);
    cudaGetSymbolAddress((void**)&ql,   g_ql);
    cudaGetSymbolAddress((void**)&kh,   g_kh);
    cudaGetSymbolAddress((void**)&kl,   g_kl);
    cudaGetSymbolAddress((void**)&vh,   g_vh);
    cudaGetSymbolAddress((void**)&vl,   g_vl);
    cudaGetSymbolAddress((void**)&gidx, g_idx);
    cudaGetSymbolAddress((void**)&gcnt, g_cnt);

    static int smem_set = 0;
    if (!smem_set) {
        cudaFuncSetAttribute(mma_gemm, cudaFuncAttributeMaxDynamicSharedMemorySize, 65536);
        smem_set = 1;
    }

    compact_kernel<<<BSZ, 256>>>(mask, gidx, gcnt);

    const int n4 = BSZ * CDIM * TDIM / 4;
    zero_kernel<<<(n4 + 255) / 256, 256>>>((float4*)out, n4);

    split_w4_kernel<<<4 * CDIM * CDIM / 256, 256>>>(Wq, Wk, Wv, Wp, wh, wl);

    dim3 gt(TDIM / 32, CDIM / 32, BSZ);
    gather_transpose_split<<<gt, dim3(32, 8)>>>(x, gidx, gcnt, xh, xl);

    const size_t WN = (size_t)CDIM * CDIM;
    dim3 gqkv(TDIM / 128, 24, BSZ);
    mma_gemm<<<gqkv, 256, 65536>>>(wh, wl, xh, xl, bq, bk, bv,
                                   nullptr, qh, ql, kh, kl, vh, vl, gcnt, gidx, 1);

    dim3 ga(TDIM / 128, HN, BSZ);
    attn_mma<<<ga, 256>>>(qh, ql, kh, kl, vh, vl, gcnt, ah, al);

    dim3 gp(TDIM / 128, CDIM / 128, BSZ);
    mma_gemm<<<gp, 256, 65536>>>(wh + 3 * WN, wl + 3 * WN, ah, al, bp, nullptr, nullptr,
                                 out, nullptr, nullptr, nullptr, nullptr, nullptr, nullptr,
                                 gcnt, gidx, 0);

    const long long nout = (long long)BSZ * CDIM * TDIM;
    const int tail = out_size - (int)nout;
    if (tail >= BSZ * TDIM) {
        write_mask_kernel<<<(BSZ * TDIM + 255) / 256, 256>>>(
            mask, out + nout, BSZ * TDIM);
    }
}

// round 8
// speedup vs baseline: 5.7559x; 1.3944x over previous
#include <cuda_runtime.h>
#include <cuda_fp16.h>
#include <stdint.h>

#define BSZ  2
#define CDIM 1024
#define TDIM 2048
#define HN   16
#define DH   64

// ---------------- scratch (static device globals) ----------------
__device__ __half g_Wh [(size_t)4 * CDIM * CDIM];   // [Wq;Wk;Wv;Wp] fp16 hi
__device__ __half g_xTh[(size_t)BSZ * TDIM * CDIM];   // (B, Tc, C) fp16 hi
__device__ __half g_xTl[(size_t)BSZ * TDIM * CDIM];   // lo
__device__ __half g_qh [(size_t)BSZ * HN * TDIM * DH]; // (B,H,Tc,D)
__device__ __half g_ql [(size_t)BSZ * HN * TDIM * DH];
__device__ __half g_kh [(size_t)BSZ * HN * TDIM * DH]; // hi only
__device__ __half g_vh [(size_t)BSZ * CDIM * TDIM];    // (B, C, Tc) hi only
__device__ __half g_aTh[(size_t)BSZ * TDIM * CDIM];    // attn out (B, Tc, C)
__device__ __half g_aTl[(size_t)BSZ * TDIM * CDIM];
__device__ int g_idx[BSZ * TDIM];
__device__ int g_cnt[BSZ];

// ---------------- helpers ----------------
__device__ __forceinline__ uint32_t smem_u32(const void* p) {
    uint32_t a;
    asm("{ .reg .u64 t; cvta.to.shared.u64 t, %1; cvt.u32.u64 %0, t; }" : "=r"(a) : "l"(p));
    return a;
}
__device__ __forceinline__ uint32_t sw128(uint32_t off) { return off ^ ((off >> 3) & 0x70); }

__device__ __forceinline__ void ldsm4(uint32_t* r, uint32_t addr) {
    asm volatile("ldmatrix.sync.aligned.m8n8.x4.shared.b16 {%0,%1,%2,%3}, [%4];"
        : "=r"(r[0]), "=r"(r[1]), "=r"(r[2]), "=r"(r[3]) : "r"(addr));
}
__device__ __forceinline__ void mma16816(float* c, const uint32_t* a, const uint32_t* b) {
    asm volatile("mma.sync.aligned.m16n8k16.row.col.f32.f16.f16.f32 "
        "{%0,%1,%2,%3}, {%4,%5,%6,%7}, {%8,%9}, {%0,%1,%2,%3};"
        : "+f"(c[0]), "+f"(c[1]), "+f"(c[2]), "+f"(c[3])
        : "r"(a[0]), "r"(a[1]), "r"(a[2]), "r"(a[3]), "r"(b[0]), "r"(b[1]));
}
__device__ __forceinline__ void split1h(float v, __half& h, __half& l) {
    h = __float2half(v);
    l = __float2half(v - __half2float(h));
}
__device__ __forceinline__ void split2h(float v0, float v1, uint32_t& hi, uint32_t& lo) {
    __half h0, l0, h1, l1;
    split1h(v0, h0, l0); split1h(v1, h1, l1);
    hi = (uint32_t)__half_as_ushort(h0) | ((uint32_t)__half_as_ushort(h1) << 16);
    lo = (uint32_t)__half_as_ushort(l0) | ((uint32_t)__half_as_ushort(l1) << 16);
}
__device__ __forceinline__ uint32_t pack2h(float v0, float v1) {
    return (uint32_t)__half_as_ushort(__float2half(v0)) |
           ((uint32_t)__half_as_ushort(__float2half(v1)) << 16);
}
__device__ __forceinline__ void cpasync16(uint32_t dst, const void* src) {
    asm volatile("cp.async.cg.shared.global [%0], [%1], 16;" :: "r"(dst), "l"(src));
}
#define CP_COMMIT() asm volatile("cp.async.commit_group;" ::: "memory")
#define CP_WAIT0()  asm volatile("cp.async.wait_group 0;" ::: "memory")
#define CP_WAIT1()  asm volatile("cp.async.wait_group 1;" ::: "memory")

// ---------------------------------------------------------------------------
__global__ __launch_bounds__(256)
void compact_kernel(const unsigned* __restrict__ mask, int* __restrict__ idx,
                    int* __restrict__ cnt)
{
    __shared__ int wsum[8];
    __shared__ int wexcl[8];
    const int b = blockIdx.x;
    const unsigned* mb = mask + (size_t)b * TDIM;
    int* ib = idx + (size_t)b * TDIM;
    const int tid  = threadIdx.x;
    const int lane = tid & 31, w = tid >> 5;
    unsigned v[8]; int c = 0;
#pragma unroll
    for (int i = 0; i < 8; ++i) { v[i] = mb[tid * 8 + i]; c += v[i] ? 1 : 0; }
    int inc = c;
#pragma unroll
    for (int off = 1; off < 32; off <<= 1) {
        int n = __shfl_up_sync(0xffffffffu, inc, off);
        if (lane >= off) inc += n;
    }
    if (lane == 31) wsum[w] = inc;
    __syncthreads();
    if (tid == 0) {
        int s = 0;
#pragma unroll
        for (int i = 0; i < 8; ++i) { wexcl[i] = s; s += wsum[i]; }
        cnt[b] = s;
    }
    __syncthreads();
    int p = wexcl[w] + inc - c;
#pragma unroll
    for (int i = 0; i < 8; ++i) if (v[i]) ib[p++] = tid * 8 + i;
}

// ---------------------------------------------------------------------------
__global__ __launch_bounds__(256)
void gather_transpose_split(const float* __restrict__ src,
                            const int* __restrict__ idx, const int* __restrict__ cnt,
                            __half* __restrict__ dh, __half* __restrict__ dl)
{
    __shared__ float tile[32][33];
    __shared__ int tloc[32];
    const int b = blockIdx.z;
    const int n = cnt[b];
    const int i0 = blockIdx.x * 32;
    if (i0 >= n) return;
    const int c0 = blockIdx.y * 32;
    const float* s = src + (size_t)b * CDIM * TDIM;
    __half* ph = dh + (size_t)b * TDIM * CDIM;
    __half* pl = dl + (size_t)b * TDIM * CDIM;
    const int tx = threadIdx.x, ty = threadIdx.y;
    if (ty == 0) tloc[tx] = (i0 + tx < n) ? idx[b * TDIM + i0 + tx] : -1;
    __syncthreads();
    const int t = tloc[tx];
#pragma unroll
    for (int i = 0; i < 4; ++i)
        tile[ty + i * 8][tx] = (t >= 0) ? s[(size_t)(c0 + ty + i * 8) * TDIM + t] : 0.f;
    __syncthreads();
#pragma unroll
    for (int i = 0; i < 4; ++i) {
        const int irow = i0 + ty + i * 8;
        if (irow < n) {
            float v = tile[tx][ty + i * 8];
            __half h, l; split1h(v, h, l);
            size_t o = (size_t)irow * CDIM + c0 + tx;
            ph[o] = h; pl[o] = l;
        }
    }
}

// ---------------------------------------------------------------------------
// fp16 2-pass GEMM: C = Wh * (Bh + Bl)^T + bias. A = weights hi only.
// fusedQKV=1: outputs Q (hi+lo), K (hi), V (hi). fusedQKV=0: scatter P-proj.
// ---------------------------------------------------------------------------
extern __shared__ unsigned char dynsm[];

__global__ __launch_bounds__(256, 2)
void mma_gemm(const __half* __restrict__ Ah,
              const __half* __restrict__ Bh, const __half* __restrict__ Bl,
              const float* __restrict__ b0, const float* __restrict__ b1,
              const float* __restrict__ b2, float* __restrict__ Cout,
              __half* __restrict__ Qh, __half* __restrict__ Ql,
              __half* __restrict__ Kh, __half* __restrict__ Vh,
              const int* __restrict__ cnt, const int* __restrict__ idx, int fusedQKV)
{
    __shared__ int sidx[128];

    const int b    = blockIdx.z;
    const int nlim = cnt[b];
    const int n0   = blockIdx.x * 128;
    if (n0 >= nlim) return;
    const int m0   = blockIdx.y * 128;
    const int tid  = threadIdx.x;
    const int wid  = tid >> 5;
    const int lane = tid & 31;
    const int wy   = wid & 1;
    const int wx   = wid >> 1;

    const uint32_t smu = smem_u32(dynsm);

    const __half* Bhb = Bh + (size_t)b * TDIM * CDIM;
    const __half* Blb = Bl + (size_t)b * TDIM * CDIM;

    const int r     = tid >> 1;
    const int which = tid & 1;
    const __half* aP = Ah + (size_t)(m0 + r) * CDIM;          // hi only, which==0 loads
    const __half* bP = (which ? Blb : Bhb) + (size_t)(n0 + r) * CDIM;
    const uint32_t rowb = (uint32_t)r * 128 + (uint32_t)which * 64;
    const uint32_t rowbA = (uint32_t)r * 128;                 // A hi at offset 0

    float acc[4][4][4];
#pragma unroll
    for (int i = 0; i < 4; ++i)
#pragma unroll
        for (int j = 0; j < 4; ++j)
#pragma unroll
            for (int c = 0; c < 4; ++c) acc[i][j][c] = 0.f;

    const uint32_t aRow = (uint32_t)(wy * 64 + (lane & 15));
    const uint32_t aCol = (uint32_t)((lane >> 4) << 4);
    const uint32_t bRow = (uint32_t)(wx * 32 + (lane & 7) + ((lane >> 4) << 3));
    const uint32_t bCol = (uint32_t)(((lane >> 3) & 1) << 4);

    {
        if (which == 0)
#pragma unroll
            for (int i = 0; i < 4; ++i)
                cpasync16(smu + sw128(rowbA + i * 16), aP + i * 8);
#pragma unroll
        for (int i = 0; i < 4; ++i)
            cpasync16(smu + 16384 + sw128(rowb + i * 16), bP + i * 8);
        CP_COMMIT();
    }

    for (int kb = 0; kb < 32; ++kb) {
        const uint32_t stg = (uint32_t)(kb & 1) * 32768u;
        if (kb < 31) {
            const uint32_t nst = (uint32_t)((kb + 1) & 1) * 32768u;
            const int k1 = (kb + 1) * 32;
            if (which == 0)
#pragma unroll
                for (int i = 0; i < 4; ++i)
                    cpasync16(smu + nst + sw128(rowbA + i * 16), aP + k1 + i * 8);
#pragma unroll
            for (int i = 0; i < 4; ++i)
                cpasync16(smu + nst + 16384 + sw128(rowb + i * 16), bP + k1 + i * 8);
            CP_COMMIT();
            CP_WAIT1();
        } else {
            CP_WAIT0();
        }
        __syncthreads();

        const uint32_t smA_u = smu + stg;
        const uint32_t smB_u = smu + stg + 16384;
#pragma unroll
        for (int s = 0; s < 2; ++s) {
            const uint32_t ksA = s * 32;
            uint32_t afr[4][4], bfr[4][2];

#pragma unroll
            for (int mt = 0; mt < 4; ++mt)
                ldsm4(afr[mt], smA_u + sw128((aRow + mt * 16) * 128 + ksA + aCol));
            // B-hi
#pragma unroll
            for (int np = 0; np < 2; ++np) {
                uint32_t rr[4];
                ldsm4(rr, smB_u + sw128((bRow + np * 16) * 128 + ksA + bCol));
                bfr[np * 2 + 0][0] = rr[0]; bfr[np * 2 + 0][1] = rr[1];
                bfr[np * 2 + 1][0] = rr[2]; bfr[np * 2 + 1][1] = rr[3];
            }
#pragma unroll
            for (int mt = 0; mt < 4; ++mt)
#pragma unroll
                for (int nt = 0; nt < 4; ++nt)
                    mma16816(acc[mt][nt], afr[mt], bfr[nt]);
            // B-lo
#pragma unroll
            for (int np = 0; np < 2; ++np) {
                uint32_t rr[4];
                ldsm4(rr, smB_u + sw128((bRow + np * 16) * 128 + 64 + ksA + bCol));
                bfr[np * 2 + 0][0] = rr[0]; bfr[np * 2 + 0][1] = rr[1];
                bfr[np * 2 + 1][0] = rr[2]; bfr[np * 2 + 1][1] = rr[3];
            }
#pragma unroll
            for (int mt = 0; mt < 4; ++mt)
#pragma unroll
                for (int nt = 0; nt < 4; ++nt)
                    mma16816(acc[mt][nt], afr[mt], bfr[nt]);
        }
        __syncthreads();
    }

    // ---- epilogue ----
    const int sector = m0 >> 10;
    const int mbase  = m0 & 1023;
    const float* bptr = fusedQKV ? (sector == 0 ? b0 : (sector == 1 ? b1 : b2)) : b0;

    if (!fusedQKV) {
        if (tid < 128) sidx[tid] = (n0 + tid < nlim) ? idx[b * TDIM + n0 + tid] : -1;
        __syncthreads();
    }

    const int qrow = lane >> 2;
    const int qcol = (lane & 3) * 2;
#pragma unroll
    for (int mt = 0; mt < 4; ++mt) {
#pragma unroll
        for (int rh = 0; rh < 2; ++rh) {
            const int rloc = mbase + wy * 64 + mt * 16 + qrow + rh * 8;
            const float bi = bptr[rloc];
#pragma unroll
            for (int nt = 0; nt < 4; ++nt) {
                const int col = n0 + wx * 32 + nt * 8 + qcol;
                float v0 = acc[mt][nt][rh * 2 + 0] + bi;
                float v1 = acc[mt][nt][rh * 2 + 1] + bi;
                if (!fusedQKV) {
                    float* dst = Cout + (size_t)b * CDIM * TDIM + (size_t)rloc * TDIM;
                    const int t0 = sidx[col - n0 + 0];
                    const int t1 = sidx[col - n0 + 1];
                    if (t0 >= 0) dst[t0] = v0;
                    if (t1 >= 0) dst[t1] = v1;
                } else if (sector < 2) {
                    __half* oh = sector ? Kh : Qh;
                    const int hh = rloc >> 6, dd = rloc & 63;
                    const size_t a0 = ((size_t)(b * HN + hh) * TDIM + col) * DH + dd;
                    __half h0, l0, h1, l1;
                    split1h(v0, h0, l0); split1h(v1, h1, l1);
                    oh[a0] = h0; oh[a0 + DH] = h1;
                    if (sector == 0) { Ql[a0] = l0; Ql[a0 + DH] = l1; }
                } else {
                    const size_t a0 = ((size_t)b * CDIM + rloc) * TDIM + col;
                    *(uint32_t*)&Vh[a0] = pack2h(v0, v1);
                }
            }
        }
    }
}

// ---------------------------------------------------------------------------
__global__ __launch_bounds__(256)
void split_w4_kernel(const float* __restrict__ w0, const float* __restrict__ w1,
                     const float* __restrict__ w2, const float* __restrict__ w3,
                     __half* __restrict__ hi)
{
    const unsigned i = blockIdx.x * 256u + threadIdx.x;
    const int sel = i >> 20;
    const float* w = (sel == 0) ? w0 : (sel == 1) ? w1 : (sel == 2) ? w2 : w3;
    hi[i] = __float2half(w[i & 0xFFFFFu]);
}

// ---------------------------------------------------------------------------
// fp16 2-pass flash attention: S = (Qh+Ql)·Kh, O = (Ph+Pl)·Vh.
// K, V hi-only in smem (8KB each).
// ---------------------------------------------------------------------------
__global__ __launch_bounds__(256, 2)
void attn_mma(const __half* __restrict__ Qh, const __half* __restrict__ Ql,
              const __half* __restrict__ Kh, const __half* __restrict__ Vh,
              const int* __restrict__ cnt,
              __half* __restrict__ Oh, __half* __restrict__ Ol)
{
    __shared__ __align__(1024) unsigned char sm[32768];
    const int b = blockIdx.z, h = blockIdx.y;
    const int kend = cnt[b];
    const int q0 = blockIdx.x * 128;
    if (q0 >= kend) return;
    const int tid = threadIdx.x, wid = tid >> 5, lane = tid & 31;
    const uint32_t smu = smem_u32(sm);

    const __half* Qhb = Qh + ((size_t)(b * HN + h) * TDIM + q0) * DH;
    const __half* Qlb = Ql + ((size_t)(b * HN + h) * TDIM + q0) * DH;
#pragma unroll
    for (int it = 0; it < 4; ++it) {
        const int lin = it * 256 + tid;
        const int row = lin >> 3, qd = lin & 7;
        uint4 a = *(const uint4*)(Qhb + (size_t)row * DH + qd * 8);
        uint4 c = *(const uint4*)(Qlb + (size_t)row * DH + qd * 8);
        const uint32_t so = sw128((uint32_t)row * 128 + qd * 16);
        *(uint4*)(sm + so) = a;
        *(uint4*)(sm + 16384 + so) = c;
    }
    __syncthreads();
    uint32_t qfh[4][4], qfl[4][4];
    {
        const uint32_t aRow = wid * 16 + (lane & 15);
        const uint32_t aColB = (lane >> 4) << 4;
#pragma unroll
        for (int kk = 0; kk < 4; ++kk) {
            ldsm4(qfh[kk], smu + sw128(aRow * 128 + kk * 32 + aColB));
            ldsm4(qfl[kk], smu + 16384 + sw128(aRow * 128 + kk * 32 + aColB));
        }
    }
    __syncthreads();

    float oacc[8][4];
#pragma unroll
    for (int i = 0; i < 8; ++i)
#pragma unroll
        for (int c = 0; c < 4; ++c) oacc[i][c] = 0.f;
    float mrow[2] = {-1e30f, -1e30f}, lrow[2] = {0.f, 0.f};
    const float scale = 0.125f;
    const uint32_t bRow  = (lane & 7) + ((lane >> 4) << 3);
    const uint32_t bColB = ((lane >> 3) & 1) << 4;
    const int jc = (lane & 3) * 2;

    const __half* Khb = Kh + ((size_t)(b * HN + h) * TDIM) * DH;
    const __half* Vhb = Vh + ((size_t)b * CDIM + h * DH) * TDIM;

    for (int k0 = 0; k0 < kend; k0 += 64) {
        // load K hi (rows=key, cols=d) @0 and V hi (rows=d, cols=key) @8192
#pragma unroll
        for (int it = 0; it < 2; ++it) {
            const int lin = it * 256 + tid;     // 0..511
            const int row = lin >> 3, qd = lin & 7;
            uint4 a = *(const uint4*)(Khb + (size_t)(k0 + row) * DH + qd * 8);
            uint4 e = *(const uint4*)(Vhb + (size_t)row * TDIM + k0 + qd * 8);
            const uint32_t so = sw128((uint32_t)row * 128 + qd * 16);
            *(uint4*)(sm + so) = a;
            *(uint4*)(sm + 8192 + so) = e;
        }
        __syncthreads();

        float s[8][4];
#pragma unroll
        for (int i = 0; i < 8; ++i)
#pragma unroll
            for (int c = 0; c < 4; ++c) s[i][c] = 0.f;
        // S = (Qh + Ql) Kh^T
#pragma unroll
        for (int kk = 0; kk < 4; ++kk) {
            uint32_t bfr[8][2];
#pragma unroll
            for (int np = 0; np < 4; ++np) {
                uint32_t rr[4];
                ldsm4(rr, smu + sw128((np * 16 + bRow) * 128 + kk * 32 + bColB));
                bfr[np * 2 + 0][0] = rr[0]; bfr[np * 2 + 0][1] = rr[1];
                bfr[np * 2 + 1][0] = rr[2]; bfr[np * 2 + 1][1] = rr[3];
            }
#pragma unroll
            for (int nt = 0; nt < 8; ++nt) mma16816(s[nt], qfh[kk], bfr[nt]);
#pragma unroll
            for (int nt = 0; nt < 8; ++nt) mma16816(s[nt], qfl[kk], bfr[nt]);
        }

#pragma unroll
        for (int rh = 0; rh < 2; ++rh) {
            float mx = -1e30f;
#pragma unroll
            for (int nt = 0; nt < 8; ++nt) {
                const int jg = k0 + nt * 8 + jc;
                float v0 = (jg     < kend) ? s[nt][rh * 2 + 0] * scale : -1e30f;
                float v1 = (jg + 1 < kend) ? s[nt][rh * 2 + 1] * scale : -1e30f;
                s[nt][rh * 2 + 0] = v0; s[nt][rh * 2 + 1] = v1;
                mx = fmaxf(mx, fmaxf(v0, v1));
            }
            mx = fmaxf(mx, __shfl_xor_sync(0xffffffffu, mx, 1));
            mx = fmaxf(mx, __shfl_xor_sync(0xffffffffu, mx, 2));
            const float mnew = fmaxf(mrow[rh], mx);
            const float fac = __expf(mrow[rh] - mnew);
            mrow[rh] = mnew;
            float sum = 0.f;
#pragma unroll
            for (int nt = 0; nt < 8; ++nt) {
                float p0 = __expf(s[nt][rh * 2 + 0] - mnew);
                float p1 = __expf(s[nt][rh * 2 + 1] - mnew);
                s[nt][rh * 2 + 0] = p0; s[nt][rh * 2 + 1] = p1;
                sum += p0 + p1;
            }
            sum += __shfl_xor_sync(0xffffffffu, sum, 1);
            sum += __shfl_xor_sync(0xffffffffu, sum, 2);
            lrow[rh] = lrow[rh] * fac + sum;
#pragma unroll
            for (int nt = 0; nt < 8; ++nt) {
                oacc[nt][rh * 2 + 0] *= fac;
                oacc[nt][rh * 2 + 1] *= fac;
            }
        }

        // P fp32 -> fp16 hi/lo A-fragments
        uint32_t ph[4][4], pl2[4][4];
#pragma unroll
        for (int kk2 = 0; kk2 < 4; ++kk2) {
            const int t0 = 2 * kk2, t1 = 2 * kk2 + 1;
            split2h(s[t0][0], s[t0][1], ph[kk2][0], pl2[kk2][0]);
            split2h(s[t0][2], s[t0][3], ph[kk2][1], pl2[kk2][1]);
            split2h(s[t1][0], s[t1][1], ph[kk2][2], pl2[kk2][2]);
            split2h(s[t1][2], s[t1][3], ph[kk2][3], pl2[kk2][3]);
        }

        // O += (Ph + Pl) Vh
#pragma unroll
        for (int kk2 = 0; kk2 < 4; ++kk2) {
            uint32_t vfr[8][2];
#pragma unroll
            for (int np = 0; np < 4; ++np) {
                uint32_t rr[4];
                ldsm4(rr, smu + 8192 + sw128((np * 16 + bRow) * 128 + kk2 * 32 + bColB));
                vfr[np * 2 + 0][0] = rr[0]; vfr[np * 2 + 0][1] = rr[1];
                vfr[np * 2 + 1][0] = rr[2]; vfr[np * 2 + 1][1] = rr[3];
            }
#pragma unroll
            for (int nt = 0; nt < 8; ++nt) mma16816(oacc[nt], ph[kk2], vfr[nt]);
#pragma unroll
            for (int nt = 0; nt < 8; ++nt) mma16816(oacc[nt], pl2[kk2], vfr[nt]);
        }
        __syncthreads();
    }

#pragma unroll
    for (int rh = 0; rh < 2; ++rh) {
        const int q = q0 + wid * 16 + (lane >> 2) + rh * 8;
        const float inv = (lrow[rh] > 0.f) ? (1.f / lrow[rh]) : 0.f;
        const size_t base = ((size_t)b * TDIM + q) * CDIM + h * DH;
#pragma unroll
        for (int nt = 0; nt < 8; ++nt) {
            const int d = nt * 8 + jc;
            uint32_t hi, lo;
            split2h(oacc[nt][rh * 2 + 0] * inv, oacc[nt][rh * 2 + 1] * inv, hi, lo);
            *(uint32_t*)&Oh[base + d] = hi;
            *(uint32_t*)&Ol[base + d] = lo;
        }
    }
}

// ---------------------------------------------------------------------------
__global__ void zero_kernel(float4* __restrict__ p, int n4)
{
    int i = blockIdx.x * blockDim.x + threadIdx.x;
    if (i < n4) p[i] = make_float4(0.f, 0.f, 0.f, 0.f);
}

__global__ void write_mask_kernel(const unsigned* __restrict__ mask,
                                  float* __restrict__ out, int n)
{
    int i = blockIdx.x * blockDim.x + threadIdx.x;
    if (i < n) out[i] = mask[i] ? 1.0f : 0.0f;
}

// ---------------------------------------------------------------------------
extern "C" void kernel_launch(void* const* d_in, const int* in_sizes, int n_in,
                              void* d_out, int out_size)
{
    const float*    x    = (const float*)d_in[0];
    const unsigned* mask = (const unsigned*)d_in[1];
    const float*    Wq   = (const float*)d_in[2];
    const float*    bq   = (const float*)d_in[3];
    const float*    Wk   = (const float*)d_in[4];
    const float*    bk   = (const float*)d_in[5];
    const float*    Wv   = (const float*)d_in[6];
    const float*    bv   = (const float*)d_in[7];
    const float*    Wp   = (const float*)d_in[8];
    const float*    bp   = (const float*)d_in[9];
    float* out = (float*)d_out;

    __half *wh, *xh, *xl, *ah, *al, *qh, *ql, *kh, *vh;
    int *gidx, *gcnt;
    cudaGetSymbolAddress((void**)&wh,   g_Wh);
    cudaGetSymbolAddress((void**)&xh,   g_xTh);
    cudaGetSymbolAddress((void**)&xl,   g_xTl);
    cudaGetSymbolAddress((void**)&ah,   g_aTh);
    cudaGetSymbolAddress((void**)&al,   g_aTl);
    cudaGetSymbolAddress((void**)&qh,   g_qh);
    cudaGetSymbolAddress((void**)&ql,   g_ql);
    cudaGetSymbolAddress((void**)&kh,   g_kh);
    cudaGetSymbolAddress((void**)&vh,   g_vh);
    cudaGetSymbolAddress((void**)&gidx, g_idx);
    cudaGetSymbolAddress((void**)&gcnt, g_cnt);

    static int smem_set = 0;
    if (!smem_set) {
        cudaFuncSetAttribute(mma_gemm, cudaFuncAttributeMaxDynamicSharedMemorySize, 65536);
        smem_set = 1;
    }

    compact_kernel<<<BSZ, 256>>>(mask, gidx, gcnt);

    const int n4 = BSZ * CDIM * TDIM / 4;
    zero_kernel<<<(n4 + 255) / 256, 256>>>((float4*)out, n4);

    split_w4_kernel<<<4 * CDIM * CDIM / 256, 256>>>(Wq, Wk, Wv, Wp, wh);

    dim3 gt(TDIM / 32, CDIM / 32, BSZ);
    gather_transpose_split<<<gt, dim3(32, 8)>>>(x, gidx, gcnt, xh, xl);

    const size_t WN = (size_t)CDIM * CDIM;
    dim3 gqkv(TDIM / 128, 24, BSZ);
    mma_gemm<<<gqkv, 256, 65536>>>(wh, xh, xl, bq, bk, bv,
                                   nullptr, qh, ql, kh, vh, gcnt, gidx, 1);

    dim3 ga(TDIM / 128, HN, BSZ);
    attn_mma<<<ga, 256>>>(qh, ql, kh, vh, gcnt, ah, al);

    dim3 gp(TDIM / 128, CDIM / 128, BSZ);
    mma_gemm<<<gp, 256, 65536>>>(wh + 3 * WN, ah, al, bp, nullptr, nullptr,
                                 out, nullptr, nullptr, nullptr, nullptr,
                                 gcnt, gidx, 0);

    const long long nout = (long long)BSZ * CDIM * TDIM;
    const int tail = out_size - (int)nout;
    if (tail >= BSZ * TDIM) {
        write_mask_kernel<<<(BSZ * TDIM + 255) / 256, 256>>>(
            mask, out + nout, BSZ * TDIM);
    }
}

// round 9
// speedup vs baseline: 6.3220x; 1.0983x over previous
#include <cuda_runtime.h>
#include <cuda_fp16.h>
#include <stdint.h>

#define BSZ  2
#define CDIM 1024
#define TDIM 2048
#define HN   16
#define DH   64

// ---------------- scratch (static device globals) ----------------
__device__ __half g_Wh [(size_t)4 * CDIM * CDIM];     // [Wq;Wk;Wv;Wp] fp16 hi
__device__ __half g_xTh[(size_t)BSZ * TDIM * CDIM];   // (B, Tc, C) fp16 hi
__device__ __half g_xTl[(size_t)BSZ * TDIM * CDIM];   // lo
__device__ __half g_qh [(size_t)BSZ * HN * TDIM * DH]; // (B,H,Tc,D) hi only
__device__ __half g_kh [(size_t)BSZ * HN * TDIM * DH]; // hi only
__device__ __half g_vh [(size_t)BSZ * CDIM * TDIM];    // (B, C, Tc) hi only
__device__ __half g_aTh[(size_t)BSZ * TDIM * CDIM];    // attn out (B, Tc, C)
__device__ __half g_aTl[(size_t)BSZ * TDIM * CDIM];
__device__ int g_idx[BSZ * TDIM];
__device__ int g_cnt[BSZ];

// ---------------- helpers ----------------
__device__ __forceinline__ uint32_t smem_u32(const void* p) {
    uint32_t a;
    asm("{ .reg .u64 t; cvta.to.shared.u64 t, %1; cvt.u32.u64 %0, t; }" : "=r"(a) : "l"(p));
    return a;
}
__device__ __forceinline__ uint32_t sw128(uint32_t off) { return off ^ ((off >> 3) & 0x70); }

__device__ __forceinline__ void ldsm4(uint32_t* r, uint32_t addr) {
    asm volatile("ldmatrix.sync.aligned.m8n8.x4.shared.b16 {%0,%1,%2,%3}, [%4];"
        : "=r"(r[0]), "=r"(r[1]), "=r"(r[2]), "=r"(r[3]) : "r"(addr));
}
__device__ __forceinline__ void mma16816(float* c, const uint32_t* a, const uint32_t* b) {
    asm volatile("mma.sync.aligned.m16n8k16.row.col.f32.f16.f16.f32 "
        "{%0,%1,%2,%3}, {%4,%5,%6,%7}, {%8,%9}, {%0,%1,%2,%3};"
        : "+f"(c[0]), "+f"(c[1]), "+f"(c[2]), "+f"(c[3])
        : "r"(a[0]), "r"(a[1]), "r"(a[2]), "r"(a[3]), "r"(b[0]), "r"(b[1]));
}
__device__ __forceinline__ void split1h(float v, __half& h, __half& l) {
    h = __float2half(v);
    l = __float2half(v - __half2float(h));
}
__device__ __forceinline__ void split2h(float v0, float v1, uint32_t& hi, uint32_t& lo) {
    __half h0, l0, h1, l1;
    split1h(v0, h0, l0); split1h(v1, h1, l1);
    hi = (uint32_t)__half_as_ushort(h0) | ((uint32_t)__half_as_ushort(h1) << 16);
    lo = (uint32_t)__half_as_ushort(l0) | ((uint32_t)__half_as_ushort(l1) << 16);
}
__device__ __forceinline__ uint32_t pack2h(float v0, float v1) {
    return (uint32_t)__half_as_ushort(__float2half(v0)) |
           ((uint32_t)__half_as_ushort(__float2half(v1)) << 16);
}
__device__ __forceinline__ void cpasync16(uint32_t dst, const void* src) {
    asm volatile("cp.async.cg.shared.global [%0], [%1], 16;" :: "r"(dst), "l"(src));
}
#define CP_COMMIT() asm volatile("cp.async.commit_group;" ::: "memory")
#define CP_WAIT0()  asm volatile("cp.async.wait_group 0;" ::: "memory")
#define CP_WAIT1()  asm volatile("cp.async.wait_group 1;" ::: "memory")

// ---------------------------------------------------------------------------
__global__ __launch_bounds__(256)
void compact_kernel(const unsigned* __restrict__ mask, int* __restrict__ idx,
                    int* __restrict__ cnt)
{
    __shared__ int wsum[8];
    __shared__ int wexcl[8];
    const int b = blockIdx.x;
    const unsigned* mb = mask + (size_t)b * TDIM;
    int* ib = idx + (size_t)b * TDIM;
    const int tid  = threadIdx.x;
    const int lane = tid & 31, w = tid >> 5;
    unsigned v[8]; int c = 0;
#pragma unroll
    for (int i = 0; i < 8; ++i) { v[i] = mb[tid * 8 + i]; c += v[i] ? 1 : 0; }
    int inc = c;
#pragma unroll
    for (int off = 1; off < 32; off <<= 1) {
        int n = __shfl_up_sync(0xffffffffu, inc, off);
        if (lane >= off) inc += n;
    }
    if (lane == 31) wsum[w] = inc;
    __syncthreads();
    if (tid == 0) {
        int s = 0;
#pragma unroll
        for (int i = 0; i < 8; ++i) { wexcl[i] = s; s += wsum[i]; }
        cnt[b] = s;
    }
    __syncthreads();
    int p = wexcl[w] + inc - c;
#pragma unroll
    for (int i = 0; i < 8; ++i) if (v[i]) ib[p++] = tid * 8 + i;
}

// ---------------------------------------------------------------------------
__global__ __launch_bounds__(256)
void gather_transpose_split(const float* __restrict__ src,
                            const int* __restrict__ idx, const int* __restrict__ cnt,
                            __half* __restrict__ dh, __half* __restrict__ dl)
{
    __shared__ float tile[32][33];
    __shared__ int tloc[32];
    const int b = blockIdx.z;
    const int n = cnt[b];
    const int i0 = blockIdx.x * 32;
    if (i0 >= n) return;
    const int c0 = blockIdx.y * 32;
    const float* s = src + (size_t)b * CDIM * TDIM;
    __half* ph = dh + (size_t)b * TDIM * CDIM;
    __half* pl = dl + (size_t)b * TDIM * CDIM;
    const int tx = threadIdx.x, ty = threadIdx.y;
    if (ty == 0) tloc[tx] = (i0 + tx < n) ? idx[b * TDIM + i0 + tx] : -1;
    __syncthreads();
    const int t = tloc[tx];
#pragma unroll
    for (int i = 0; i < 4; ++i)
        tile[ty + i * 8][tx] = (t >= 0) ? s[(size_t)(c0 + ty + i * 8) * TDIM + t] : 0.f;
    __syncthreads();
#pragma unroll
    for (int i = 0; i < 4; ++i) {
        const int irow = i0 + ty + i * 8;
        if (irow < n) {
            float v = tile[tx][ty + i * 8];
            __half h, l; split1h(v, h, l);
            size_t o = (size_t)irow * CDIM + c0 + tx;
            ph[o] = h; pl[o] = l;
        }
    }
}

// ---------------------------------------------------------------------------
// fp16 2-pass GEMM: C = Wh * (Bh + Bl)^T + bias. A = weights hi only.
// fusedQKV=1: outputs Q (hi), K (hi), V (hi). fusedQKV=0: scatter P-proj.
// ---------------------------------------------------------------------------
extern __shared__ unsigned char dynsm[];

__global__ __launch_bounds__(256, 2)
void mma_gemm(const __half* __restrict__ Ah,
              const __half* __restrict__ Bh, const __half* __restrict__ Bl,
              const float* __restrict__ b0, const float* __restrict__ b1,
              const float* __restrict__ b2, float* __restrict__ Cout,
              __half* __restrict__ Qh, __half* __restrict__ Kh, __half* __restrict__ Vh,
              const int* __restrict__ cnt, const int* __restrict__ idx, int fusedQKV)
{
    __shared__ int sidx[128];

    const int b    = blockIdx.z;
    const int nlim = cnt[b];
    const int n0   = blockIdx.x * 128;
    if (n0 >= nlim) return;
    const int m0   = blockIdx.y * 128;
    const int tid  = threadIdx.x;
    const int wid  = tid >> 5;
    const int lane = tid & 31;
    const int wy   = wid & 1;
    const int wx   = wid >> 1;

    const uint32_t smu = smem_u32(dynsm);

    const __half* Bhb = Bh + (size_t)b * TDIM * CDIM;
    const __half* Blb = Bl + (size_t)b * TDIM * CDIM;

    const int r     = tid >> 1;
    const int which = tid & 1;
    const __half* aP = Ah + (size_t)(m0 + r) * CDIM;
    const __half* bP = (which ? Blb : Bhb) + (size_t)(n0 + r) * CDIM;
    const uint32_t rowb = (uint32_t)r * 128 + (uint32_t)which * 64;
    const uint32_t rowbA = (uint32_t)r * 128;

    float acc[4][4][4];
#pragma unroll
    for (int i = 0; i < 4; ++i)
#pragma unroll
        for (int j = 0; j < 4; ++j)
#pragma unroll
            for (int c = 0; c < 4; ++c) acc[i][j][c] = 0.f;

    const uint32_t aRow = (uint32_t)(wy * 64 + (lane & 15));
    const uint32_t aCol = (uint32_t)((lane >> 4) << 4);
    const uint32_t bRow = (uint32_t)(wx * 32 + (lane & 7) + ((lane >> 4) << 3));
    const uint32_t bCol = (uint32_t)(((lane >> 3) & 1) << 4);

    {
        if (which == 0)
#pragma unroll
            for (int i = 0; i < 4; ++i)
                cpasync16(smu + sw128(rowbA + i * 16), aP + i * 8);
#pragma unroll
        for (int i = 0; i < 4; ++i)
            cpasync16(smu + 16384 + sw128(rowb + i * 16), bP + i * 8);
        CP_COMMIT();
    }

    for (int kb = 0; kb < 32; ++kb) {
        const uint32_t stg = (uint32_t)(kb & 1) * 32768u;
        if (kb < 31) {
            const uint32_t nst = (uint32_t)((kb + 1) & 1) * 32768u;
            const int k1 = (kb + 1) * 32;
            if (which == 0)
#pragma unroll
                for (int i = 0; i < 4; ++i)
                    cpasync16(smu + nst + sw128(rowbA + i * 16), aP + k1 + i * 8);
#pragma unroll
            for (int i = 0; i < 4; ++i)
                cpasync16(smu + nst + 16384 + sw128(rowb + i * 16), bP + k1 + i * 8);
            CP_COMMIT();
            CP_WAIT1();
        } else {
            CP_WAIT0();
        }
        __syncthreads();

        const uint32_t smA_u = smu + stg;
        const uint32_t smB_u = smu + stg + 16384;
#pragma unroll
        for (int s = 0; s < 2; ++s) {
            const uint32_t ksA = s * 32;
            uint32_t afr[4][4], bfr[4][2];

#pragma unroll
            for (int mt = 0; mt < 4; ++mt)
                ldsm4(afr[mt], smA_u + sw128((aRow + mt * 16) * 128 + ksA + aCol));
#pragma unroll
            for (int np = 0; np < 2; ++np) {
                uint32_t rr[4];
                ldsm4(rr, smB_u + sw128((bRow + np * 16) * 128 + ksA + bCol));
                bfr[np * 2 + 0][0] = rr[0]; bfr[np * 2 + 0][1] = rr[1];
                bfr[np * 2 + 1][0] = rr[2]; bfr[np * 2 + 1][1] = rr[3];
            }
#pragma unroll
            for (int mt = 0; mt < 4; ++mt)
#pragma unroll
                for (int nt = 0; nt < 4; ++nt)
                    mma16816(acc[mt][nt], afr[mt], bfr[nt]);
#pragma unroll
            for (int np = 0; np < 2; ++np) {
                uint32_t rr[4];
                ldsm4(rr, smB_u + sw128((bRow + np * 16) * 128 + 64 + ksA + bCol));
                bfr[np * 2 + 0][0] = rr[0]; bfr[np * 2 + 0][1] = rr[1];
                bfr[np * 2 + 1][0] = rr[2]; bfr[np * 2 + 1][1] = rr[3];
            }
#pragma unroll
            for (int mt = 0; mt < 4; ++mt)
#pragma unroll
                for (int nt = 0; nt < 4; ++nt)
                    mma16816(acc[mt][nt], afr[mt], bfr[nt]);
        }
        __syncthreads();
    }

    // ---- epilogue ----
    const int sector = m0 >> 10;
    const int mbase  = m0 & 1023;
    const float* bptr = fusedQKV ? (sector == 0 ? b0 : (sector == 1 ? b1 : b2)) : b0;

    if (!fusedQKV) {
        if (tid < 128) sidx[tid] = (n0 + tid < nlim) ? idx[b * TDIM + n0 + tid] : -1;
        __syncthreads();
    }

    const int qrow = lane >> 2;
    const int qcol = (lane & 3) * 2;
#pragma unroll
    for (int mt = 0; mt < 4; ++mt) {
#pragma unroll
        for (int rh = 0; rh < 2; ++rh) {
            const int rloc = mbase + wy * 64 + mt * 16 + qrow + rh * 8;
            const float bi = bptr[rloc];
#pragma unroll
            for (int nt = 0; nt < 4; ++nt) {
                const int col = n0 + wx * 32 + nt * 8 + qcol;
                float v0 = acc[mt][nt][rh * 2 + 0] + bi;
                float v1 = acc[mt][nt][rh * 2 + 1] + bi;
                if (!fusedQKV) {
                    float* dst = Cout + (size_t)b * CDIM * TDIM + (size_t)rloc * TDIM;
                    const int t0 = sidx[col - n0 + 0];
                    const int t1 = sidx[col - n0 + 1];
                    if (t0 >= 0) dst[t0] = v0;
                    if (t1 >= 0) dst[t1] = v1;
                } else if (sector < 2) {
                    __half* oh = sector ? Kh : Qh;
                    const int hh = rloc >> 6, dd = rloc & 63;
                    const size_t a0 = ((size_t)(b * HN + hh) * TDIM + col) * DH + dd;
                    oh[a0]      = __float2half(v0);
                    oh[a0 + DH] = __float2half(v1);
                } else {
                    const size_t a0 = ((size_t)b * CDIM + rloc) * TDIM + col;
                    *(uint32_t*)&Vh[a0] = pack2h(v0, v1);
                }
            }
        }
    }
}

// ---------------------------------------------------------------------------
__global__ __launch_bounds__(256)
void split_w4_kernel(const float* __restrict__ w0, const float* __restrict__ w1,
                     const float* __restrict__ w2, const float* __restrict__ w3,
                     __half* __restrict__ hi)
{
    const unsigned i = blockIdx.x * 256u + threadIdx.x;
    const int sel = i >> 20;
    const float* w = (sel == 0) ? w0 : (sel == 1) ? w1 : (sel == 2) ? w2 : w3;
    hi[i] = __float2half(w[i & 0xFFFFFu]);
}

// ---------------------------------------------------------------------------
// fp16 single-pass flash attention: S = Qh·Kh, O = Ph·Vh (hi-only operands,
// fp32 accumulators). Out kept hi/lo for the 2-pass P-projection.
// ---------------------------------------------------------------------------
__global__ __launch_bounds__(256, 2)
void attn_mma(const __half* __restrict__ Qh, const __half* __restrict__ Kh,
              const __half* __restrict__ Vh, const int* __restrict__ cnt,
              __half* __restrict__ Oh, __half* __restrict__ Ol)
{
    __shared__ __align__(1024) unsigned char sm[24576];
    const int b = blockIdx.z, h = blockIdx.y;
    const int kend = cnt[b];
    const int q0 = blockIdx.x * 128;
    if (q0 >= kend) return;
    const int tid = threadIdx.x, wid = tid >> 5, lane = tid & 31;
    const uint32_t smu = smem_u32(sm);

    // stage Q (hi), extract A-fragments
    const __half* Qhb = Qh + ((size_t)(b * HN + h) * TDIM + q0) * DH;
#pragma unroll
    for (int it = 0; it < 4; ++it) {
        const int lin = it * 256 + tid;         // 0..1023
        const int row = lin >> 3, qd = lin & 7;
        uint4 a = *(const uint4*)(Qhb + (size_t)row * DH + qd * 8);
        *(uint4*)(sm + sw128((uint32_t)row * 128 + qd * 16)) = a;
    }
    __syncthreads();
    uint32_t qfh[4][4];
    {
        const uint32_t aRow = wid * 16 + (lane & 15);
        const uint32_t aColB = (lane >> 4) << 4;
#pragma unroll
        for (int kk = 0; kk < 4; ++kk)
            ldsm4(qfh[kk], smu + sw128(aRow * 128 + kk * 32 + aColB));
    }
    __syncthreads();

    float oacc[8][4];
#pragma unroll
    for (int i = 0; i < 8; ++i)
#pragma unroll
        for (int c = 0; c < 4; ++c) oacc[i][c] = 0.f;
    float mrow[2] = {-1e30f, -1e30f}, lrow[2] = {0.f, 0.f};
    const float scale = 0.125f;
    const uint32_t bRow  = (lane & 7) + ((lane >> 4) << 3);
    const uint32_t bColB = ((lane >> 3) & 1) << 4;
    const int jc = (lane & 3) * 2;

    const __half* Khb = Kh + ((size_t)(b * HN + h) * TDIM) * DH;
    const __half* Vhb = Vh + ((size_t)b * CDIM + h * DH) * TDIM;

    for (int k0 = 0; k0 < kend; k0 += 64) {
        // load K (rows=key, cols=d) @0 and V (rows=d, cols=key) @8192
#pragma unroll
        for (int it = 0; it < 2; ++it) {
            const int lin = it * 256 + tid;     // 0..511
            const int row = lin >> 3, qd = lin & 7;
            uint4 a = *(const uint4*)(Khb + (size_t)(k0 + row) * DH + qd * 8);
            uint4 e = *(const uint4*)(Vhb + (size_t)row * TDIM + k0 + qd * 8);
            const uint32_t so = sw128((uint32_t)row * 128 + qd * 16);
            *(uint4*)(sm + so) = a;
            *(uint4*)(sm + 8192 + so) = e;
        }
        __syncthreads();

        float s[8][4];
#pragma unroll
        for (int i = 0; i < 8; ++i)
#pragma unroll
            for (int c = 0; c < 4; ++c) s[i][c] = 0.f;
        // S = Qh Kh^T
#pragma unroll
        for (int kk = 0; kk < 4; ++kk) {
            uint32_t bfr[8][2];
#pragma unroll
            for (int np = 0; np < 4; ++np) {
                uint32_t rr[4];
                ldsm4(rr, smu + sw128((np * 16 + bRow) * 128 + kk * 32 + bColB));
                bfr[np * 2 + 0][0] = rr[0]; bfr[np * 2 + 0][1] = rr[1];
                bfr[np * 2 + 1][0] = rr[2]; bfr[np * 2 + 1][1] = rr[3];
            }
#pragma unroll
            for (int nt = 0; nt < 8; ++nt) mma16816(s[nt], qfh[kk], bfr[nt]);
        }

#pragma unroll
        for (int rh = 0; rh < 2; ++rh) {
            float mx = -1e30f;
#pragma unroll
            for (int nt = 0; nt < 8; ++nt) {
                const int jg = k0 + nt * 8 + jc;
                float v0 = (jg     < kend) ? s[nt][rh * 2 + 0] * scale : -1e30f;
                float v1 = (jg + 1 < kend) ? s[nt][rh * 2 + 1] * scale : -1e30f;
                s[nt][rh * 2 + 0] = v0; s[nt][rh * 2 + 1] = v1;
                mx = fmaxf(mx, fmaxf(v0, v1));
            }
            mx = fmaxf(mx, __shfl_xor_sync(0xffffffffu, mx, 1));
            mx = fmaxf(mx, __shfl_xor_sync(0xffffffffu, mx, 2));
            const float mnew = fmaxf(mrow[rh], mx);
            const float fac = __expf(mrow[rh] - mnew);
            mrow[rh] = mnew;
            float sum = 0.f;
#pragma unroll
            for (int nt = 0; nt < 8; ++nt) {
                float p0 = __expf(s[nt][rh * 2 + 0] - mnew);
                float p1 = __expf(s[nt][rh * 2 + 1] - mnew);
                s[nt][rh * 2 + 0] = p0; s[nt][rh * 2 + 1] = p1;
                sum += p0 + p1;
            }
            sum += __shfl_xor_sync(0xffffffffu, sum, 1);
            sum += __shfl_xor_sync(0xffffffffu, sum, 2);
            lrow[rh] = lrow[rh] * fac + sum;
#pragma unroll
            for (int nt = 0; nt < 8; ++nt) {
                oacc[nt][rh * 2 + 0] *= fac;
                oacc[nt][rh * 2 + 1] *= fac;
            }
        }

        // P fp32 -> fp16 hi A-fragments
        uint32_t ph[4][4];
#pragma unroll
        for (int kk2 = 0; kk2 < 4; ++kk2) {
            const int t0 = 2 * kk2, t1 = 2 * kk2 + 1;
            ph[kk2][0] = pack2h(s[t0][0], s[t0][1]);
            ph[kk2][1] = pack2h(s[t0][2], s[t0][3]);
            ph[kk2][2] = pack2h(s[t1][0], s[t1][1]);
            ph[kk2][3] = pack2h(s[t1][2], s[t1][3]);
        }

        // O += Ph Vh
#pragma unroll
        for (int kk2 = 0; kk2 < 4; ++kk2) {
            uint32_t vfr[8][2];
#pragma unroll
            for (int np = 0; np < 4; ++np) {
                uint32_t rr[4];
                ldsm4(rr, smu + 8192 + sw128((np * 16 + bRow) * 128 + kk2 * 32 + bColB));
                vfr[np * 2 + 0][0] = rr[0]; vfr[np * 2 + 0][1] = rr[1];
                vfr[np * 2 + 1][0] = rr[2]; vfr[np * 2 + 1][1] = rr[3];
            }
#pragma unroll
            for (int nt = 0; nt < 8; ++nt) mma16816(oacc[nt], ph[kk2], vfr[nt]);
        }
        __syncthreads();
    }

#pragma unroll
    for (int rh = 0; rh < 2; ++rh) {
        const int q = q0 + wid * 16 + (lane >> 2) + rh * 8;
        const float inv = (lrow[rh] > 0.f) ? (1.f / lrow[rh]) : 0.f;
        const size_t base = ((size_t)b * TDIM + q) * CDIM + h * DH;
#pragma unroll
        for (int nt = 0; nt < 8; ++nt) {
            const int d = nt * 8 + jc;
            uint32_t hi, lo;
            split2h(oacc[nt][rh * 2 + 0] * inv, oacc[nt][rh * 2 + 1] * inv, hi, lo);
            *(uint32_t*)&Oh[base + d] = hi;
            *(uint32_t*)&Ol[base + d] = lo;
        }
    }
}

// ---------------------------------------------------------------------------
__global__ void zero_kernel(float4* __restrict__ p, int n4)
{
    int i = blockIdx.x * blockDim.x + threadIdx.x;
    if (i < n4) p[i] = make_float4(0.f, 0.f, 0.f, 0.f);
}

__global__ void write_mask_kernel(const unsigned* __restrict__ mask,
                                  float* __restrict__ out, int n)
{
    int i = blockIdx.x * blockDim.x + threadIdx.x;
    if (i < n) out[i] = mask[i] ? 1.0f : 0.0f;
}

// ---------------------------------------------------------------------------
extern "C" void kernel_launch(void* const* d_in, const int* in_sizes, int n_in,
                              void* d_out, int out_size)
{
    const float*    x    = (const float*)d_in[0];
    const unsigned* mask = (const unsigned*)d_in[1];
    const float*    Wq   = (const float*)d_in[2];
    const float*    bq   = (const float*)d_in[3];
    const float*    Wk   = (const float*)d_in[4];
    const float*    bk   = (const float*)d_in[5];
    const float*    Wv   = (const float*)d_in[6];
    const float*    bv   = (const float*)d_in[7];
    const float*    Wp   = (const float*)d_in[8];
    const float*    bp   = (const float*)d_in[9];
    float* out = (float*)d_out;

    __half *wh, *xh, *xl, *ah, *al, *qh, *kh, *vh;
    int *gidx, *gcnt;
    cudaGetSymbolAddress((void**)&wh,   g_Wh);
    cudaGetSymbolAddress((void**)&xh,   g_xTh);
    cudaGetSymbolAddress((void**)&xl,   g_xTl);
    cudaGetSymbolAddress((void**)&ah,   g_aTh);
    cudaGetSymbolAddress((void**)&al,   g_aTl);
    cudaGetSymbolAddress((void**)&qh,   g_qh);
    cudaGetSymbolAddress((void**)&kh,   g_kh);
    cudaGetSymbolAddress((void**)&vh,   g_vh);
    cudaGetSymbolAddress((void**)&gidx, g_idx);
    cudaGetSymbolAddress((void**)&gcnt, g_cnt);

    static int smem_set = 0;
    if (!smem_set) {
        cudaFuncSetAttribute(mma_gemm, cudaFuncAttributeMaxDynamicSharedMemorySize, 65536);
        smem_set = 1;
    }

    compact_kernel<<<BSZ, 256>>>(mask, gidx, gcnt);

    const int n4 = BSZ * CDIM * TDIM / 4;
    zero_kernel<<<(n4 + 255) / 256, 256>>>((float4*)out, n4);

    split_w4_kernel<<<4 * CDIM * CDIM / 256, 256>>>(Wq, Wk, Wv, Wp, wh);

    dim3 gt(TDIM / 32, CDIM / 32, BSZ);
    gather_transpose_split<<<gt, dim3(32, 8)>>>(x, gidx, gcnt, xh, xl);

    const size_t WN = (size_t)CDIM * CDIM;
    dim3 gqkv(TDIM / 128, 24, BSZ);
    mma_gemm<<<gqkv, 256, 65536>>>(wh, xh, xl, bq, bk, bv,
                                   nullptr, qh, kh, vh, gcnt, gidx, 1);

    dim3 ga(TDIM / 128, HN, BSZ);
    attn_mma<<<ga, 256>>>(qh, kh, vh, gcnt, ah, al);

    dim3 gp(TDIM / 128, CDIM / 128, BSZ);
    mma_gemm<<<gp, 256, 65536>>>(wh + 3 * WN, ah, al, bp, nullptr, nullptr,
                                 out, nullptr, nullptr, nullptr,
                                 gcnt, gidx, 0);

    const long long nout = (long long)BSZ * CDIM * TDIM;
    const int tail = out_size - (int)nout;
    if (tail >= BSZ * TDIM) {
        write_mask_kernel<<<(BSZ * TDIM + 255) / 256, 256>>>(
            mask, out + nout, BSZ * TDIM);
    }
}

// round 10
// speedup vs baseline: 7.4199x; 1.1737x over previous
#include <cuda_runtime.h>
#include <cuda_fp16.h>
#include <stdint.h>

#define BSZ  2
#define CDIM 1024
#define TDIM 2048
#define HN   16
#define DH   64

// ---------------- scratch (static device globals) ----------------
__device__ __half g_Wh [(size_t)4 * CDIM * CDIM];     // [Wq;Wk;Wv;Wp] fp16 hi
__device__ __half g_xTh[(size_t)BSZ * TDIM * CDIM];   // (B, Tc, C) fp16 hi
__device__ __half g_qh [(size_t)BSZ * HN * TDIM * DH]; // (B,H,Tc,D) hi only
__device__ __half g_kh [(size_t)BSZ * HN * TDIM * DH]; // hi only
__device__ __half g_vh [(size_t)BSZ * CDIM * TDIM];    // (B, C, Tc) hi only
__device__ __half g_aTh[(size_t)BSZ * TDIM * CDIM];    // attn out (B, Tc, C)
__device__ __half g_aTl[(size_t)BSZ * TDIM * CDIM];
__device__ int g_idx[BSZ * TDIM];
__device__ int g_cnt[BSZ];

// ---------------- helpers ----------------
__device__ __forceinline__ uint32_t smem_u32(const void* p) {
    uint32_t a;
    asm("{ .reg .u64 t; cvta.to.shared.u64 t, %1; cvt.u32.u64 %0, t; }" : "=r"(a) : "l"(p));
    return a;
}
__device__ __forceinline__ uint32_t sw128(uint32_t off) { return off ^ ((off >> 3) & 0x70); }

__device__ __forceinline__ void ldsm4(uint32_t* r, uint32_t addr) {
    asm volatile("ldmatrix.sync.aligned.m8n8.x4.shared.b16 {%0,%1,%2,%3}, [%4];"
        : "=r"(r[0]), "=r"(r[1]), "=r"(r[2]), "=r"(r[3]) : "r"(addr));
}
__device__ __forceinline__ void mma16816(float* c, const uint32_t* a, const uint32_t* b) {
    asm volatile("mma.sync.aligned.m16n8k16.row.col.f32.f16.f16.f32 "
        "{%0,%1,%2,%3}, {%4,%5,%6,%7}, {%8,%9}, {%0,%1,%2,%3};"
        : "+f"(c[0]), "+f"(c[1]), "+f"(c[2]), "+f"(c[3])
        : "r"(a[0]), "r"(a[1]), "r"(a[2]), "r"(a[3]), "r"(b[0]), "r"(b[1]));
}
__device__ __forceinline__ void split1h(float v, __half& h, __half& l) {
    h = __float2half(v);
    l = __float2half(v - __half2float(h));
}
__device__ __forceinline__ void split2h(float v0, float v1, uint32_t& hi, uint32_t& lo) {
    __half h0, l0, h1, l1;
    split1h(v0, h0, l0); split1h(v1, h1, l1);
    hi = (uint32_t)__half_as_ushort(h0) | ((uint32_t)__half_as_ushort(h1) << 16);
    lo = (uint32_t)__half_as_ushort(l0) | ((uint32_t)__half_as_ushort(l1) << 16);
}
__device__ __forceinline__ uint32_t pack2h(float v0, float v1) {
    return (uint32_t)__half_as_ushort(__float2half(v0)) |
           ((uint32_t)__half_as_ushort(__float2half(v1)) << 16);
}
__device__ __forceinline__ void cpasync16(uint32_t dst, const void* src) {
    asm volatile("cp.async.cg.shared.global [%0], [%1], 16;" :: "r"(dst), "l"(src));
}
#define CP_COMMIT() asm volatile("cp.async.commit_group;" ::: "memory")
#define CP_WAIT0()  asm volatile("cp.async.wait_group 0;" ::: "memory")
#define CP_WAIT1()  asm volatile("cp.async.wait_group 1;" ::: "memory")

// ---------------------------------------------------------------------------
__global__ __launch_bounds__(256)
void compact_kernel(const unsigned* __restrict__ mask, int* __restrict__ idx,
                    int* __restrict__ cnt)
{
    __shared__ int wsum[8];
    __shared__ int wexcl[8];
    const int b = blockIdx.x;
    const unsigned* mb = mask + (size_t)b * TDIM;
    int* ib = idx + (size_t)b * TDIM;
    const int tid  = threadIdx.x;
    const int lane = tid & 31, w = tid >> 5;
    unsigned v[8]; int c = 0;
#pragma unroll
    for (int i = 0; i < 8; ++i) { v[i] = mb[tid * 8 + i]; c += v[i] ? 1 : 0; }
    int inc = c;
#pragma unroll
    for (int off = 1; off < 32; off <<= 1) {
        int n = __shfl_up_sync(0xffffffffu, inc, off);
        if (lane >= off) inc += n;
    }
    if (lane == 31) wsum[w] = inc;
    __syncthreads();
    if (tid == 0) {
        int s = 0;
#pragma unroll
        for (int i = 0; i < 8; ++i) { wexcl[i] = s; s += wsum[i]; }
        cnt[b] = s;
    }
    __syncthreads();
    int p = wexcl[w] + inc - c;
#pragma unroll
    for (int i = 0; i < 8; ++i) if (v[i]) ib[p++] = tid * 8 + i;
}

// ---------------------------------------------------------------------------
// Gather + transpose: x (B,C,T) -> (B, Tc, C) fp16 hi only.
// ---------------------------------------------------------------------------
__global__ __launch_bounds__(256)
void gather_transpose(const float* __restrict__ src,
                      const int* __restrict__ idx, const int* __restrict__ cnt,
                      __half* __restrict__ dh)
{
    __shared__ float tile[32][33];
    __shared__ int tloc[32];
    const int b = blockIdx.z;
    const int n = cnt[b];
    const int i0 = blockIdx.x * 32;
    if (i0 >= n) return;
    const int c0 = blockIdx.y * 32;
    const float* s = src + (size_t)b * CDIM * TDIM;
    __half* ph = dh + (size_t)b * TDIM * CDIM;
    const int tx = threadIdx.x, ty = threadIdx.y;
    if (ty == 0) tloc[tx] = (i0 + tx < n) ? idx[b * TDIM + i0 + tx] : -1;
    __syncthreads();
    const int t = tloc[tx];
#pragma unroll
    for (int i = 0; i < 4; ++i)
        tile[ty + i * 8][tx] = (t >= 0) ? s[(size_t)(c0 + ty + i * 8) * TDIM + t] : 0.f;
    __syncthreads();
#pragma unroll
    for (int i = 0; i < 4; ++i) {
        const int irow = i0 + ty + i * 8;
        if (irow < n)
            ph[(size_t)irow * CDIM + c0 + tx] = __float2half(tile[tx][ty + i * 8]);
    }
}

// ---------------------------------------------------------------------------
// fp16 GEMM: C = Ah * (Bh [+ Bl])^T + bias.
// fusedQKV=1: single B pass (x hi only); outputs Q/K (B,H,Tc,D), V (B,C,Tc).
// fusedQKV=0: two B passes (attn-out hi+lo); scatter fp32 P-proj via idx.
// ---------------------------------------------------------------------------
extern __shared__ unsigned char dynsm[];

__global__ __launch_bounds__(256, 2)
void mma_gemm(const __half* __restrict__ Ah,
              const __half* __restrict__ Bh, const __half* __restrict__ Bl,
              const float* __restrict__ b0, const float* __restrict__ b1,
              const float* __restrict__ b2, float* __restrict__ Cout,
              __half* __restrict__ Qh, __half* __restrict__ Kh, __half* __restrict__ Vh,
              const int* __restrict__ cnt, const int* __restrict__ idx, int fusedQKV)
{
    __shared__ int sidx[128];

    const int b    = blockIdx.z;
    const int nlim = cnt[b];
    const int n0   = blockIdx.x * 128;
    if (n0 >= nlim) return;
    const int m0   = blockIdx.y * 128;
    const int tid  = threadIdx.x;
    const int wid  = tid >> 5;
    const int lane = tid & 31;
    const int wy   = wid & 1;
    const int wx   = wid >> 1;
    const int twoPass = !fusedQKV;

    const uint32_t smu = smem_u32(dynsm);

    const __half* Bhb = Bh + (size_t)b * TDIM * CDIM;
    const __half* Blb = Bl ? (Bl + (size_t)b * TDIM * CDIM) : Bhb;

    const int r     = tid >> 1;
    const int which = tid & 1;
    const __half* aP = Ah + (size_t)(m0 + r) * CDIM;
    const __half* bP = (which ? Blb : Bhb) + (size_t)(n0 + r) * CDIM;
    const uint32_t rowb = (uint32_t)r * 128 + (uint32_t)which * 64;
    const uint32_t rowbA = (uint32_t)r * 128;
    const bool loadB = twoPass || (which == 0);

    float acc[4][4][4];
#pragma unroll
    for (int i = 0; i < 4; ++i)
#pragma unroll
        for (int j = 0; j < 4; ++j)
#pragma unroll
            for (int c = 0; c < 4; ++c) acc[i][j][c] = 0.f;

    const uint32_t aRow = (uint32_t)(wy * 64 + (lane & 15));
    const uint32_t aCol = (uint32_t)((lane >> 4) << 4);
    const uint32_t bRow = (uint32_t)(wx * 32 + (lane & 7) + ((lane >> 4) << 3));
    const uint32_t bCol = (uint32_t)(((lane >> 3) & 1) << 4);

    {
        if (which == 0)
#pragma unroll
            for (int i = 0; i < 4; ++i)
                cpasync16(smu + sw128(rowbA + i * 16), aP + i * 8);
        if (loadB)
#pragma unroll
            for (int i = 0; i < 4; ++i)
                cpasync16(smu + 16384 + sw128(rowb + i * 16), bP + i * 8);
        CP_COMMIT();
    }

    for (int kb = 0; kb < 32; ++kb) {
        const uint32_t stg = (uint32_t)(kb & 1) * 32768u;
        if (kb < 31) {
            const uint32_t nst = (uint32_t)((kb + 1) & 1) * 32768u;
            const int k1 = (kb + 1) * 32;
            if (which == 0)
#pragma unroll
                for (int i = 0; i < 4; ++i)
                    cpasync16(smu + nst + sw128(rowbA + i * 16), aP + k1 + i * 8);
            if (loadB)
#pragma unroll
                for (int i = 0; i < 4; ++i)
                    cpasync16(smu + nst + 16384 + sw128(rowb + i * 16), bP + k1 + i * 8);
            CP_COMMIT();
            CP_WAIT1();
        } else {
            CP_WAIT0();
        }
        __syncthreads();

        const uint32_t smA_u = smu + stg;
        const uint32_t smB_u = smu + stg + 16384;
#pragma unroll
        for (int s = 0; s < 2; ++s) {
            const uint32_t ksA = s * 32;
            uint32_t afr[4][4], bfr[4][2];

#pragma unroll
            for (int mt = 0; mt < 4; ++mt)
                ldsm4(afr[mt], smA_u + sw128((aRow + mt * 16) * 128 + ksA + aCol));
#pragma unroll
            for (int np = 0; np < 2; ++np) {
                uint32_t rr[4];
                ldsm4(rr, smB_u + sw128((bRow + np * 16) * 128 + ksA + bCol));
                bfr[np * 2 + 0][0] = rr[0]; bfr[np * 2 + 0][1] = rr[1];
                bfr[np * 2 + 1][0] = rr[2]; bfr[np * 2 + 1][1] = rr[3];
            }
#pragma unroll
            for (int mt = 0; mt < 4; ++mt)
#pragma unroll
                for (int nt = 0; nt < 4; ++nt)
                    mma16816(acc[mt][nt], afr[mt], bfr[nt]);
            if (twoPass) {
#pragma unroll
                for (int np = 0; np < 2; ++np) {
                    uint32_t rr[4];
                    ldsm4(rr, smB_u + sw128((bRow + np * 16) * 128 + 64 + ksA + bCol));
                    bfr[np * 2 + 0][0] = rr[0]; bfr[np * 2 + 0][1] = rr[1];
                    bfr[np * 2 + 1][0] = rr[2]; bfr[np * 2 + 1][1] = rr[3];
                }
#pragma unroll
                for (int mt = 0; mt < 4; ++mt)
#pragma unroll
                    for (int nt = 0; nt < 4; ++nt)
                        mma16816(acc[mt][nt], afr[mt], bfr[nt]);
            }
        }
        __syncthreads();
    }

    // ---- epilogue ----
    const int sector = m0 >> 10;
    const int mbase  = m0 & 1023;
    const float* bptr = fusedQKV ? (sector == 0 ? b0 : (sector == 1 ? b1 : b2)) : b0;

    if (!fusedQKV) {
        if (tid < 128) sidx[tid] = (n0 + tid < nlim) ? idx[b * TDIM + n0 + tid] : -1;
        __syncthreads();
    }

    const int qrow = lane >> 2;
    const int qcol = (lane & 3) * 2;
#pragma unroll
    for (int mt = 0; mt < 4; ++mt) {
#pragma unroll
        for (int rh = 0; rh < 2; ++rh) {
            const int rloc = mbase + wy * 64 + mt * 16 + qrow + rh * 8;
            const float bi = bptr[rloc];
#pragma unroll
            for (int nt = 0; nt < 4; ++nt) {
                const int col = n0 + wx * 32 + nt * 8 + qcol;
                float v0 = acc[mt][nt][rh * 2 + 0] + bi;
                float v1 = acc[mt][nt][rh * 2 + 1] + bi;
                if (!fusedQKV) {
                    float* dst = Cout + (size_t)b * CDIM * TDIM + (size_t)rloc * TDIM;
                    const int t0 = sidx[col - n0 + 0];
                    const int t1 = sidx[col - n0 + 1];
                    if (t0 >= 0) dst[t0] = v0;
                    if (t1 >= 0) dst[t1] = v1;
                } else if (sector < 2) {
                    __half* oh = sector ? Kh : Qh;
                    const int hh = rloc >> 6, dd = rloc & 63;
                    const size_t a0 = ((size_t)(b * HN + hh) * TDIM + col) * DH + dd;
                    oh[a0]      = __float2half(v0);
                    oh[a0 + DH] = __float2half(v1);
                } else {
                    const size_t a0 = ((size_t)b * CDIM + rloc) * TDIM + col;
                    *(uint32_t*)&Vh[a0] = pack2h(v0, v1);
                }
            }
        }
    }
}

// ---------------------------------------------------------------------------
__global__ __launch_bounds__(256)
void split_w4_kernel(const float* __restrict__ w0, const float* __restrict__ w1,
                     const float* __restrict__ w2, const float* __restrict__ w3,
                     __half* __restrict__ hi)
{
    const unsigned i = blockIdx.x * 256u + threadIdx.x;
    const int sel = i >> 20;
    const float* w = (sel == 0) ? w0 : (sel == 1) ? w1 : (sel == 2) ? w2 : w3;
    hi[i] = __float2half(w[i & 0xFFFFFu]);
}

// ---------------------------------------------------------------------------
// fp16 single-pass flash attention: S = Qh·Kh, O = Ph·Vh.
// Out kept hi/lo for the 2-pass P-projection.
// ---------------------------------------------------------------------------
__global__ __launch_bounds__(256, 2)
void attn_mma(const __half* __restrict__ Qh, const __half* __restrict__ Kh,
              const __half* __restrict__ Vh, const int* __restrict__ cnt,
              __half* __restrict__ Oh, __half* __restrict__ Ol)
{
    __shared__ __align__(1024) unsigned char sm[24576];
    const int b = blockIdx.z, h = blockIdx.y;
    const int kend = cnt[b];
    const int q0 = blockIdx.x * 128;
    if (q0 >= kend) return;
    const int tid = threadIdx.x, wid = tid >> 5, lane = tid & 31;
    const uint32_t smu = smem_u32(sm);

    const __half* Qhb = Qh + ((size_t)(b * HN + h) * TDIM + q0) * DH;
#pragma unroll
    for (int it = 0; it < 4; ++it) {
        const int lin = it * 256 + tid;
        const int row = lin >> 3, qd = lin & 7;
        uint4 a = *(const uint4*)(Qhb + (size_t)row * DH + qd * 8);
        *(uint4*)(sm + sw128((uint32_t)row * 128 + qd * 16)) = a;
    }
    __syncthreads();
    uint32_t qfh[4][4];
    {
        const uint32_t aRow = wid * 16 + (lane & 15);
        const uint32_t aColB = (lane >> 4) << 4;
#pragma unroll
        for (int kk = 0; kk < 4; ++kk)
            ldsm4(qfh[kk], smu + sw128(aRow * 128 + kk * 32 + aColB));
    }
    __syncthreads();

    float oacc[8][4];
#pragma unroll
    for (int i = 0; i < 8; ++i)
#pragma unroll
        for (int c = 0; c < 4; ++c) oacc[i][c] = 0.f;
    float mrow[2] = {-1e30f, -1e30f}, lrow[2] = {0.f, 0.f};
    const float scale = 0.125f;
    const uint32_t bRow  = (lane & 7) + ((lane >> 4) << 3);
    const uint32_t bColB = ((lane >> 3) & 1) << 4;
    const int jc = (lane & 3) * 2;

    const __half* Khb = Kh + ((size_t)(b * HN + h) * TDIM) * DH;
    const __half* Vhb = Vh + ((size_t)b * CDIM + h * DH) * TDIM;

    for (int k0 = 0; k0 < kend; k0 += 64) {
#pragma unroll
        for (int it = 0; it < 2; ++it) {
            const int lin = it * 256 + tid;
            const int row = lin >> 3, qd = lin & 7;
            uint4 a = *(const uint4*)(Khb + (size_t)(k0 + row) * DH + qd * 8);
            uint4 e = *(const uint4*)(Vhb + (size_t)row * TDIM + k0 + qd * 8);
            const uint32_t so = sw128((uint32_t)row * 128 + qd * 16);
            *(uint4*)(sm + so) = a;
            *(uint4*)(sm + 8192 + so) = e;
        }
        __syncthreads();

        float s[8][4];
#pragma unroll
        for (int i = 0; i < 8; ++i)
#pragma unroll
            for (int c = 0; c < 4; ++c) s[i][c] = 0.f;
#pragma unroll
        for (int kk = 0; kk < 4; ++kk) {
            uint32_t bfr[8][2];
#pragma unroll
            for (int np = 0; np < 4; ++np) {
                uint32_t rr[4];
                ldsm4(rr, smu + sw128((np * 16 + bRow) * 128 + kk * 32 + bColB));
                bfr[np * 2 + 0][0] = rr[0]; bfr[np * 2 + 0][1] = rr[1];
                bfr[np * 2 + 1][0] = rr[2]; bfr[np * 2 + 1][1] = rr[3];
            }
#pragma unroll
            for (int nt = 0; nt < 8; ++nt) mma16816(s[nt], qfh[kk], bfr[nt]);
        }

#pragma unroll
        for (int rh = 0; rh < 2; ++rh) {
            float mx = -1e30f;
#pragma unroll
            for (int nt = 0; nt < 8; ++nt) {
                const int jg = k0 + nt * 8 + jc;
                float v0 = (jg     < kend) ? s[nt][rh * 2 + 0] * scale : -1e30f;
                float v1 = (jg + 1 < kend) ? s[nt][rh * 2 + 1] * scale : -1e30f;
                s[nt][rh * 2 + 0] = v0; s[nt][rh * 2 + 1] = v1;
                mx = fmaxf(mx, fmaxf(v0, v1));
            }
            mx = fmaxf(mx, __shfl_xor_sync(0xffffffffu, mx, 1));
            mx = fmaxf(mx, __shfl_xor_sync(0xffffffffu, mx, 2));
            const float mnew = fmaxf(mrow[rh], mx);
            const float fac = __expf(mrow[rh] - mnew);
            mrow[rh] = mnew;
            float sum = 0.f;
#pragma unroll
            for (int nt = 0; nt < 8; ++nt) {
                float p0 = __expf(s[nt][rh * 2 + 0] - mnew);
                float p1 = __expf(s[nt][rh * 2 + 1] - mnew);
                s[nt][rh * 2 + 0] = p0; s[nt][rh * 2 + 1] = p1;
                sum += p0 + p1;
            }
            sum += __shfl_xor_sync(0xffffffffu, sum, 1);
            sum += __shfl_xor_sync(0xffffffffu, sum, 2);
            lrow[rh] = lrow[rh] * fac + sum;
#pragma unroll
            for (int nt = 0; nt < 8; ++nt) {
                oacc[nt][rh * 2 + 0] *= fac;
                oacc[nt][rh * 2 + 1] *= fac;
            }
        }

        uint32_t ph[4][4];
#pragma unroll
        for (int kk2 = 0; kk2 < 4; ++kk2) {
            const int t0 = 2 * kk2, t1 = 2 * kk2 + 1;
            ph[kk2][0] = pack2h(s[t0][0], s[t0][1]);
            ph[kk2][1] = pack2h(s[t0][2], s[t0][3]);
            ph[kk2][2] = pack2h(s[t1][0], s[t1][1]);
            ph[kk2][3] = pack2h(s[t1][2], s[t1][3]);
        }

#pragma unroll
        for (int kk2 = 0; kk2 < 4; ++kk2) {
            uint32_t vfr[8][2];
#pragma unroll
            for (int np = 0; np < 4; ++np) {
                uint32_t rr[4];
                ldsm4(rr, smu + 8192 + sw128((np * 16 + bRow) * 128 + kk2 * 32 + bColB));
                vfr[np * 2 + 0][0] = rr[0]; vfr[np * 2 + 0][1] = rr[1];
                vfr[np * 2 + 1][0] = rr[2]; vfr[np * 2 + 1][1] = rr[3];
            }
#pragma unroll
            for (int nt = 0; nt < 8; ++nt) mma16816(oacc[nt], ph[kk2], vfr[nt]);
        }
        __syncthreads();
    }

#pragma unroll
    for (int rh = 0; rh < 2; ++rh) {
        const int q = q0 + wid * 16 + (lane >> 2) + rh * 8;
        const float inv = (lrow[rh] > 0.f) ? (1.f / lrow[rh]) : 0.f;
        const size_t base = ((size_t)b * TDIM + q) * CDIM + h * DH;
#pragma unroll
        for (int nt = 0; nt < 8; ++nt) {
            const int d = nt * 8 + jc;
            uint32_t hi, lo;
            split2h(oacc[nt][rh * 2 + 0] * inv, oacc[nt][rh * 2 + 1] * inv, hi, lo);
            *(uint32_t*)&Oh[base + d] = hi;
            *(uint32_t*)&Ol[base + d] = lo;
        }
    }
}

// ---------------------------------------------------------------------------
__global__ void zero_kernel(float4* __restrict__ p, int n4)
{
    int i = blockIdx.x * blockDim.x + threadIdx.x;
    if (i < n4) p[i] = make_float4(0.f, 0.f, 0.f, 0.f);
}

__global__ void write_mask_kernel(const unsigned* __restrict__ mask,
                                  float* __restrict__ out, int n)
{
    int i = blockIdx.x * blockDim.x + threadIdx.x;
    if (i < n) out[i] = mask[i] ? 1.0f : 0.0f;
}

// ---------------------------------------------------------------------------
extern "C" void kernel_launch(void* const* d_in, const int* in_sizes, int n_in,
                              void* d_out, int out_size)
{
    const float*    x    = (const float*)d_in[0];
    const unsigned* mask = (const unsigned*)d_in[1];
    const float*    Wq   = (const float*)d_in[2];
    const float*    bq   = (const float*)d_in[3];
    const float*    Wk   = (const float*)d_in[4];
    const float*    bk   = (const float*)d_in[5];
    const float*    Wv   = (const float*)d_in[6];
    const float*    bv   = (const float*)d_in[7];
    const float*    Wp   = (const float*)d_in[8];
    const float*    bp   = (const float*)d_in[9];
    float* out = (float*)d_out;

    __half *wh, *xh, *ah, *al, *qh, *kh, *vh;
    int *gidx, *gcnt;
    cudaGetSymbolAddress((void**)&wh,   g_Wh);
    cudaGetSymbolAddress((void**)&xh,   g_xTh);
    cudaGetSymbolAddress((void**)&ah,   g_aTh);
    cudaGetSymbolAddress((void**)&al,   g_aTl);
    cudaGetSymbolAddress((void**)&qh,   g_qh);
    cudaGetSymbolAddress((void**)&kh,   g_kh);
    cudaGetSymbolAddress((void**)&vh,   g_vh);
    cudaGetSymbolAddress((void**)&gidx, g_idx);
    cudaGetSymbolAddress((void**)&gcnt, g_cnt);

    static int smem_set = 0;
    if (!smem_set) {
        cudaFuncSetAttribute(mma_gemm, cudaFuncAttributeMaxDynamicSharedMemorySize, 65536);
        smem_set = 1;
    }

    compact_kernel<<<BSZ, 256>>>(mask, gidx, gcnt);

    const int n4 = BSZ * CDIM * TDIM / 4;
    zero_kernel<<<(n4 + 255) / 256, 256>>>((float4*)out, n4);

    split_w4_kernel<<<4 * CDIM * CDIM / 256, 256>>>(Wq, Wk, Wv, Wp, wh);

    dim3 gt(TDIM / 32, CDIM / 32, BSZ);
    gather_transpose<<<gt, dim3(32, 8)>>>(x, gidx, gcnt, xh);

    const size_t WN = (size_t)CDIM * CDIM;
    dim3 gqkv(TDIM / 128, 24, BSZ);
    mma_gemm<<<gqkv, 256, 65536>>>(wh, xh, nullptr, bq, bk, bv,
                                   nullptr, qh, kh, vh, gcnt, gidx, 1);

    dim3 ga(TDIM / 128, HN, BSZ);
    attn_mma<<<ga, 256>>>(qh, kh, vh, gcnt, ah, al);

    dim3 gp(TDIM / 128, CDIM / 128, BSZ);
    mma_gemm<<<gp, 256, 65536>>>(wh + 3 * WN, ah, al, bp, nullptr, nullptr,
                                 out, nullptr, nullptr, nullptr,
                                 gcnt, gidx, 0);

    const long long nout = (long long)BSZ * CDIM * TDIM;
    const int tail = out_size - (int)nout;
    if (tail >= BSZ * TDIM) {
        write_mask_kernel<<<(BSZ * TDIM + 255) / 256, 256>>>(
            mask, out + nout, BSZ * TDIM);
    }
}

// round 11
// speedup vs baseline: 8.6028x; 1.1594x over previous
#include <cuda_runtime.h>
#include <cuda_fp16.h>
#include <stdint.h>

#define BSZ  2
#define CDIM 1024
#define TDIM 2048
#define HN   16
#define DH   64

// ---------------- scratch (static device globals) ----------------
__device__ __half g_Wh [(size_t)4 * CDIM * CDIM];     // [Wq;Wk;Wv;Wp] fp16
__device__ __half g_xTh[(size_t)BSZ * TDIM * CDIM];   // (B, Tc, C) fp16
__device__ __half g_qh [(size_t)BSZ * HN * TDIM * DH]; // (B,H,Tc,D)
__device__ __half g_kh [(size_t)BSZ * HN * TDIM * DH];
__device__ __half g_vh [(size_t)BSZ * CDIM * TDIM];    // (B, C, Tc)
__device__ __half g_aTh[(size_t)BSZ * TDIM * CDIM];    // attn out (B, Tc, C)
__device__ int g_idx[BSZ * TDIM];
__device__ int g_cnt[BSZ];

// ---------------- helpers ----------------
__device__ __forceinline__ uint32_t smem_u32(const void* p) {
    uint32_t a;
    asm("{ .reg .u64 t; cvta.to.shared.u64 t, %1; cvt.u32.u64 %0, t; }" : "=r"(a) : "l"(p));
    return a;
}
__device__ __forceinline__ uint32_t sw128(uint32_t off) { return off ^ ((off >> 3) & 0x70); }

__device__ __forceinline__ void ldsm4(uint32_t* r, uint32_t addr) {
    asm volatile("ldmatrix.sync.aligned.m8n8.x4.shared.b16 {%0,%1,%2,%3}, [%4];"
        : "=r"(r[0]), "=r"(r[1]), "=r"(r[2]), "=r"(r[3]) : "r"(addr));
}
__device__ __forceinline__ void mma16816(float* c, const uint32_t* a, const uint32_t* b) {
    asm volatile("mma.sync.aligned.m16n8k16.row.col.f32.f16.f16.f32 "
        "{%0,%1,%2,%3}, {%4,%5,%6,%7}, {%8,%9}, {%0,%1,%2,%3};"
        : "+f"(c[0]), "+f"(c[1]), "+f"(c[2]), "+f"(c[3])
        : "r"(a[0]), "r"(a[1]), "r"(a[2]), "r"(a[3]), "r"(b[0]), "r"(b[1]));
}
__device__ __forceinline__ uint32_t pack2h(float v0, float v1) {
    return (uint32_t)__half_as_ushort(__float2half(v0)) |
           ((uint32_t)__half_as_ushort(__float2half(v1)) << 16);
}
__device__ __forceinline__ void cpasync16(uint32_t dst, const void* src) {
    asm volatile("cp.async.cg.shared.global [%0], [%1], 16;" :: "r"(dst), "l"(src));
}
#define CP_COMMIT() asm volatile("cp.async.commit_group;" ::: "memory")
#define CP_WAIT0()  asm volatile("cp.async.wait_group 0;" ::: "memory")
#define CP_WAIT1()  asm volatile("cp.async.wait_group 1;" ::: "memory")

// ---------------------------------------------------------------------------
__global__ __launch_bounds__(256)
void compact_kernel(const unsigned* __restrict__ mask, int* __restrict__ idx,
                    int* __restrict__ cnt)
{
    __shared__ int wsum[8];
    __shared__ int wexcl[8];
    const int b = blockIdx.x;
    const unsigned* mb = mask + (size_t)b * TDIM;
    int* ib = idx + (size_t)b * TDIM;
    const int tid  = threadIdx.x;
    const int lane = tid & 31, w = tid >> 5;
    unsigned v[8]; int c = 0;
#pragma unroll
    for (int i = 0; i < 8; ++i) { v[i] = mb[tid * 8 + i]; c += v[i] ? 1 : 0; }
    int inc = c;
#pragma unroll
    for (int off = 1; off < 32; off <<= 1) {
        int n = __shfl_up_sync(0xffffffffu, inc, off);
        if (lane >= off) inc += n;
    }
    if (lane == 31) wsum[w] = inc;
    __syncthreads();
    if (tid == 0) {
        int s = 0;
#pragma unroll
        for (int i = 0; i < 8; ++i) { wexcl[i] = s; s += wsum[i]; }
        cnt[b] = s;
    }
    __syncthreads();
    int p = wexcl[w] + inc - c;
#pragma unroll
    for (int i = 0; i < 8; ++i) if (v[i]) ib[p++] = tid * 8 + i;
}

// ---------------------------------------------------------------------------
// Gather + transpose: x (B,C,T) -> (B, Tc, C) fp16.
// ---------------------------------------------------------------------------
__global__ __launch_bounds__(256)
void gather_transpose(const float* __restrict__ src,
                      const int* __restrict__ idx, const int* __restrict__ cnt,
                      __half* __restrict__ dh)
{
    __shared__ float tile[32][33];
    __shared__ int tloc[32];
    const int b = blockIdx.z;
    const int n = cnt[b];
    const int i0 = blockIdx.x * 32;
    if (i0 >= n) return;
    const int c0 = blockIdx.y * 32;
    const float* s = src + (size_t)b * CDIM * TDIM;
    __half* ph = dh + (size_t)b * TDIM * CDIM;
    const int tx = threadIdx.x, ty = threadIdx.y;
    if (ty == 0) tloc[tx] = (i0 + tx < n) ? idx[b * TDIM + i0 + tx] : -1;
    __syncthreads();
    const int t = tloc[tx];
#pragma unroll
    for (int i = 0; i < 4; ++i)
        tile[ty + i * 8][tx] = (t >= 0) ? s[(size_t)(c0 + ty + i * 8) * TDIM + t] : 0.f;
    __syncthreads();
#pragma unroll
    for (int i = 0; i < 4; ++i) {
        const int irow = i0 + ty + i * 8;
        if (irow < n)
            ph[(size_t)irow * CDIM + c0 + tx] = __float2half(tile[tx][ty + i * 8]);
    }
}

// ---------------------------------------------------------------------------
// fp16 single-pass GEMM, BK=64, double-buffered cp.async (2 x 32KB stages).
// fusedQKV=1: A rows 0..3071 = [Wq;Wk;Wv]; outputs Q/K (B,H,Tc,D), V (B,C,Tc).
// fusedQKV=0: P-proj; scatter fp32 through idx into (C,T) (out pre-zeroed).
// Thread map: tid 0..127 load A rows, 128..255 load B rows (128B each).
// ---------------------------------------------------------------------------
extern __shared__ unsigned char dynsm[];

__global__ __launch_bounds__(256, 2)
void mma_gemm(const __half* __restrict__ Ah, const __half* __restrict__ Bh,
              const float* __restrict__ b0, const float* __restrict__ b1,
              const float* __restrict__ b2, float* __restrict__ Cout,
              __half* __restrict__ Qh, __half* __restrict__ Kh, __half* __restrict__ Vh,
              const int* __restrict__ cnt, const int* __restrict__ idx, int fusedQKV)
{
    __shared__ int sidx[128];

    const int b    = blockIdx.z;
    const int nlim = cnt[b];
    const int n0   = blockIdx.x * 128;
    if (n0 >= nlim) return;
    const int m0   = blockIdx.y * 128;
    const int tid  = threadIdx.x;
    const int wid  = tid >> 5;
    const int lane = tid & 31;
    const int wy   = wid & 1;
    const int wx   = wid >> 1;

    const uint32_t smu = smem_u32(dynsm);

    const int r   = tid & 127;
    const int isB = tid >> 7;
    const __half* Bhb = Bh + (size_t)b * TDIM * CDIM;
    const __half* srcP = isB ? (Bhb + (size_t)(n0 + r) * CDIM)
                             : (Ah + (size_t)(m0 + r) * CDIM);
    const uint32_t regOff = (uint32_t)isB * 16384u;
    uint32_t so[8];
#pragma unroll
    for (int i = 0; i < 8; ++i) so[i] = regOff + sw128((uint32_t)r * 128u + i * 16u);

    float acc[4][4][4];
#pragma unroll
    for (int i = 0; i < 4; ++i)
#pragma unroll
        for (int j = 0; j < 4; ++j)
#pragma unroll
            for (int c = 0; c < 4; ++c) acc[i][j][c] = 0.f;

    const uint32_t aRow = (uint32_t)(wy * 64 + (lane & 15));
    const uint32_t aCol = (uint32_t)((lane >> 4) << 4);
    const uint32_t bRow = (uint32_t)(wx * 32 + (lane & 7) + ((lane >> 4) << 3));
    const uint32_t bCol = (uint32_t)(((lane >> 3) & 1) << 4);

    // prologue: stage 0 (k 0..63)
    {
#pragma unroll
        for (int i = 0; i < 8; ++i)
            cpasync16(smu + so[i], srcP + i * 8);
        CP_COMMIT();
    }

    for (int kb = 0; kb < 16; ++kb) {
        const uint32_t stg = (uint32_t)(kb & 1) * 32768u;
        if (kb < 15) {
            const uint32_t nst = (uint32_t)((kb + 1) & 1) * 32768u;
            const int k1 = (kb + 1) * 64;
#pragma unroll
            for (int i = 0; i < 8; ++i)
                cpasync16(smu + nst + so[i], srcP + k1 + i * 8);
            CP_COMMIT();
            CP_WAIT1();
        } else {
            CP_WAIT0();
        }
        __syncthreads();

        const uint32_t smA_u = smu + stg;
        const uint32_t smB_u = smu + stg + 16384;
#pragma unroll
        for (int s = 0; s < 4; ++s) {
            const uint32_t ksA = s * 32;      // 16 k per step (32 bytes)
            uint32_t afr[4][4], bfr[4][2];
#pragma unroll
            for (int mt = 0; mt < 4; ++mt)
                ldsm4(afr[mt], smA_u + sw128((aRow + mt * 16) * 128 + ksA + aCol));
#pragma unroll
            for (int np = 0; np < 2; ++np) {
                uint32_t rr[4];
                ldsm4(rr, smB_u + sw128((bRow + np * 16) * 128 + ksA + bCol));
                bfr[np * 2 + 0][0] = rr[0]; bfr[np * 2 + 0][1] = rr[1];
                bfr[np * 2 + 1][0] = rr[2]; bfr[np * 2 + 1][1] = rr[3];
            }
#pragma unroll
            for (int mt = 0; mt < 4; ++mt)
#pragma unroll
                for (int nt = 0; nt < 4; ++nt)
                    mma16816(acc[mt][nt], afr[mt], bfr[nt]);
        }
        __syncthreads();
    }

    // ---- epilogue ----
    const int sector = m0 >> 10;
    const int mbase  = m0 & 1023;
    const float* bptr = fusedQKV ? (sector == 0 ? b0 : (sector == 1 ? b1 : b2)) : b0;

    if (!fusedQKV) {
        if (tid < 128) sidx[tid] = (n0 + tid < nlim) ? idx[b * TDIM + n0 + tid] : -1;
        __syncthreads();
    }

    const int qrow = lane >> 2;
    const int qcol = (lane & 3) * 2;
#pragma unroll
    for (int mt = 0; mt < 4; ++mt) {
#pragma unroll
        for (int rh = 0; rh < 2; ++rh) {
            const int rloc = mbase + wy * 64 + mt * 16 + qrow + rh * 8;
            const float bi = bptr[rloc];
#pragma unroll
            for (int nt = 0; nt < 4; ++nt) {
                const int col = n0 + wx * 32 + nt * 8 + qcol;
                float v0 = acc[mt][nt][rh * 2 + 0] + bi;
                float v1 = acc[mt][nt][rh * 2 + 1] + bi;
                if (!fusedQKV) {
                    float* dst = Cout + (size_t)b * CDIM * TDIM + (size_t)rloc * TDIM;
                    const int t0 = sidx[col - n0 + 0];
                    const int t1 = sidx[col - n0 + 1];
                    if (t0 >= 0) dst[t0] = v0;
                    if (t1 >= 0) dst[t1] = v1;
                } else if (sector < 2) {
                    __half* oh = sector ? Kh : Qh;
                    const int hh = rloc >> 6, dd = rloc & 63;
                    const size_t a0 = ((size_t)(b * HN + hh) * TDIM + col) * DH + dd;
                    oh[a0]      = __float2half(v0);
                    oh[a0 + DH] = __float2half(v1);
                } else {
                    const size_t a0 = ((size_t)b * CDIM + rloc) * TDIM + col;
                    *(uint32_t*)&Vh[a0] = pack2h(v0, v1);
                }
            }
        }
    }
}

// ---------------------------------------------------------------------------
__global__ __launch_bounds__(256)
void split_w4_kernel(const float* __restrict__ w0, const float* __restrict__ w1,
                     const float* __restrict__ w2, const float* __restrict__ w3,
                     __half* __restrict__ hi)
{
    const unsigned i = blockIdx.x * 256u + threadIdx.x;
    const int sel = i >> 20;
    const float* w = (sel == 0) ? w0 : (sel == 1) ? w1 : (sel == 2) ? w2 : w3;
    hi[i] = __float2half(w[i & 0xFFFFFu]);
}

// ---------------------------------------------------------------------------
// fp16 single-pass flash attention: S = Qh·Kh, O = Ph·Vh.
// Output fp16 hi only (B, Tc, C).
// ---------------------------------------------------------------------------
__global__ __launch_bounds__(256, 2)
void attn_mma(const __half* __restrict__ Qh, const __half* __restrict__ Kh,
              const __half* __restrict__ Vh, const int* __restrict__ cnt,
              __half* __restrict__ Oh)
{
    __shared__ __align__(1024) unsigned char sm[24576];
    const int b = blockIdx.z, h = blockIdx.y;
    const int kend = cnt[b];
    const int q0 = blockIdx.x * 128;
    if (q0 >= kend) return;
    const int tid = threadIdx.x, wid = tid >> 5, lane = tid & 31;
    const uint32_t smu = smem_u32(sm);

    const __half* Qhb = Qh + ((size_t)(b * HN + h) * TDIM + q0) * DH;
#pragma unroll
    for (int it = 0; it < 4; ++it) {
        const int lin = it * 256 + tid;
        const int row = lin >> 3, qd = lin & 7;
        uint4 a = *(const uint4*)(Qhb + (size_t)row * DH + qd * 8);
        *(uint4*)(sm + sw128((uint32_t)row * 128 + qd * 16)) = a;
    }
    __syncthreads();
    uint32_t qfh[4][4];
    {
        const uint32_t aRow = wid * 16 + (lane & 15);
        const uint32_t aColB = (lane >> 4) << 4;
#pragma unroll
        for (int kk = 0; kk < 4; ++kk)
            ldsm4(qfh[kk], smu + sw128(aRow * 128 + kk * 32 + aColB));
    }
    __syncthreads();

    float oacc[8][4];
#pragma unroll
    for (int i = 0; i < 8; ++i)
#pragma unroll
        for (int c = 0; c < 4; ++c) oacc[i][c] = 0.f;
    float mrow[2] = {-1e30f, -1e30f}, lrow[2] = {0.f, 0.f};
    const float scale = 0.125f;
    const uint32_t bRow  = (lane & 7) + ((lane >> 4) << 3);
    const uint32_t bColB = ((lane >> 3) & 1) << 4;
    const int jc = (lane & 3) * 2;

    const __half* Khb = Kh + ((size_t)(b * HN + h) * TDIM) * DH;
    const __half* Vhb = Vh + ((size_t)b * CDIM + h * DH) * TDIM;

    for (int k0 = 0; k0 < kend; k0 += 64) {
#pragma unroll
        for (int it = 0; it < 2; ++it) {
            const int lin = it * 256 + tid;
            const int row = lin >> 3, qd = lin & 7;
            uint4 a = *(const uint4*)(Khb + (size_t)(k0 + row) * DH + qd * 8);
            uint4 e = *(const uint4*)(Vhb + (size_t)row * TDIM + k0 + qd * 8);
            const uint32_t so = sw128((uint32_t)row * 128 + qd * 16);
            *(uint4*)(sm + so) = a;
            *(uint4*)(sm + 8192 + so) = e;
        }
        __syncthreads();

        float s[8][4];
#pragma unroll
        for (int i = 0; i < 8; ++i)
#pragma unroll
            for (int c = 0; c < 4; ++c) s[i][c] = 0.f;
#pragma unroll
        for (int kk = 0; kk < 4; ++kk) {
            uint32_t bfr[8][2];
#pragma unroll
            for (int np = 0; np < 4; ++np) {
                uint32_t rr[4];
                ldsm4(rr, smu + sw128((np * 16 + bRow) * 128 + kk * 32 + bColB));
                bfr[np * 2 + 0][0] = rr[0]; bfr[np * 2 + 0][1] = rr[1];
                bfr[np * 2 + 1][0] = rr[2]; bfr[np * 2 + 1][1] = rr[3];
            }
#pragma unroll
            for (int nt = 0; nt < 8; ++nt) mma16816(s[nt], qfh[kk], bfr[nt]);
        }

#pragma unroll
        for (int rh = 0; rh < 2; ++rh) {
            float mx = -1e30f;
#pragma unroll
            for (int nt = 0; nt < 8; ++nt) {
                const int jg = k0 + nt * 8 + jc;
                float v0 = (jg     < kend) ? s[nt][rh * 2 + 0] * scale : -1e30f;
                float v1 = (jg + 1 < kend) ? s[nt][rh * 2 + 1] * scale : -1e30f;
                s[nt][rh * 2 + 0] = v0; s[nt][rh * 2 + 1] = v1;
                mx = fmaxf(mx, fmaxf(v0, v1));
            }
            mx = fmaxf(mx, __shfl_xor_sync(0xffffffffu, mx, 1));
            mx = fmaxf(mx, __shfl_xor_sync(0xffffffffu, mx, 2));
            const float mnew = fmaxf(mrow[rh], mx);
            const float fac = __expf(mrow[rh] - mnew);
            mrow[rh] = mnew;
            float sum = 0.f;
#pragma unroll
            for (int nt = 0; nt < 8; ++nt) {
                float p0 = __expf(s[nt][rh * 2 + 0] - mnew);
                float p1 = __expf(s[nt][rh * 2 + 1] - mnew);
                s[nt][rh * 2 + 0] = p0; s[nt][rh * 2 + 1] = p1;
                sum += p0 + p1;
            }
            sum += __shfl_xor_sync(0xffffffffu, sum, 1);
            sum += __shfl_xor_sync(0xffffffffu, sum, 2);
            lrow[rh] = lrow[rh] * fac + sum;
#pragma unroll
            for (int nt = 0; nt < 8; ++nt) {
                oacc[nt][rh * 2 + 0] *= fac;
                oacc[nt][rh * 2 + 1] *= fac;
            }
        }

        uint32_t ph[4][4];
#pragma unroll
        for (int kk2 = 0; kk2 < 4; ++kk2) {
            const int t0 = 2 * kk2, t1 = 2 * kk2 + 1;
            ph[kk2][0] = pack2h(s[t0][0], s[t0][1]);
            ph[kk2][1] = pack2h(s[t0][2], s[t0][3]);
            ph[kk2][2] = pack2h(s[t1][0], s[t1][1]);
            ph[kk2][3] = pack2h(s[t1][2], s[t1][3]);
        }

#pragma unroll
        for (int kk2 = 0; kk2 < 4; ++kk2) {
            uint32_t vfr[8][2];
#pragma unroll
            for (int np = 0; np < 4; ++np) {
                uint32_t rr[4];
                ldsm4(rr, smu + 8192 + sw128((np * 16 + bRow) * 128 + kk2 * 32 + bColB));
                vfr[np * 2 + 0][0] = rr[0]; vfr[np * 2 + 0][1] = rr[1];
                vfr[np * 2 + 1][0] = rr[2]; vfr[np * 2 + 1][1] = rr[3];
            }
#pragma unroll
            for (int nt = 0; nt < 8; ++nt) mma16816(oacc[nt], ph[kk2], vfr[nt]);
        }
        __syncthreads();
    }

#pragma unroll
    for (int rh = 0; rh < 2; ++rh) {
        const int q = q0 + wid * 16 + (lane >> 2) + rh * 8;
        const float inv = (lrow[rh] > 0.f) ? (1.f / lrow[rh]) : 0.f;
        const size_t base = ((size_t)b * TDIM + q) * CDIM + h * DH;
#pragma unroll
        for (int nt = 0; nt < 8; ++nt) {
            const int d = nt * 8 + jc;
            *(uint32_t*)&Oh[base + d] =
                pack2h(oacc[nt][rh * 2 + 0] * inv, oacc[nt][rh * 2 + 1] * inv);
        }
    }
}

// ---------------------------------------------------------------------------
__global__ void zero_kernel(float4* __restrict__ p, int n4)
{
    int i = blockIdx.x * blockDim.x + threadIdx.x;
    if (i < n4) p[i] = make_float4(0.f, 0.f, 0.f, 0.f);
}

__global__ void write_mask_kernel(const unsigned* __restrict__ mask,
                                  float* __restrict__ out, int n)
{
    int i = blockIdx.x * blockDim.x + threadIdx.x;
    if (i < n) out[i] = mask[i] ? 1.0f : 0.0f;
}

// ---------------------------------------------------------------------------
extern "C" void kernel_launch(void* const* d_in, const int* in_sizes, int n_in,
                              void* d_out, int out_size)
{
    const float*    x    = (const float*)d_in[0];
    const unsigned* mask = (const unsigned*)d_in[1];
    const float*    Wq   = (const float*)d_in[2];
    const float*    bq   = (const float*)d_in[3];
    const float*    Wk   = (const float*)d_in[4];
    const float*    bk   = (const float*)d_in[5];
    const float*    Wv   = (const float*)d_in[6];
    const float*    bv   = (const float*)d_in[7];
    const float*    Wp   = (const float*)d_in[8];
    const float*    bp   = (const float*)d_in[9];
    float* out = (float*)d_out;

    __half *wh, *xh, *ah, *qh, *kh, *vh;
    int *gidx, *gcnt;
    cudaGetSymbolAddress((void**)&wh,   g_Wh);
    cudaGetSymbolAddress((void**)&xh,   g_xTh);
    cudaGetSymbolAddress((void**)&ah,   g_aTh);
    cudaGetSymbolAddress((void**)&qh,   g_qh);
    cudaGetSymbolAddress((void**)&kh,   g_kh);
    cudaGetSymbolAddress((void**)&vh,   g_vh);
    cudaGetSymbolAddress((void**)&gidx, g_idx);
    cudaGetSymbolAddress((void**)&gcnt, g_cnt);

    static int smem_set = 0;
    if (!smem_set) {
        cudaFuncSetAttribute(mma_gemm, cudaFuncAttributeMaxDynamicSharedMemorySize, 65536);
        smem_set = 1;
    }

    compact_kernel<<<BSZ, 256>>>(mask, gidx, gcnt);

    const int n4 = BSZ * CDIM * TDIM / 4;
    zero_kernel<<<(n4 + 255) / 256, 256>>>((float4*)out, n4);

    split_w4_kernel<<<4 * CDIM * CDIM / 256, 256>>>(Wq, Wk, Wv, Wp, wh);

    dim3 gt(TDIM / 32, CDIM / 32, BSZ);
    gather_transpose<<<gt, dim3(32, 8)>>>(x, gidx, gcnt, xh);

    const size_t WN = (size_t)CDIM * CDIM;
    dim3 gqkv(TDIM / 128, 24, BSZ);
    mma_gemm<<<gqkv, 256, 65536>>>(wh, xh, bq, bk, bv,
                                   nullptr, qh, kh, vh, gcnt, gidx, 1);

    dim3 ga(TDIM / 128, HN, BSZ);
    attn_mma<<<ga, 256>>>(qh, kh, vh, gcnt, ah);

    dim3 gp(TDIM / 128, CDIM / 128, BSZ);
    mma_gemm<<<gp, 256, 65536>>>(wh + 3 * WN, ah, bp, nullptr, nullptr,
                                 out, nullptr, nullptr, nullptr,
                                 gcnt, gidx, 0);

    const long long nout = (long long)BSZ * CDIM * TDIM;
    const int tail = out_size - (int)nout;
    if (tail >= BSZ * TDIM) {
        write_mask_kernel<<<(BSZ * TDIM + 255) / 256, 256>>>(
            mask, out + nout, BSZ * TDIM);
    }
}

// round 12
// speedup vs baseline: 8.9027x; 1.0349x over previous
#include <cuda_runtime.h>
#include <cuda_fp16.h>
#include <stdint.h>

#define BSZ  2
#define CDIM 1024
#define TDIM 2048
#define HN   16
#define DH   64

// ---------------- scratch (static device globals) ----------------
__device__ __half g_Wh [(size_t)4 * CDIM * CDIM];     // [Wq;Wk;Wv;Wp] fp16
__device__ __half g_xTh[(size_t)BSZ * TDIM * CDIM];   // (B, Tc, C) fp16
__device__ __half g_qh [(size_t)BSZ * HN * TDIM * DH]; // (B,H,Tc,D)
__device__ __half g_kh [(size_t)BSZ * HN * TDIM * DH];
__device__ __half g_vh [(size_t)BSZ * CDIM * TDIM];    // (B, C, Tc)
__device__ __half g_aTh[(size_t)BSZ * TDIM * CDIM];    // attn out (B, Tc, C)
__device__ int g_idx[BSZ * TDIM];
__device__ int g_cnt[BSZ];

// ---------------- helpers ----------------
__device__ __forceinline__ uint32_t smem_u32(const void* p) {
    uint32_t a;
    asm("{ .reg .u64 t; cvta.to.shared.u64 t, %1; cvt.u32.u64 %0, t; }" : "=r"(a) : "l"(p));
    return a;
}
__device__ __forceinline__ uint32_t sw128(uint32_t off) { return off ^ ((off >> 3) & 0x70); }

__device__ __forceinline__ void ldsm4(uint32_t* r, uint32_t addr) {
    asm volatile("ldmatrix.sync.aligned.m8n8.x4.shared.b16 {%0,%1,%2,%3}, [%4];"
        : "=r"(r[0]), "=r"(r[1]), "=r"(r[2]), "=r"(r[3]) : "r"(addr));
}
__device__ __forceinline__ void mma16816(float* c, const uint32_t* a, const uint32_t* b) {
    asm volatile("mma.sync.aligned.m16n8k16.row.col.f32.f16.f16.f32 "
        "{%0,%1,%2,%3}, {%4,%5,%6,%7}, {%8,%9}, {%0,%1,%2,%3};"
        : "+f"(c[0]), "+f"(c[1]), "+f"(c[2]), "+f"(c[3])
        : "r"(a[0]), "r"(a[1]), "r"(a[2]), "r"(a[3]), "r"(b[0]), "r"(b[1]));
}
__device__ __forceinline__ uint32_t pack2h(float v0, float v1) {
    return (uint32_t)__half_as_ushort(__float2half(v0)) |
           ((uint32_t)__half_as_ushort(__float2half(v1)) << 16);
}
__device__ __forceinline__ void cpasync16(uint32_t dst, const void* src) {
    asm volatile("cp.async.cg.shared.global [%0], [%1], 16;" :: "r"(dst), "l"(src));
}
#define CP_COMMIT() asm volatile("cp.async.commit_group;" ::: "memory")
#define CP_WAIT0()  asm volatile("cp.async.wait_group 0;" ::: "memory")
#define CP_WAIT1()  asm volatile("cp.async.wait_group 1;" ::: "memory")

// ---------------------------------------------------------------------------
__global__ __launch_bounds__(256)
void compact_kernel(const unsigned* __restrict__ mask, int* __restrict__ idx,
                    int* __restrict__ cnt)
{
    __shared__ int wsum[8];
    __shared__ int wexcl[8];
    const int b = blockIdx.x;
    const unsigned* mb = mask + (size_t)b * TDIM;
    int* ib = idx + (size_t)b * TDIM;
    const int tid  = threadIdx.x;
    const int lane = tid & 31, w = tid >> 5;
    unsigned v[8]; int c = 0;
#pragma unroll
    for (int i = 0; i < 8; ++i) { v[i] = mb[tid * 8 + i]; c += v[i] ? 1 : 0; }
    int inc = c;
#pragma unroll
    for (int off = 1; off < 32; off <<= 1) {
        int n = __shfl_up_sync(0xffffffffu, inc, off);
        if (lane >= off) inc += n;
    }
    if (lane == 31) wsum[w] = inc;
    __syncthreads();
    if (tid == 0) {
        int s = 0;
#pragma unroll
        for (int i = 0; i < 8; ++i) { wexcl[i] = s; s += wsum[i]; }
        cnt[b] = s;
    }
    __syncthreads();
    int p = wexcl[w] + inc - c;
#pragma unroll
    for (int i = 0; i < 8; ++i) if (v[i]) ib[p++] = tid * 8 + i;
}

// ---------------------------------------------------------------------------
__global__ __launch_bounds__(256)
void gather_transpose(const float* __restrict__ src,
                      const int* __restrict__ idx, const int* __restrict__ cnt,
                      __half* __restrict__ dh)
{
    __shared__ float tile[32][33];
    __shared__ int tloc[32];
    const int b = blockIdx.z;
    const int n = cnt[b];
    const int i0 = blockIdx.x * 32;
    if (i0 >= n) return;
    const int c0 = blockIdx.y * 32;
    const float* s = src + (size_t)b * CDIM * TDIM;
    __half* ph = dh + (size_t)b * TDIM * CDIM;
    const int tx = threadIdx.x, ty = threadIdx.y;
    if (ty == 0) tloc[tx] = (i0 + tx < n) ? idx[b * TDIM + i0 + tx] : -1;
    __syncthreads();
    const int t = tloc[tx];
#pragma unroll
    for (int i = 0; i < 4; ++i)
        tile[ty + i * 8][tx] = (t >= 0) ? s[(size_t)(c0 + ty + i * 8) * TDIM + t] : 0.f;
    __syncthreads();
#pragma unroll
    for (int i = 0; i < 4; ++i) {
        const int irow = i0 + ty + i * 8;
        if (irow < n)
            ph[(size_t)irow * CDIM + c0 + tx] = __float2half(tile[tx][ty + i * 8]);
    }
}

// ---------------------------------------------------------------------------
// fp16 GEMM, BK=64, 3-stage cp.async pipeline, 1 barrier per k-iteration.
// fusedQKV=1: A rows 0..3071 = [Wq;Wk;Wv]; outputs Q/K (B,H,Tc,D), V (B,C,Tc).
// fusedQKV=0: P-proj; scatter fp32 through idx into (C,T) (out pre-zeroed).
// Dynamic smem: 3 x 32KB stages (A 16KB | B 16KB each).
// ---------------------------------------------------------------------------
extern __shared__ unsigned char dynsm[];

__global__ __launch_bounds__(256, 2)
void mma_gemm(const __half* __restrict__ Ah, const __half* __restrict__ Bh,
              const float* __restrict__ b0, const float* __restrict__ b1,
              const float* __restrict__ b2, float* __restrict__ Cout,
              __half* __restrict__ Qh, __half* __restrict__ Kh, __half* __restrict__ Vh,
              const int* __restrict__ cnt, const int* __restrict__ idx, int fusedQKV)
{
    __shared__ int sidx[128];

    const int b    = blockIdx.z;
    const int nlim = cnt[b];
    const int n0   = blockIdx.x * 128;
    if (n0 >= nlim) return;
    const int m0   = blockIdx.y * 128;
    const int tid  = threadIdx.x;
    const int wid  = tid >> 5;
    const int lane = tid & 31;
    const int wy   = wid & 1;
    const int wx   = wid >> 1;

    const uint32_t smu = smem_u32(dynsm);

    const int r   = tid & 127;
    const int isB = tid >> 7;
    const __half* Bhb = Bh + (size_t)b * TDIM * CDIM;
    const __half* srcP = isB ? (Bhb + (size_t)(n0 + r) * CDIM)
                             : (Ah + (size_t)(m0 + r) * CDIM);
    const uint32_t regOff = (uint32_t)isB * 16384u;
    uint32_t so[8];
#pragma unroll
    for (int i = 0; i < 8; ++i) so[i] = regOff + sw128((uint32_t)r * 128u + i * 16u);

    float acc[4][4][4];
#pragma unroll
    for (int i = 0; i < 4; ++i)
#pragma unroll
        for (int j = 0; j < 4; ++j)
#pragma unroll
            for (int c = 0; c < 4; ++c) acc[i][j][c] = 0.f;

    const uint32_t aRow = (uint32_t)(wy * 64 + (lane & 15));
    const uint32_t aCol = (uint32_t)((lane >> 4) << 4);
    const uint32_t bRow = (uint32_t)(wx * 32 + (lane & 7) + ((lane >> 4) << 3));
    const uint32_t bCol = (uint32_t)(((lane >> 3) & 1) << 4);

    // prologue: stages 0 and 1 (k 0..63, 64..127)
    {
#pragma unroll
        for (int i = 0; i < 8; ++i)
            cpasync16(smu + so[i], srcP + i * 8);
        CP_COMMIT();
#pragma unroll
        for (int i = 0; i < 8; ++i)
            cpasync16(smu + 32768u + so[i], srcP + 64 + i * 8);
        CP_COMMIT();
    }

    uint32_t stg = 0;                // stage byte offset of current k-block
    uint32_t nst = 2 * 32768u;       // stage to fill next (kb+2)
    for (int kb = 0; kb < 16; ++kb) {
        if (kb < 15) { CP_WAIT1(); } else { CP_WAIT0(); }
        __syncthreads();             // all warps done with stage (kb-1) == nst target
        if (kb + 2 < 16) {
            const int k2 = (kb + 2) * 64;
#pragma unroll
            for (int i = 0; i < 8; ++i)
                cpasync16(smu + nst + so[i], srcP + k2 + i * 8);
            CP_COMMIT();
        }

        const uint32_t smA_u = smu + stg;
        const uint32_t smB_u = smu + stg + 16384;
#pragma unroll
        for (int s = 0; s < 4; ++s) {
            const uint32_t ksA = s * 32;
            uint32_t afr[4][4], bfr[4][2];
#pragma unroll
            for (int mt = 0; mt < 4; ++mt)
                ldsm4(afr[mt], smA_u + sw128((aRow + mt * 16) * 128 + ksA + aCol));
#pragma unroll
            for (int np = 0; np < 2; ++np) {
                uint32_t rr[4];
                ldsm4(rr, smB_u + sw128((bRow + np * 16) * 128 + ksA + bCol));
                bfr[np * 2 + 0][0] = rr[0]; bfr[np * 2 + 0][1] = rr[1];
                bfr[np * 2 + 1][0] = rr[2]; bfr[np * 2 + 1][1] = rr[3];
            }
#pragma unroll
            for (int mt = 0; mt < 4; ++mt)
#pragma unroll
                for (int nt = 0; nt < 4; ++nt)
                    mma16816(acc[mt][nt], afr[mt], bfr[nt]);
        }
        stg = (stg == 2 * 32768u) ? 0u : stg + 32768u;
        nst = (nst == 2 * 32768u) ? 0u : nst + 32768u;
    }

    // ---- epilogue ----
    const int sector = m0 >> 10;
    const int mbase  = m0 & 1023;
    const float* bptr = fusedQKV ? (sector == 0 ? b0 : (sector == 1 ? b1 : b2)) : b0;

    if (!fusedQKV) {
        __syncthreads();
        if (tid < 128) sidx[tid] = (n0 + tid < nlim) ? idx[b * TDIM + n0 + tid] : -1;
        __syncthreads();
    }

    const int qrow = lane >> 2;
    const int qcol = (lane & 3) * 2;
#pragma unroll
    for (int mt = 0; mt < 4; ++mt) {
#pragma unroll
        for (int rh = 0; rh < 2; ++rh) {
            const int rloc = mbase + wy * 64 + mt * 16 + qrow + rh * 8;
            const float bi = bptr[rloc];
#pragma unroll
            for (int nt = 0; nt < 4; ++nt) {
                const int col = n0 + wx * 32 + nt * 8 + qcol;
                float v0 = acc[mt][nt][rh * 2 + 0] + bi;
                float v1 = acc[mt][nt][rh * 2 + 1] + bi;
                if (!fusedQKV) {
                    float* dst = Cout + (size_t)b * CDIM * TDIM + (size_t)rloc * TDIM;
                    const int t0 = sidx[col - n0 + 0];
                    const int t1 = sidx[col - n0 + 1];
                    if (t0 >= 0) dst[t0] = v0;
                    if (t1 >= 0) dst[t1] = v1;
                } else if (sector < 2) {
                    __half* oh = sector ? Kh : Qh;
                    const int hh = rloc >> 6, dd = rloc & 63;
                    const size_t a0 = ((size_t)(b * HN + hh) * TDIM + col) * DH + dd;
                    oh[a0]      = __float2half(v0);
                    oh[a0 + DH] = __float2half(v1);
                } else {
                    const size_t a0 = ((size_t)b * CDIM + rloc) * TDIM + col;
                    *(uint32_t*)&Vh[a0] = pack2h(v0, v1);
                }
            }
        }
    }
}

// ---------------------------------------------------------------------------
__global__ __launch_bounds__(256)
void split_w4_kernel(const float* __restrict__ w0, const float* __restrict__ w1,
                     const float* __restrict__ w2, const float* __restrict__ w3,
                     __half* __restrict__ hi)
{
    const unsigned i = blockIdx.x * 256u + threadIdx.x;
    const int sel = i >> 20;
    const float* w = (sel == 0) ? w0 : (sel == 1) ? w1 : (sel == 2) ? w2 : w3;
    hi[i] = __float2half(w[i & 0xFFFFFu]);
}

// ---------------------------------------------------------------------------
// fp16 flash attention, double-buffered cp.async K/V tiles, 1 barrier/tile.
// smem: stage0 @0 (K|V 16KB), stage1 @16384, Q staging @32768 (16KB).
// ---------------------------------------------------------------------------
__global__ __launch_bounds__(256, 2)
void attn_mma(const __half* __restrict__ Qh, const __half* __restrict__ Kh,
              const __half* __restrict__ Vh, const int* __restrict__ cnt,
              __half* __restrict__ Oh)
{
    __shared__ __align__(1024) unsigned char sm[49152];
    const int b = blockIdx.z, h = blockIdx.y;
    const int kend = cnt[b];
    const int q0 = blockIdx.x * 128;
    if (q0 >= kend) return;
    const int tid = threadIdx.x, wid = tid >> 5, lane = tid & 31;
    const uint32_t smu = smem_u32(sm);

    // ---- stage Q, extract A-fragments ----
    const __half* Qhb = Qh + ((size_t)(b * HN + h) * TDIM + q0) * DH;
#pragma unroll
    for (int it = 0; it < 4; ++it) {
        const int lin = it * 256 + tid;
        const int row = lin >> 3, qd = lin & 7;
        uint4 a = *(const uint4*)(Qhb + (size_t)row * DH + qd * 8);
        *(uint4*)(sm + 32768 + sw128((uint32_t)row * 128 + qd * 16)) = a;
    }
    __syncthreads();
    uint32_t qfh[4][4];
    {
        const uint32_t aRow = wid * 16 + (lane & 15);
        const uint32_t aColB = (lane >> 4) << 4;
#pragma unroll
        for (int kk = 0; kk < 4; ++kk)
            ldsm4(qfh[kk], smu + 32768 + sw128(aRow * 128 + kk * 32 + aColB));
    }

    float oacc[8][4];
#pragma unroll
    for (int i = 0; i < 8; ++i)
#pragma unroll
        for (int c = 0; c < 4; ++c) oacc[i][c] = 0.f;
    float mrow[2] = {-1e30f, -1e30f}, lrow[2] = {0.f, 0.f};
    const float scale = 0.125f;
    const uint32_t bRow  = (lane & 7) + ((lane >> 4) << 3);
    const uint32_t bColB = ((lane >> 3) & 1) << 4;
    const int jc = (lane & 3) * 2;

    const __half* Khb = Kh + ((size_t)(b * HN + h) * TDIM) * DH;
    const __half* Vhb = Vh + ((size_t)b * CDIM + h * DH) * TDIM;

    // per-thread tile-load addressing (two 16B chunks per thread per tile)
    const int l0row = tid >> 3, lqd = tid & 7;            // rows 0..31
    const int l1row = 32 + l0row;                         // rows 32..63
    const uint32_t soK0 = sw128((uint32_t)l0row * 128 + lqd * 16);
    const uint32_t soK1 = sw128((uint32_t)l1row * 128 + lqd * 16);

    // prologue: tile 0 into stage 0
    {
        cpasync16(smu + soK0,        Khb + (size_t)l0row * DH + lqd * 8);
        cpasync16(smu + soK1,        Khb + (size_t)l1row * DH + lqd * 8);
        cpasync16(smu + 8192 + soK0, Vhb + (size_t)l0row * TDIM + lqd * 8);
        cpasync16(smu + 8192 + soK1, Vhb + (size_t)l1row * TDIM + lqd * 8);
        CP_COMMIT();
    }

    for (int k0 = 0; k0 < kend; k0 += 64) {
        const uint32_t stg = ((uint32_t)(k0 >> 6) & 1u) * 16384u;
        CP_WAIT0();
        __syncthreads();     // compute of previous tile done -> other stage free
        if (k0 + 64 < kend) {
            const uint32_t nst = stg ^ 16384u;
            const int kn = k0 + 64;
            cpasync16(smu + nst + soK0,        Khb + (size_t)(kn + l0row) * DH + lqd * 8);
            cpasync16(smu + nst + soK1,        Khb + (size_t)(kn + l1row) * DH + lqd * 8);
            cpasync16(smu + nst + 8192 + soK0, Vhb + (size_t)l0row * TDIM + kn + lqd * 8);
            cpasync16(smu + nst + 8192 + soK1, Vhb + (size_t)l1row * TDIM + kn + lqd * 8);
            CP_COMMIT();
        }

        float s[8][4];
#pragma unroll
        for (int i = 0; i < 8; ++i)
#pragma unroll
            for (int c = 0; c < 4; ++c) s[i][c] = 0.f;
#pragma unroll
        for (int kk = 0; kk < 4; ++kk) {
            uint32_t bfr[8][2];
#pragma unroll
            for (int np = 0; np < 4; ++np) {
                uint32_t rr[4];
                ldsm4(rr, smu + stg + sw128((np * 16 + bRow) * 128 + kk * 32 + bColB));
                bfr[np * 2 + 0][0] = rr[0]; bfr[np * 2 + 0][1] = rr[1];
                bfr[np * 2 + 1][0] = rr[2]; bfr[np * 2 + 1][1] = rr[3];
            }
#pragma unroll
            for (int nt = 0; nt < 8; ++nt) mma16816(s[nt], qfh[kk], bfr[nt]);
        }

#pragma unroll
        for (int rh = 0; rh < 2; ++rh) {
            float mx = -1e30f;
#pragma unroll
            for (int nt = 0; nt < 8; ++nt) {
                const int jg = k0 + nt * 8 + jc;
                float v0 = (jg     < kend) ? s[nt][rh * 2 + 0] * scale : -1e30f;
                float v1 = (jg + 1 < kend) ? s[nt][rh * 2 + 1] * scale : -1e30f;
                s[nt][rh * 2 + 0] = v0; s[nt][rh * 2 + 1] = v1;
                mx = fmaxf(mx, fmaxf(v0, v1));
            }
            mx = fmaxf(mx, __shfl_xor_sync(0xffffffffu, mx, 1));
            mx = fmaxf(mx, __shfl_xor_sync(0xffffffffu, mx, 2));
            const float mnew = fmaxf(mrow[rh], mx);
            const float fac = __expf(mrow[rh] - mnew);
            mrow[rh] = mnew;
            float sum = 0.f;
#pragma unroll
            for (int nt = 0; nt < 8; ++nt) {
                float p0 = __expf(s[nt][rh * 2 + 0] - mnew);
                float p1 = __expf(s[nt][rh * 2 + 1] - mnew);
                s[nt][rh * 2 + 0] = p0; s[nt][rh * 2 + 1] = p1;
                sum += p0 + p1;
            }
            sum += __shfl_xor_sync(0xffffffffu, sum, 1);
            sum += __shfl_xor_sync(0xffffffffu, sum, 2);
            lrow[rh] = lrow[rh] * fac + sum;
#pragma unroll
            for (int nt = 0; nt < 8; ++nt) {
                oacc[nt][rh * 2 + 0] *= fac;
                oacc[nt][rh * 2 + 1] *= fac;
            }
        }

        uint32_t ph[4][4];
#pragma unroll
        for (int kk2 = 0; kk2 < 4; ++kk2) {
            const int t0 = 2 * kk2, t1 = 2 * kk2 + 1;
            ph[kk2][0] = pack2h(s[t0][0], s[t0][1]);
            ph[kk2][1] = pack2h(s[t0][2], s[t0][3]);
            ph[kk2][2] = pack2h(s[t1][0], s[t1][1]);
            ph[kk2][3] = pack2h(s[t1][2], s[t1][3]);
        }

#pragma unroll
        for (int kk2 = 0; kk2 < 4; ++kk2) {
            uint32_t vfr[8][2];
#pragma unroll
            for (int np = 0; np < 4; ++np) {
                uint32_t rr[4];
                ldsm4(rr, smu + stg + 8192 + sw128((np * 16 + bRow) * 128 + kk2 * 32 + bColB));
                vfr[np * 2 + 0][0] = rr[0]; vfr[np * 2 + 0][1] = rr[1];
                vfr[np * 2 + 1][0] = rr[2]; vfr[np * 2 + 1][1] = rr[3];
            }
#pragma unroll
            for (int nt = 0; nt < 8; ++nt) mma16816(oacc[nt], ph[kk2], vfr[nt]);
        }
    }

#pragma unroll
    for (int rh = 0; rh < 2; ++rh) {
        const int q = q0 + wid * 16 + (lane >> 2) + rh * 8;
        const float inv = (lrow[rh] > 0.f) ? (1.f / lrow[rh]) : 0.f;
        const size_t base = ((size_t)b * TDIM + q) * CDIM + h * DH;
#pragma unroll
        for (int nt = 0; nt < 8; ++nt) {
            const int d = nt * 8 + jc;
            *(uint32_t*)&Oh[base + d] =
                pack2h(oacc[nt][rh * 2 + 0] * inv, oacc[nt][rh * 2 + 1] * inv);
        }
    }
}

// ---------------------------------------------------------------------------
__global__ void zero_kernel(float4* __restrict__ p, int n4)
{
    int i = blockIdx.x * blockDim.x + threadIdx.x;
    if (i < n4) p[i] = make_float4(0.f, 0.f, 0.f, 0.f);
}

__global__ void write_mask_kernel(const unsigned* __restrict__ mask,
                                  float* __restrict__ out, int n)
{
    int i = blockIdx.x * blockDim.x + threadIdx.x;
    if (i < n) out[i] = mask[i] ? 1.0f : 0.0f;
}

// ---------------------------------------------------------------------------
extern "C" void kernel_launch(void* const* d_in, const int* in_sizes, int n_in,
                              void* d_out, int out_size)
{
    const float*    x    = (const float*)d_in[0];
    const unsigned* mask = (const unsigned*)d_in[1];
    const float*    Wq   = (const float*)d_in[2];
    const float*    bq   = (const float*)d_in[3];
    const float*    Wk   = (const float*)d_in[4];
    const float*    bk   = (const float*)d_in[5];
    const float*    Wv   = (const float*)d_in[6];
    const float*    bv   = (const float*)d_in[7];
    const float*    Wp   = (const float*)d_in[8];
    const float*    bp   = (const float*)d_in[9];
    float* out = (float*)d_out;

    __half *wh, *xh, *ah, *qh, *kh, *vh;
    int *gidx, *gcnt;
    cudaGetSymbolAddress((void**)&wh,   g_Wh);
    cudaGetSymbolAddress((void**)&xh,   g_xTh);
    cudaGetSymbolAddress((void**)&ah,   g_aTh);
    cudaGetSymbolAddress((void**)&qh,   g_qh);
    cudaGetSymbolAddress((void**)&kh,   g_kh);
    cudaGetSymbolAddress((void**)&vh,   g_vh);
    cudaGetSymbolAddress((void**)&gidx, g_idx);
    cudaGetSymbolAddress((void**)&gcnt, g_cnt);

    static int smem_set = 0;
    if (!smem_set) {
        cudaFuncSetAttribute(mma_gemm, cudaFuncAttributeMaxDynamicSharedMemorySize, 98304);
        smem_set = 1;
    }

    compact_kernel<<<BSZ, 256>>>(mask, gidx, gcnt);

    const int n4 = BSZ * CDIM * TDIM / 4;
    zero_kernel<<<(n4 + 255) / 256, 256>>>((float4*)out, n4);

    split_w4_kernel<<<4 * CDIM * CDIM / 256, 256>>>(Wq, Wk, Wv, Wp, wh);

    dim3 gt(TDIM / 32, CDIM / 32, BSZ);
    gather_transpose<<<gt, dim3(32, 8)>>>(x, gidx, gcnt, xh);

    const size_t WN = (size_t)CDIM * CDIM;
    dim3 gqkv(TDIM / 128, 24, BSZ);
    mma_gemm<<<gqkv, 256, 98304>>>(wh, xh, bq, bk, bv,
                                   nullptr, qh, kh, vh, gcnt, gidx, 1);

    dim3 ga(TDIM / 128, HN, BSZ);
    attn_mma<<<ga, 256>>>(qh, kh, vh, gcnt, ah);

    dim3 gp(TDIM / 128, CDIM / 128, BSZ);
    mma_gemm<<<gp, 256, 98304>>>(wh + 3 * WN, ah, bp, nullptr, nullptr,
                                 out, nullptr, nullptr, nullptr,
                                 gcnt, gidx, 0);

    const long long nout = (long long)BSZ * CDIM * TDIM;
    const int tail = out_size - (int)nout;
    if (tail >= BSZ * TDIM) {
        write_mask_kernel<<<(BSZ * TDIM + 255) / 256, 256>>>(
            mask, out + nout, BSZ * TDIM);
    }
}

// round 13
// speedup vs baseline: 9.2569x; 1.0398x over previous
#include <cuda_runtime.h>
#include <cuda_fp16.h>
#include <stdint.h>

#define BSZ  2
#define CDIM 1024
#define TDIM 2048
#define HN   16
#define DH   64

// ---------------- scratch (static device globals) ----------------
__device__ __half g_Wh [(size_t)4 * CDIM * CDIM];     // [Wq;Wk;Wv;Wp] fp16
__device__ __half g_xTh[(size_t)BSZ * TDIM * CDIM];   // (B, Tc, C) fp16
__device__ __half g_qh [(size_t)BSZ * HN * TDIM * DH]; // (B,H,Tc,D)
__device__ __half g_kh [(size_t)BSZ * HN * TDIM * DH];
__device__ __half g_vh [(size_t)BSZ * CDIM * TDIM];    // (B, C, Tc)
__device__ __half g_aTh[(size_t)BSZ * TDIM * CDIM];    // attn out (B, Tc, C)
__device__ int g_idx[BSZ * TDIM];
__device__ int g_cnt[BSZ];

// ---------------- helpers ----------------
__device__ __forceinline__ uint32_t smem_u32(const void* p) {
    uint32_t a;
    asm("{ .reg .u64 t; cvta.to.shared.u64 t, %1; cvt.u32.u64 %0, t; }" : "=r"(a) : "l"(p));
    return a;
}
__device__ __forceinline__ uint32_t sw128(uint32_t off) { return off ^ ((off >> 3) & 0x70); }

__device__ __forceinline__ void ldsm4(uint32_t* r, uint32_t addr) {
    asm volatile("ldmatrix.sync.aligned.m8n8.x4.shared.b16 {%0,%1,%2,%3}, [%4];"
        : "=r"(r[0]), "=r"(r[1]), "=r"(r[2]), "=r"(r[3]) : "r"(addr));
}
__device__ __forceinline__ void mma16816(float* c, const uint32_t* a, const uint32_t* b) {
    asm volatile("mma.sync.aligned.m16n8k16.row.col.f32.f16.f16.f32 "
        "{%0,%1,%2,%3}, {%4,%5,%6,%7}, {%8,%9}, {%0,%1,%2,%3};"
        : "+f"(c[0]), "+f"(c[1]), "+f"(c[2]), "+f"(c[3])
        : "r"(a[0]), "r"(a[1]), "r"(a[2]), "r"(a[3]), "r"(b[0]), "r"(b[1]));
}
__device__ __forceinline__ uint32_t pack2h(float v0, float v1) {
    return (uint32_t)__half_as_ushort(__float2half(v0)) |
           ((uint32_t)__half_as_ushort(__float2half(v1)) << 16);
}
__device__ __forceinline__ void cpasync16(uint32_t dst, const void* src) {
    asm volatile("cp.async.cg.shared.global [%0], [%1], 16;" :: "r"(dst), "l"(src));
}
#define CP_COMMIT() asm volatile("cp.async.commit_group;" ::: "memory")
#define CP_WAIT0()  asm volatile("cp.async.wait_group 0;" ::: "memory")
#define CP_WAIT1()  asm volatile("cp.async.wait_group 1;" ::: "memory")

// ---------------------------------------------------------------------------
__global__ __launch_bounds__(256)
void compact_kernel(const unsigned* __restrict__ mask, int* __restrict__ idx,
                    int* __restrict__ cnt)
{
    __shared__ int wsum[8];
    __shared__ int wexcl[8];
    const int b = blockIdx.x;
    const unsigned* mb = mask + (size_t)b * TDIM;
    int* ib = idx + (size_t)b * TDIM;
    const int tid  = threadIdx.x;
    const int lane = tid & 31, w = tid >> 5;
    unsigned v[8]; int c = 0;
#pragma unroll
    for (int i = 0; i < 8; ++i) { v[i] = mb[tid * 8 + i]; c += v[i] ? 1 : 0; }
    int inc = c;
#pragma unroll
    for (int off = 1; off < 32; off <<= 1) {
        int n = __shfl_up_sync(0xffffffffu, inc, off);
        if (lane >= off) inc += n;
    }
    if (lane == 31) wsum[w] = inc;
    __syncthreads();
    if (tid == 0) {
        int s = 0;
#pragma unroll
        for (int i = 0; i < 8; ++i) { wexcl[i] = s; s += wsum[i]; }
        cnt[b] = s;
    }
    __syncthreads();
    int p = wexcl[w] + inc - c;
#pragma unroll
    for (int i = 0; i < 8; ++i) if (v[i]) ib[p++] = tid * 8 + i;
}

// ---------------------------------------------------------------------------
// Fused prep: grid sections.
//  [0, 2048)        : split W  (4M elems, 8/thread, fp32 -> fp16)
//  [2048, 2560)     : zero out (1M float4, 8/thread)
//  [2560, 6656)     : gather+transpose x -> (B,Tc,C) fp16 (32x32 tiles)
//  [6656, 6672)     : mask tail write (if writeTail)
// ---------------------------------------------------------------------------
#define PREP_SPLIT0   0
#define PREP_ZERO0    2048
#define PREP_GATH0    2560
#define PREP_TAIL0    6656
#define PREP_BLOCKS   6672

__global__ __launch_bounds__(256)
void prep_kernel(const float* __restrict__ x, const unsigned* __restrict__ mask,
                 const int* __restrict__ idx, const int* __restrict__ cnt,
                 const float* __restrict__ w0, const float* __restrict__ w1,
                 const float* __restrict__ w2, const float* __restrict__ w3,
                 __half* __restrict__ wh, __half* __restrict__ xh,
                 float* __restrict__ out, int writeTail)
{
    const int bx = blockIdx.x;
    const int tid = threadIdx.x;

    if (bx < PREP_ZERO0) {
        // ---- weight split: block covers 2048 consecutive elems ----
        const unsigned base = (unsigned)bx * 2048u + (unsigned)tid * 8u;
#pragma unroll
        for (int i = 0; i < 8; i += 4) {
            const unsigned idx4 = base + i;
            const int sel = idx4 >> 20;
            const float* w = (sel == 0) ? w0 : (sel == 1) ? w1 : (sel == 2) ? w2 : w3;
            float4 v = *(const float4*)(w + (idx4 & 0xFFFFFu));
            uint2 o;
            o.x = pack2h(v.x, v.y);
            o.y = pack2h(v.z, v.w);
            *(uint2*)(wh + idx4) = o;
        }
    } else if (bx < PREP_GATH0) {
        // ---- zero output: block covers 2048 float4 ----
        float4* p = (float4*)out;
        const unsigned base = (unsigned)(bx - PREP_ZERO0) * 2048u + (unsigned)tid * 8u;
#pragma unroll
        for (int i = 0; i < 8; ++i)
            p[base + i] = make_float4(0.f, 0.f, 0.f, 0.f);
    } else if (bx < PREP_TAIL0) {
        // ---- gather + transpose ----
        __shared__ float tile[32][33];
        __shared__ int tloc[32];
        const int g = bx - PREP_GATH0;          // 0..4095
        const int b = g >> 11;                  // / 2048
        const int rem = g & 2047;
        const int cy = rem >> 6;                // / 64 -> c tile
        const int gx = rem & 63;                // t tile
        const int n = cnt[b];
        const int i0 = gx * 32;
        if (i0 >= n) return;
        const int c0 = cy * 32;
        const float* s = x + (size_t)b * CDIM * TDIM;
        __half* ph = xh + (size_t)b * TDIM * CDIM;
        const int tx = tid & 31, ty = tid >> 5;
        if (ty == 0) tloc[tx] = (i0 + tx < n) ? idx[b * TDIM + i0 + tx] : -1;
        __syncthreads();
        const int t = tloc[tx];
#pragma unroll
        for (int i = 0; i < 4; ++i)
            tile[ty + i * 8][tx] = (t >= 0) ? s[(size_t)(c0 + ty + i * 8) * TDIM + t] : 0.f;
        __syncthreads();
#pragma unroll
        for (int i = 0; i < 4; ++i) {
            const int irow = i0 + ty + i * 8;
            if (irow < n)
                ph[(size_t)irow * CDIM + c0 + tx] = __float2half(tile[tx][ty + i * 8]);
        }
    } else {
        // ---- mask tail ----
        if (!writeTail) return;
        const int i = (bx - PREP_TAIL0) * 256 + tid;   // < BSZ*TDIM = 4096
        float* outTail = out + (size_t)BSZ * CDIM * TDIM;
        outTail[i] = mask[i] ? 1.0f : 0.0f;
    }
}

// ---------------------------------------------------------------------------
// fp16 GEMM, BK=64, 3-stage cp.async pipeline, 1 barrier per k-iteration.
// fusedQKV=1: A rows 0..3071 = [Wq;Wk;Wv]; outputs Q/K (B,H,Tc,D), V (B,C,Tc).
// fusedQKV=0: P-proj; scatter fp32 through idx into (C,T) (out pre-zeroed).
// ---------------------------------------------------------------------------
extern __shared__ unsigned char dynsm[];

__global__ __launch_bounds__(256, 2)
void mma_gemm(const __half* __restrict__ Ah, const __half* __restrict__ Bh,
              const float* __restrict__ b0, const float* __restrict__ b1,
              const float* __restrict__ b2, float* __restrict__ Cout,
              __half* __restrict__ Qh, __half* __restrict__ Kh, __half* __restrict__ Vh,
              const int* __restrict__ cnt, const int* __restrict__ idx, int fusedQKV)
{
    __shared__ int sidx[128];

    const int b    = blockIdx.z;
    const int nlim = cnt[b];
    const int n0   = blockIdx.x * 128;
    if (n0 >= nlim) return;
    const int m0   = blockIdx.y * 128;
    const int tid  = threadIdx.x;
    const int wid  = tid >> 5;
    const int lane = tid & 31;
    const int wy   = wid & 1;
    const int wx   = wid >> 1;

    const uint32_t smu = smem_u32(dynsm);

    const int r   = tid & 127;
    const int isB = tid >> 7;
    const __half* Bhb = Bh + (size_t)b * TDIM * CDIM;
    const __half* srcP = isB ? (Bhb + (size_t)(n0 + r) * CDIM)
                             : (Ah + (size_t)(m0 + r) * CDIM);
    const uint32_t regOff = (uint32_t)isB * 16384u;
    uint32_t so[8];
#pragma unroll
    for (int i = 0; i < 8; ++i) so[i] = regOff + sw128((uint32_t)r * 128u + i * 16u);

    float acc[4][4][4];
#pragma unroll
    for (int i = 0; i < 4; ++i)
#pragma unroll
        for (int j = 0; j < 4; ++j)
#pragma unroll
            for (int c = 0; c < 4; ++c) acc[i][j][c] = 0.f;

    const uint32_t aRow = (uint32_t)(wy * 64 + (lane & 15));
    const uint32_t aCol = (uint32_t)((lane >> 4) << 4);
    const uint32_t bRow = (uint32_t)(wx * 32 + (lane & 7) + ((lane >> 4) << 3));
    const uint32_t bCol = (uint32_t)(((lane >> 3) & 1) << 4);

    {
#pragma unroll
        for (int i = 0; i < 8; ++i)
            cpasync16(smu + so[i], srcP + i * 8);
        CP_COMMIT();
#pragma unroll
        for (int i = 0; i < 8; ++i)
            cpasync16(smu + 32768u + so[i], srcP + 64 + i * 8);
        CP_COMMIT();
    }

    uint32_t stg = 0;
    uint32_t nst = 2 * 32768u;
    for (int kb = 0; kb < 16; ++kb) {
        if (kb < 15) { CP_WAIT1(); } else { CP_WAIT0(); }
        __syncthreads();
        if (kb + 2 < 16) {
            const int k2 = (kb + 2) * 64;
#pragma unroll
            for (int i = 0; i < 8; ++i)
                cpasync16(smu + nst + so[i], srcP + k2 + i * 8);
            CP_COMMIT();
        }

        const uint32_t smA_u = smu + stg;
        const uint32_t smB_u = smu + stg + 16384;
#pragma unroll
        for (int s = 0; s < 4; ++s) {
            const uint32_t ksA = s * 32;
            uint32_t afr[4][4], bfr[4][2];
#pragma unroll
            for (int mt = 0; mt < 4; ++mt)
                ldsm4(afr[mt], smA_u + sw128((aRow + mt * 16) * 128 + ksA + aCol));
#pragma unroll
            for (int np = 0; np < 2; ++np) {
                uint32_t rr[4];
                ldsm4(rr, smB_u + sw128((bRow + np * 16) * 128 + ksA + bCol));
                bfr[np * 2 + 0][0] = rr[0]; bfr[np * 2 + 0][1] = rr[1];
                bfr[np * 2 + 1][0] = rr[2]; bfr[np * 2 + 1][1] = rr[3];
            }
#pragma unroll
            for (int mt = 0; mt < 4; ++mt)
#pragma unroll
                for (int nt = 0; nt < 4; ++nt)
                    mma16816(acc[mt][nt], afr[mt], bfr[nt]);
        }
        stg = (stg == 2 * 32768u) ? 0u : stg + 32768u;
        nst = (nst == 2 * 32768u) ? 0u : nst + 32768u;
    }

    // ---- epilogue ----
    const int sector = m0 >> 10;
    const int mbase  = m0 & 1023;
    const float* bptr = fusedQKV ? (sector == 0 ? b0 : (sector == 1 ? b1 : b2)) : b0;

    if (!fusedQKV) {
        __syncthreads();
        if (tid < 128) sidx[tid] = (n0 + tid < nlim) ? idx[b * TDIM + n0 + tid] : -1;
        __syncthreads();
    }

    const int qrow = lane >> 2;
    const int qcol = (lane & 3) * 2;
#pragma unroll
    for (int mt = 0; mt < 4; ++mt) {
#pragma unroll
        for (int rh = 0; rh < 2; ++rh) {
            const int rloc = mbase + wy * 64 + mt * 16 + qrow + rh * 8;
            const float bi = bptr[rloc];
#pragma unroll
            for (int nt = 0; nt < 4; ++nt) {
                const int col = n0 + wx * 32 + nt * 8 + qcol;
                float v0 = acc[mt][nt][rh * 2 + 0] + bi;
                float v1 = acc[mt][nt][rh * 2 + 1] + bi;
                if (!fusedQKV) {
                    float* dst = Cout + (size_t)b * CDIM * TDIM + (size_t)rloc * TDIM;
                    const int t0 = sidx[col - n0 + 0];
                    const int t1 = sidx[col - n0 + 1];
                    if (t0 >= 0) dst[t0] = v0;
                    if (t1 >= 0) dst[t1] = v1;
                } else if (sector < 2) {
                    __half* oh = sector ? Kh : Qh;
                    const int hh = rloc >> 6, dd = rloc & 63;
                    const size_t a0 = ((size_t)(b * HN + hh) * TDIM + col) * DH + dd;
                    oh[a0]      = __float2half(v0);
                    oh[a0 + DH] = __float2half(v1);
                } else {
                    const size_t a0 = ((size_t)b * CDIM + rloc) * TDIM + col;
                    *(uint32_t*)&Vh[a0] = pack2h(v0, v1);
                }
            }
        }
    }
}

// ---------------------------------------------------------------------------
// fp16 flash attention, double-buffered cp.async K/V tiles, 1 barrier/tile.
// ---------------------------------------------------------------------------
__global__ __launch_bounds__(256, 2)
void attn_mma(const __half* __restrict__ Qh, const __half* __restrict__ Kh,
              const __half* __restrict__ Vh, const int* __restrict__ cnt,
              __half* __restrict__ Oh)
{
    __shared__ __align__(1024) unsigned char sm[49152];
    const int b = blockIdx.z, h = blockIdx.y;
    const int kend = cnt[b];
    const int q0 = blockIdx.x * 128;
    if (q0 >= kend) return;
    const int tid = threadIdx.x, wid = tid >> 5, lane = tid & 31;
    const uint32_t smu = smem_u32(sm);

    const __half* Qhb = Qh + ((size_t)(b * HN + h) * TDIM + q0) * DH;
#pragma unroll
    for (int it = 0; it < 4; ++it) {
        const int lin = it * 256 + tid;
        const int row = lin >> 3, qd = lin & 7;
        uint4 a = *(const uint4*)(Qhb + (size_t)row * DH + qd * 8);
        *(uint4*)(sm + 32768 + sw128((uint32_t)row * 128 + qd * 16)) = a;
    }
    __syncthreads();
    uint32_t qfh[4][4];
    {
        const uint32_t aRow = wid * 16 + (lane & 15);
        const uint32_t aColB = (lane >> 4) << 4;
#pragma unroll
        for (int kk = 0; kk < 4; ++kk)
            ldsm4(qfh[kk], smu + 32768 + sw128(aRow * 128 + kk * 32 + aColB));
    }

    float oacc[8][4];
#pragma unroll
    for (int i = 0; i < 8; ++i)
#pragma unroll
        for (int c = 0; c < 4; ++c) oacc[i][c] = 0.f;
    float mrow[2] = {-1e30f, -1e30f}, lrow[2] = {0.f, 0.f};
    const float scale = 0.125f;
    const uint32_t bRow  = (lane & 7) + ((lane >> 4) << 3);
    const uint32_t bColB = ((lane >> 3) & 1) << 4;
    const int jc = (lane & 3) * 2;

    const __half* Khb = Kh + ((size_t)(b * HN + h) * TDIM) * DH;
    const __half* Vhb = Vh + ((size_t)b * CDIM + h * DH) * TDIM;

    const int l0row = tid >> 3, lqd = tid & 7;
    const int l1row = 32 + l0row;
    const uint32_t soK0 = sw128((uint32_t)l0row * 128 + lqd * 16);
    const uint32_t soK1 = sw128((uint32_t)l1row * 128 + lqd * 16);

    {
        cpasync16(smu + soK0,        Khb + (size_t)l0row * DH + lqd * 8);
        cpasync16(smu + soK1,        Khb + (size_t)l1row * DH + lqd * 8);
        cpasync16(smu + 8192 + soK0, Vhb + (size_t)l0row * TDIM + lqd * 8);
        cpasync16(smu + 8192 + soK1, Vhb + (size_t)l1row * TDIM + lqd * 8);
        CP_COMMIT();
    }

    for (int k0 = 0; k0 < kend; k0 += 64) {
        const uint32_t stg = ((uint32_t)(k0 >> 6) & 1u) * 16384u;
        CP_WAIT0();
        __syncthreads();
        if (k0 + 64 < kend) {
            const uint32_t nst = stg ^ 16384u;
            const int kn = k0 + 64;
            cpasync16(smu + nst + soK0,        Khb + (size_t)(kn + l0row) * DH + lqd * 8);
            cpasync16(smu + nst + soK1,        Khb + (size_t)(kn + l1row) * DH + lqd * 8);
            cpasync16(smu + nst + 8192 + soK0, Vhb + (size_t)l0row * TDIM + kn + lqd * 8);
            cpasync16(smu + nst + 8192 + soK1, Vhb + (size_t)l1row * TDIM + kn + lqd * 8);
            CP_COMMIT();
        }

        float s[8][4];
#pragma unroll
        for (int i = 0; i < 8; ++i)
#pragma unroll
            for (int c = 0; c < 4; ++c) s[i][c] = 0.f;
#pragma unroll
        for (int kk = 0; kk < 4; ++kk) {
            uint32_t bfr[8][2];
#pragma unroll
            for (int np = 0; np < 4; ++np) {
                uint32_t rr[4];
                ldsm4(rr, smu + stg + sw128((np * 16 + bRow) * 128 + kk * 32 + bColB));
                bfr[np * 2 + 0][0] = rr[0]; bfr[np * 2 + 0][1] = rr[1];
                bfr[np * 2 + 1][0] = rr[2]; bfr[np * 2 + 1][1] = rr[3];
            }
#pragma unroll
            for (int nt = 0; nt < 8; ++nt) mma16816(s[nt], qfh[kk], bfr[nt]);
        }

#pragma unroll
        for (int rh = 0; rh < 2; ++rh) {
            float mx = -1e30f;
#pragma unroll
            for (int nt = 0; nt < 8; ++nt) {
                const int jg = k0 + nt * 8 + jc;
                float v0 = (jg     < kend) ? s[nt][rh * 2 + 0] * scale : -1e30f;
                float v1 = (jg + 1 < kend) ? s[nt][rh * 2 + 1] * scale : -1e30f;
                s[nt][rh * 2 + 0] = v0; s[nt][rh * 2 + 1] = v1;
                mx = fmaxf(mx, fmaxf(v0, v1));
            }
            mx = fmaxf(mx, __shfl_xor_sync(0xffffffffu, mx, 1));
            mx = fmaxf(mx, __shfl_xor_sync(0xffffffffu, mx, 2));
            const float mnew = fmaxf(mrow[rh], mx);
            const float fac = __expf(mrow[rh] - mnew);
            mrow[rh] = mnew;
            float sum = 0.f;
#pragma unroll
            for (int nt = 0; nt < 8; ++nt) {
                float p0 = __expf(s[nt][rh * 2 + 0] - mnew);
                float p1 = __expf(s[nt][rh * 2 + 1] - mnew);
                s[nt][rh * 2 + 0] = p0; s[nt][rh * 2 + 1] = p1;
                sum += p0 + p1;
            }
            sum += __shfl_xor_sync(0xffffffffu, sum, 1);
            sum += __shfl_xor_sync(0xffffffffu, sum, 2);
            lrow[rh] = lrow[rh] * fac + sum;
#pragma unroll
            for (int nt = 0; nt < 8; ++nt) {
                oacc[nt][rh * 2 + 0] *= fac;
                oacc[nt][rh * 2 + 1] *= fac;
            }
        }

        uint32_t ph[4][4];
#pragma unroll
        for (int kk2 = 0; kk2 < 4; ++kk2) {
            const int t0 = 2 * kk2, t1 = 2 * kk2 + 1;
            ph[kk2][0] = pack2h(s[t0][0], s[t0][1]);
            ph[kk2][1] = pack2h(s[t0][2], s[t0][3]);
            ph[kk2][2] = pack2h(s[t1][0], s[t1][1]);
            ph[kk2][3] = pack2h(s[t1][2], s[t1][3]);
        }

#pragma unroll
        for (int kk2 = 0; kk2 < 4; ++kk2) {
            uint32_t vfr[8][2];
#pragma unroll
            for (int np = 0; np < 4; ++np) {
                uint32_t rr[4];
                ldsm4(rr, smu + stg + 8192 + sw128((np * 16 + bRow) * 128 + kk2 * 32 + bColB));
                vfr[np * 2 + 0][0] = rr[0]; vfr[np * 2 + 0][1] = rr[1];
                vfr[np * 2 + 1][0] = rr[2]; vfr[np * 2 + 1][1] = rr[3];
            }
#pragma unroll
            for (int nt = 0; nt < 8; ++nt) mma16816(oacc[nt], ph[kk2], vfr[nt]);
        }
    }

#pragma unroll
    for (int rh = 0; rh < 2; ++rh) {
        const int q = q0 + wid * 16 + (lane >> 2) + rh * 8;
        const float inv = (lrow[rh] > 0.f) ? (1.f / lrow[rh]) : 0.f;
        const size_t base = ((size_t)b * TDIM + q) * CDIM + h * DH;
#pragma unroll
        for (int nt = 0; nt < 8; ++nt) {
            const int d = nt * 8 + jc;
            *(uint32_t*)&Oh[base + d] =
                pack2h(oacc[nt][rh * 2 + 0] * inv, oacc[nt][rh * 2 + 1] * inv);
        }
    }
}

// ---------------------------------------------------------------------------
extern "C" void kernel_launch(void* const* d_in, const int* in_sizes, int n_in,
                              void* d_out, int out_size)
{
    const float*    x    = (const float*)d_in[0];
    const unsigned* mask = (const unsigned*)d_in[1];
    const float*    Wq   = (const float*)d_in[2];
    const float*    bq   = (const float*)d_in[3];
    const float*    Wk   = (const float*)d_in[4];
    const float*    bk   = (const float*)d_in[5];
    const float*    Wv   = (const float*)d_in[6];
    const float*    bv   = (const float*)d_in[7];
    const float*    Wp   = (const float*)d_in[8];
    const float*    bp   = (const float*)d_in[9];
    float* out = (float*)d_out;

    __half *wh, *xh, *ah, *qh, *kh, *vh;
    int *gidx, *gcnt;
    cudaGetSymbolAddress((void**)&wh,   g_Wh);
    cudaGetSymbolAddress((void**)&xh,   g_xTh);
    cudaGetSymbolAddress((void**)&ah,   g_aTh);
    cudaGetSymbolAddress((void**)&qh,   g_qh);
    cudaGetSymbolAddress((void**)&kh,   g_kh);
    cudaGetSymbolAddress((void**)&vh,   g_vh);
    cudaGetSymbolAddress((void**)&gidx, g_idx);
    cudaGetSymbolAddress((void**)&gcnt, g_cnt);

    static int smem_set = 0;
    if (!smem_set) {
        cudaFuncSetAttribute(mma_gemm, cudaFuncAttributeMaxDynamicSharedMemorySize, 98304);
        smem_set = 1;
    }

    const long long nout = (long long)BSZ * CDIM * TDIM;
    const int writeTail = (out_size - (int)nout) >= BSZ * TDIM ? 1 : 0;

    compact_kernel<<<BSZ, 256>>>(mask, gidx, gcnt);

    prep_kernel<<<PREP_BLOCKS, 256>>>(x, mask, gidx, gcnt,
                                      Wq, Wk, Wv, Wp, wh, xh, out, writeTail);

    const size_t WN = (size_t)CDIM * CDIM;
    dim3 gqkv(TDIM / 128, 24, BSZ);
    mma_gemm<<<gqkv, 256, 98304>>>(wh, xh, bq, bk, bv,
                                   nullptr, qh, kh, vh, gcnt, gidx, 1);

    dim3 ga(TDIM / 128, HN, BSZ);
    attn_mma<<<ga, 256>>>(qh, kh, vh, gcnt, ah);

    dim3 gp(TDIM / 128, CDIM / 128, BSZ);
    mma_gemm<<<gp, 256, 98304>>>(wh + 3 * WN, ah, bp, nullptr, nullptr,
                                 out, nullptr, nullptr, nullptr,
                                 gcnt, gidx, 0);
}